// round 9
// baseline (speedup 1.0000x reference)
#include <cuda_runtime.h>

#define D 64
#define S 64
#define L 64
#define W 300
#define H 300
#define NROWS (D*S)          // 4096
#define NEGV (-9999999.0f)

// ---------------- device scratch (no allocation allowed) ----------------
__device__ float g_enc[NROWS * H];
__device__ float g_P  [NROWS * H];
__device__ float g_C  [NROWS * H];
__device__ float g_Y2 [NROWS * H];
__device__ float g_fin[D * H];
__device__ float g_v2 [H];

__device__ __forceinline__ float lrelu_f(float x) { return x > 0.f ? x : 0.01f * x; }

__device__ __forceinline__ unsigned f2tf32(float f) {
    unsigned u;
    asm("cvt.rna.tf32.f32 %0, %1;" : "=r"(u) : "f"(f));
    return u;
}
__device__ __forceinline__ uint4 cvt4(float4 v) {
    return make_uint4(f2tf32(v.x), f2tf32(v.y), f2tf32(v.z), f2tf32(v.w));
}

__device__ __forceinline__ void mma8(float* c, const unsigned* a, const unsigned* b) {
    asm volatile(
        "mma.sync.aligned.m16n8k8.row.col.f32.tf32.tf32.f32 "
        "{%0,%1,%2,%3}, {%4,%5,%6,%7}, {%8,%9}, {%0,%1,%2,%3};"
        : "+f"(c[0]), "+f"(c[1]), "+f"(c[2]), "+f"(c[3])
        : "r"(a[0]), "r"(a[1]), "r"(a[2]), "r"(a[3]), "r"(b[0]), "r"(b[1]));
}

#define BM 128
#define BN 64
#define BK 16
#define BKP 20

// =====================================================================
// TF32 GEMM (R5-proven): Out[M,N] = act( A[M,K] @ B[N,K(ld=ldb)]^T + b )
// z selects among 3 (B,bias,Out) triples; bias==nullptr => linear.
// =====================================================================
template<bool GATHER>
__global__ void gemm_tf32_kernel(
    const float* __restrict__ Abase, const int* __restrict__ idx, int idxStride,
    const float* __restrict__ B0, const float* __restrict__ bias0, float* __restrict__ Out0,
    const float* __restrict__ B1, const float* __restrict__ bias1, float* __restrict__ Out1,
    const float* __restrict__ B2, const float* __restrict__ bias2, float* __restrict__ Out2,
    int N, int K, int ldb0, int ldb1, int ldb2)
{
    const float* Bw   = B0;
    const float* bias = bias0;
    float*       Out  = Out0;
    int          ldb  = ldb0;
    if (blockIdx.z == 1) { Bw = B1; bias = bias1; Out = Out1; ldb = ldb1; }
    if (blockIdx.z == 2) { Bw = B2; bias = bias2; Out = Out2; ldb = ldb2; }
    const bool act = (bias != nullptr);

    __shared__ __align__(16) unsigned As[BM][BKP];
    __shared__ __align__(16) unsigned Bs[BN][BKP];

    const int tid  = threadIdx.x;
    const int lane = tid & 31;
    const int wid  = tid >> 5;
    const int wm   = wid >> 1;
    const int wn   = wid & 1;
    const int m0   = blockIdx.y * BM;
    const int n0   = blockIdx.x * BN;

    const int am0 = tid >> 2;
    const int ac  = (tid & 3) * 4;
    long aoff0, aoff1;
    if (GATHER) {
        aoff0 = (long)idx[(long)(m0 + am0) * idxStride] * K;
        aoff1 = (long)idx[(long)(m0 + am0 + 64) * idxStride] * K;
    } else {
        aoff0 = (long)(m0 + am0) * K;
        aoff1 = (long)(m0 + am0 + 64) * K;
    }
    const int  bn     = tid >> 2;
    const bool bvalid = (n0 + bn) < N;
    const long boff   = (long)(n0 + bn) * ldb;

    float acc[2][4][4];
    #pragma unroll
    for (int i = 0; i < 2; i++)
        #pragma unroll
        for (int j = 0; j < 4; j++)
            #pragma unroll
            for (int q = 0; q < 4; q++) acc[i][j][q] = 0.f;

    const int lr = lane >> 2;
    const int lc = lane & 3;

    for (int k0 = 0; k0 < K; k0 += BK) {
        if (k0 + BK <= K) {
            float4 a0 = *(const float4*)(Abase + aoff0 + k0 + ac);
            float4 a1 = *(const float4*)(Abase + aoff1 + k0 + ac);
            float4 bv = bvalid ? *(const float4*)(Bw + boff + k0 + ac)
                               : make_float4(0.f, 0.f, 0.f, 0.f);
            *(uint4*)&As[am0][ac]      = cvt4(a0);
            *(uint4*)&As[am0 + 64][ac] = cvt4(a1);
            *(uint4*)&Bs[bn][ac]       = cvt4(bv);
        } else {
            #pragma unroll
            for (int u = 0; u < 4; u++) {
                int k = k0 + ac + u;
                As[am0][ac + u]      = (k < K) ? f2tf32(Abase[aoff0 + k]) : 0u;
                As[am0 + 64][ac + u] = (k < K) ? f2tf32(Abase[aoff1 + k]) : 0u;
                Bs[bn][ac + u]       = (bvalid && k < K) ? f2tf32(Bw[boff + k]) : 0u;
            }
        }
        __syncthreads();
        #pragma unroll
        for (int ks = 0; ks < 2; ks++) {
            const int kb = ks * 8;
            unsigned a[2][4], b[4][2];
            #pragma unroll
            for (int mi = 0; mi < 2; mi++) {
                int r = wm * 32 + mi * 16 + lr;
                a[mi][0] = As[r][kb + lc];
                a[mi][1] = As[r + 8][kb + lc];
                a[mi][2] = As[r][kb + lc + 4];
                a[mi][3] = As[r + 8][kb + lc + 4];
            }
            #pragma unroll
            for (int ni = 0; ni < 4; ni++) {
                int c = wn * 32 + ni * 8 + lr;
                b[ni][0] = Bs[c][kb + lc];
                b[ni][1] = Bs[c][kb + lc + 4];
            }
            #pragma unroll
            for (int mi = 0; mi < 2; mi++)
                #pragma unroll
                for (int ni = 0; ni < 4; ni++)
                    mma8(acc[mi][ni], a[mi], b[ni]);
        }
        __syncthreads();
    }

    #pragma unroll
    for (int mi = 0; mi < 2; mi++) {
        int r = m0 + wm * 32 + mi * 16 + lr;
        #pragma unroll
        for (int ni = 0; ni < 4; ni++) {
            int cb = n0 + wn * 32 + ni * 8 + 2 * lc;
            #pragma unroll
            for (int q = 0; q < 2; q++) {
                int cc = cb + q;
                if (cc >= N) continue;
                float bv = act ? bias[cc] : 0.f;
                float v0 = acc[mi][ni][q]     + bv;
                float v1 = acc[mi][ni][q + 2] + bv;
                if (act) { v0 = lrelu_f(v0); v1 = lrelu_f(v1); }
                Out[(long)r * N + cc]       = v0;
                Out[(long)(r + 8) * N + cc] = v1;
            }
        }
    }
}

// =====================================================================
// Scores + diag mask + column softmax, grid (4, D), 256 thr.
// Block (jb, d) -> A[d, :, jb*16 : jb*16+16].
// Extras: jb==0 -> fri[d,:] (softmax(enc@w_root+b));
//         jb==1 -> v2 slice (n = d*5 .. d*5+4).
// =====================================================================
#define SPAD 308
#define SCORES_SMEM ((80 * SPAD + 64 * 17) * 4)   // 102,912 B

__global__ void scores_kernel(const float* __restrict__ P,
                              const float* __restrict__ Cm,
                              const float* __restrict__ enc,
                              const float* __restrict__ w_root,
                              const float* __restrict__ b_root,
                              const float* __restrict__ W_r,
                              const float* __restrict__ root_embed,
                              float* __restrict__ A_out,
                              float* __restrict__ fri_out,
                              float* __restrict__ v2_out)
{
    extern __shared__ unsigned sdyn[];
    unsigned* Pt = sdyn;                       // [64][SPAD]
    unsigned* Ct = sdyn + 64 * SPAD;           // [16][SPAD]
    float*    Sh = (float*)(sdyn + 80 * SPAD); // [64][17]
    __shared__ float sred[64];

    const int d  = blockIdx.y;
    const int j0 = blockIdx.x * 16;
    const int t = threadIdx.x;
    const int lane = t & 31;
    const int wid  = t >> 5;
    const int wm = wid >> 1;    // 0..3
    const int wn = wid & 1;     // 0..1
    const int lr = lane >> 2, lc = lane & 3;

    const float4* Pd4 = (const float4*)(P  + (long)d * S * H);   // 75 float4 per row
    const float4* Cd4 = (const float4*)(Cm + (long)d * S * H);

    for (int u = t; u < 64 * 76; u += 256) {
        int r = u / 76, c4 = u - r * 76;
        float4 v = make_float4(0.f, 0.f, 0.f, 0.f);
        if (c4 < 75) v = Pd4[r * 75 + c4];
        *(uint4*)&Pt[r * SPAD + c4 * 4] = cvt4(v);
    }
    for (int u = t; u < 16 * 76; u += 256) {
        int r = u / 76, c4 = u - r * 76;
        float4 v = make_float4(0.f, 0.f, 0.f, 0.f);
        if (c4 < 75) v = Cd4[(j0 + r) * 75 + c4];
        *(uint4*)&Ct[r * SPAD + c4 * 4] = cvt4(v);
    }
    __syncthreads();

    float acc[4] = {};
    {
        const int r = wm * 16 + lr;
        const int c = wn * 8 + lr;
        #pragma unroll
        for (int ks = 0; ks < 38; ks++) {
            const int kb = ks * 8;
            unsigned a[4], b[2];
            a[0] = Pt[r * SPAD + kb + lc];
            a[1] = Pt[(r + 8) * SPAD + kb + lc];
            a[2] = Pt[r * SPAD + kb + lc + 4];
            a[3] = Pt[(r + 8) * SPAD + kb + lc + 4];
            b[0] = Ct[c * SPAD + kb + lc];
            b[1] = Ct[c * SPAD + kb + lc + 4];
            mma8(acc, a, b);
        }
    }

    {
        int r = wm * 16 + lr;
        int cb = wn * 8 + 2 * lc;
        int gc = j0 + cb;
        Sh[r * 17 + cb]           = (r == gc)         ? NEGV : acc[0];
        Sh[r * 17 + cb + 1]       = (r == gc + 1)     ? NEGV : acc[1];
        Sh[(r + 8) * 17 + cb]     = (r + 8 == gc)     ? NEGV : acc[2];
        Sh[(r + 8) * 17 + cb + 1] = (r + 8 == gc + 1) ? NEGV : acc[3];
    }
    __syncthreads();

    #pragma unroll
    for (int cc = 0; cc < 2; cc++) {
        int c = wid * 2 + cc;
        float v0 = Sh[lane * 17 + c];
        float v1 = Sh[(lane + 32) * 17 + c];
        float m = fmaxf(v0, v1);
        #pragma unroll
        for (int o = 16; o; o >>= 1) m = fmaxf(m, __shfl_xor_sync(0xffffffffu, m, o));
        float e0 = __expf(v0 - m), e1 = __expf(v1 - m);
        float s = e0 + e1;
        #pragma unroll
        for (int o = 16; o; o >>= 1) s += __shfl_xor_sync(0xffffffffu, s, o);
        float inv = 1.f / s;
        Sh[lane * 17 + c]        = e0 * inv;
        Sh[(lane + 32) * 17 + c] = e1 * inv;
    }
    __syncthreads();

    for (int u = t; u < 64 * 16; u += 256) {
        int i = u >> 4, j = u & 15;
        A_out[(long)d * 4096 + i * 64 + j0 + j] = Sh[i * 17 + j];
    }

    // ---------- extras ----------
    if (blockIdx.x == 0) {
        // fri = softmax(enc @ w_root + b_root) for this d
        const float* Ed = enc + (long)d * S * H;
        const float br0 = b_root[0];
        #pragma unroll
        for (int ss = 0; ss < 8; ss++) {
            int s = wid * 8 + ss;
            const float* e = Ed + s * H;
            float p = 0.f;
            for (int h = lane; h < H; h += 32) p += e[h] * w_root[h];
            #pragma unroll
            for (int o = 16; o; o >>= 1) p += __shfl_xor_sync(0xffffffffu, p, o);
            if (lane == 0) sred[s] = p + br0;
        }
        __syncthreads();
        float mye = 0.f;
        if (t < 64) {
            float m = -1e30f;
            for (int u = 0; u < 64; u++) m = fmaxf(m, sred[u]);
            mye = __expf(sred[t] - m);
        }
        __syncthreads();
        if (t < 64) sred[t] = mye;
        __syncthreads();
        if (t < 64) {
            float ssum = 0.f;
            for (int u = 0; u < 64; u++) ssum += sred[u];
            fri_out[d * 64 + t] = mye / ssum;
        }
    } else if (blockIdx.x == 1) {
        // v2[n] = W_r[n, 300:600] . root_embed, n = d*5 .. d*5+4
        if (wid < 5) {
            int n = d * 5 + wid;
            if (n < H) {
                const float* w = W_r + (long)n * 900 + 300;
                float p = 0.f;
                for (int k = lane; k < H; k += 32) p += w[k] * root_embed[k];
                #pragma unroll
                for (int o = 16; o; o >>= 1) p += __shfl_xor_sync(0xffffffffu, p, o);
                if (lane == 0) v2_out[n] = p;
            }
        }
    }
}

// =====================================================================
// Fused ri+mean with in-block G:
//   G[d,i,h] = sum_k A[d,k,i] * Y2[d,k,h]     (computed in-block)
//   rs[i]    = sum_j A[d,i,j]                 (computed in-block, fp32)
//   fin[doc,n] = mean_s lrelu( enc@W1^T + rs*(enc@W3^T) + G + fri*v2 + b_r )
// Grid (5, 32); block covers 2 docs x 64 cols.
// =====================================================================
__global__ void ri_mean_kernel(const float* __restrict__ enc,
                               const float* __restrict__ W_r,   // [H, 900]
                               const float* __restrict__ b_r,
                               const float* __restrict__ A_in,  // [D,64,64]
                               const float* __restrict__ Y2,    // [NROWS,H]
                               const float* __restrict__ fri,
                               const float* __restrict__ v2,
                               float* __restrict__ fin)
{
    // buf overlays: main loop {As[128][20], B1s[64][20], B3s[64][20]} = 5120 words
    //               G phase   {Ak[64][65], Ys[64][65]}               = 8320 words
    __shared__ __align__(16) unsigned buf[8320];
    __shared__ float red[2][BN];
    __shared__ float rs_sh[BM];

    unsigned (*As)[BKP]  = (unsigned(*)[BKP])buf;            // [128][20]
    unsigned (*B1s)[BKP] = (unsigned(*)[BKP])(buf + 2560);   // [64][20]
    unsigned (*B3s)[BKP] = (unsigned(*)[BKP])(buf + 3840);   // [64][20]
    unsigned (*Ak)[65]   = (unsigned(*)[65])buf;             // [64][65]
    unsigned (*Ys)[65]   = (unsigned(*)[65])(buf + 4160);    // [64][65]

    const int K = H;
    const int N = H;
    const int tid  = threadIdx.x;
    const int lane = tid & 31;
    const int wid  = tid >> 5;
    const int wm = wid >> 1, wn = wid & 1;
    const int m0 = blockIdx.y * BM;
    const int n0 = blockIdx.x * BN;

    if (tid < 2 * BN) ((float*)red)[tid] = 0.f;

    // ---- rs from fp32 A: thread pair per row ----
    {
        int rr   = tid >> 1;        // 0..127
        int half = tid & 1;
        int doc  = blockIdx.y * 2 + (rr >> 6);
        int rloc = rr & 63;
        const float* arow = A_in + (long)doc * 4096 + rloc * 64 + half * 32;
        float s = 0.f;
        #pragma unroll 8
        for (int j = 0; j < 32; j++) s += arow[j];
        s += __shfl_xor_sync(0xffffffffu, s, 1);
        if (half == 0) rs_sh[rr] = s;
    }

    const int am0 = tid >> 2;
    const int ac  = (tid & 3) * 4;
    const long aoff0 = (long)(m0 + am0) * K;
    const long aoff1 = (long)(m0 + am0 + 64) * K;
    const int  bn     = tid >> 2;
    const bool bvalid = (n0 + bn) < N;
    const long boff   = (long)(n0 + bn) * 900;

    float acc1[2][4][4], acc3[2][4][4];
    #pragma unroll
    for (int i = 0; i < 2; i++)
        #pragma unroll
        for (int j = 0; j < 4; j++)
            #pragma unroll
            for (int q = 0; q < 4; q++) { acc1[i][j][q] = 0.f; acc3[i][j][q] = 0.f; }

    const int lr = lane >> 2, lc = lane & 3;

    for (int k0 = 0; k0 < K; k0 += BK) {
        if (k0 > 0 || true) __syncthreads();   // protects buf (also orders rs_sh)
        if (k0 + BK <= K) {
            float4 a0 = *(const float4*)(enc + aoff0 + k0 + ac);
            float4 a1 = *(const float4*)(enc + aoff1 + k0 + ac);
            float4 b1 = bvalid ? *(const float4*)(W_r + boff + k0 + ac) : make_float4(0,0,0,0);
            float4 b3 = bvalid ? *(const float4*)(W_r + boff + 600 + k0 + ac) : make_float4(0,0,0,0);
            *(uint4*)&As[am0][ac]      = cvt4(a0);
            *(uint4*)&As[am0 + 64][ac] = cvt4(a1);
            *(uint4*)&B1s[bn][ac]      = cvt4(b1);
            *(uint4*)&B3s[bn][ac]      = cvt4(b3);
        } else {
            #pragma unroll
            for (int u = 0; u < 4; u++) {
                int k = k0 + ac + u;
                bool kk = k < K;
                As[am0][ac + u]      = kk ? f2tf32(enc[aoff0 + k]) : 0u;
                As[am0 + 64][ac + u] = kk ? f2tf32(enc[aoff1 + k]) : 0u;
                B1s[bn][ac + u]      = (bvalid && kk) ? f2tf32(W_r[boff + k]) : 0u;
                B3s[bn][ac + u]      = (bvalid && kk) ? f2tf32(W_r[boff + 600 + k]) : 0u;
            }
        }
        __syncthreads();
        #pragma unroll
        for (int ks = 0; ks < 2; ks++) {
            const int kb = ks * 8;
            unsigned a[2][4], b1[4][2], b3[4][2];
            #pragma unroll
            for (int mi = 0; mi < 2; mi++) {
                int r = wm * 32 + mi * 16 + lr;
                a[mi][0] = As[r][kb + lc];
                a[mi][1] = As[r + 8][kb + lc];
                a[mi][2] = As[r][kb + lc + 4];
                a[mi][3] = As[r + 8][kb + lc + 4];
            }
            #pragma unroll
            for (int ni = 0; ni < 4; ni++) {
                int c = wn * 32 + ni * 8 + lr;
                b1[ni][0] = B1s[c][kb + lc];
                b1[ni][1] = B1s[c][kb + lc + 4];
                b3[ni][0] = B3s[c][kb + lc];
                b3[ni][1] = B3s[c][kb + lc + 4];
            }
            #pragma unroll
            for (int mi = 0; mi < 2; mi++)
                #pragma unroll
                for (int ni = 0; ni < 4; ni++) {
                    mma8(acc1[mi][ni], a[mi], b1[ni]);
                    mma8(acc3[mi][ni], a[mi], b3[ni]);
                }
        }
    }

    // ---- G phase: 2 docs, buf reused for Ak/Ys ----
    float gacc[2][4][4];
    #pragma unroll
    for (int i = 0; i < 2; i++)
        #pragma unroll
        for (int j = 0; j < 4; j++)
            #pragma unroll
            for (int q = 0; q < 4; q++) gacc[i][j][q] = 0.f;

    for (int dd = 0; dd < 2; dd++) {
        __syncthreads();
        const int doc = blockIdx.y * 2 + dd;
        const float* Ad = A_in + (long)doc * 4096;
        const float* Yd = Y2 + (long)doc * 64 * H;
        for (int u = tid; u < 1024; u += 256) {
            float4 v = ((const float4*)Ad)[u];
            int k = u >> 4, i = (u & 15) * 4;
            Ak[k][i]     = f2tf32(v.x);
            Ak[k][i + 1] = f2tf32(v.y);
            Ak[k][i + 2] = f2tf32(v.z);
            Ak[k][i + 3] = f2tf32(v.w);
        }
        for (int u = tid; u < 1024; u += 256) {
            int k = u >> 4, i = (u & 15) * 4;
            int h = n0 + i;
            float4 v = make_float4(0.f, 0.f, 0.f, 0.f);
            if (h < H) v = *(const float4*)(Yd + k * H + h);
            Ys[k][i]     = f2tf32(v.x);
            Ys[k][i + 1] = f2tf32(v.y);
            Ys[k][i + 2] = f2tf32(v.z);
            Ys[k][i + 3] = f2tf32(v.w);
        }
        __syncthreads();

        if ((wm >> 1) == dd) {
            const int rbase = (wm & 1) * 32;
            #pragma unroll
            for (int ks = 0; ks < 8; ks++) {
                const int kb = ks * 8;
                unsigned a[2][4], b[4][2];
                #pragma unroll
                for (int mi = 0; mi < 2; mi++) {
                    int rloc = rbase + mi * 16 + lr;
                    a[mi][0] = Ak[kb + lc][rloc];
                    a[mi][1] = Ak[kb + lc][rloc + 8];
                    a[mi][2] = Ak[kb + lc + 4][rloc];
                    a[mi][3] = Ak[kb + lc + 4][rloc + 8];
                }
                #pragma unroll
                for (int ni = 0; ni < 4; ni++) {
                    int c = wn * 32 + ni * 8 + lr;
                    b[ni][0] = Ys[kb + lc][c];
                    b[ni][1] = Ys[kb + lc + 4][c];
                }
                #pragma unroll
                for (int mi = 0; mi < 2; mi++)
                    #pragma unroll
                    for (int ni = 0; ni < 4; ni++)
                        mma8(gacc[mi][ni], a[mi], b[ni]);
            }
        }
    }
    __syncthreads();

    // ---- epilogue: combine + lrelu + per-document column mean ----
    const int dl = wm >> 1;
    #pragma unroll
    for (int ni = 0; ni < 4; ni++) {
        int cb = n0 + wn * 32 + ni * 8 + 2 * lc;
        float s0 = 0.f, s1 = 0.f;
        #pragma unroll
        for (int mi = 0; mi < 2; mi++) {
            #pragma unroll
            for (int half = 0; half < 2; half++) {
                int rloc = wm * 32 + mi * 16 + lr + half * 8;   // 0..127
                int m = m0 + rloc;
                float rsm = rs_sh[rloc], frm = fri[m];
                if (cb < N) {
                    float v = acc1[mi][ni][half * 2] + rsm * acc3[mi][ni][half * 2]
                            + gacc[mi][ni][half * 2] + frm * v2[cb] + b_r[cb];
                    s0 += lrelu_f(v);
                }
                if (cb + 1 < N) {
                    float v = acc1[mi][ni][half * 2 + 1] + rsm * acc3[mi][ni][half * 2 + 1]
                            + gacc[mi][ni][half * 2 + 1] + frm * v2[cb + 1] + b_r[cb + 1];
                    s1 += lrelu_f(v);
                }
            }
        }
        #pragma unroll
        for (int o = 4; o < 32; o <<= 1) {
            s0 += __shfl_xor_sync(0xffffffffu, s0, o);
            s1 += __shfl_xor_sync(0xffffffffu, s1, o);
        }
        if (lane < 4) {
            atomicAdd(&red[dl][wn * 32 + ni * 8 + 2 * lc],     s0);
            atomicAdd(&red[dl][wn * 32 + ni * 8 + 2 * lc + 1], s1);
        }
    }
    __syncthreads();
    if (tid < 128) {
        int dloc = tid >> 6, c = tid & 63;
        int col = n0 + c;
        if (col < N)
            fin[(long)(blockIdx.y * 2 + dloc) * H + col] = red[dloc][c] * (1.f / 64.f);
    }
}

// out[d,c]: one warp per output
__global__ void cls_kernel(const float* __restrict__ fin,
                           const float* __restrict__ Wc,
                           const float* __restrict__ bc,
                           float* __restrict__ out)
{
    int gw = blockIdx.x * (blockDim.x >> 5) + (threadIdx.x >> 5);
    int lane = threadIdx.x & 31;
    if (gw >= 128) return;
    int d = gw >> 1, c = gw & 1;
    const float* f = fin + d * H;
    const float* w = Wc + c * H;
    float p = 0.f;
    for (int h = lane; h < H; h += 32) p += f[h] * w[h];
    #pragma unroll
    for (int o = 16; o; o >>= 1) p += __shfl_xor_sync(0xffffffffu, p, o);
    if (lane == 0) out[d * 2 + c] = p + bc[c];
}

// =====================================================================
extern "C" void kernel_launch(void* const* d_in, const int* in_sizes, int n_in,
                              void* d_out, int out_size)
{
    const int*   word_indices = (const int*)  d_in[0];
    const float* E            = (const float*)d_in[1];
    const float* W_sent       = (const float*)d_in[2];
    const float* b_sent       = (const float*)d_in[3];
    const float* W_par        = (const float*)d_in[4];
    const float* b_par        = (const float*)d_in[5];
    const float* W_ch         = (const float*)d_in[6];
    const float* b_ch         = (const float*)d_in[7];
    const float* w_root       = (const float*)d_in[8];
    const float* b_root       = (const float*)d_in[9];
    const float* root_embed   = (const float*)d_in[10];
    const float* W_r          = (const float*)d_in[11];
    const float* b_r          = (const float*)d_in[12];
    const float* W_cls        = (const float*)d_in[13];
    const float* b_cls        = (const float*)d_in[14];

    float* out_ptr = (float*)d_out;
    float* A_ptr   = out_ptr + D * 2;
    float* fri_ptr = A_ptr + D * S * S;

    float *enc, *Pm, *Cm, *Y2, *fin, *v2;
    cudaGetSymbolAddress((void**)&enc, g_enc);
    cudaGetSymbolAddress((void**)&Pm,  g_P);
    cudaGetSymbolAddress((void**)&Cm,  g_C);
    cudaGetSymbolAddress((void**)&Y2,  g_Y2);
    cudaGetSymbolAddress((void**)&fin, g_fin);
    cudaGetSymbolAddress((void**)&v2,  g_v2);

    cudaFuncSetAttribute(scores_kernel,
                         cudaFuncAttributeMaxDynamicSharedMemorySize, SCORES_SMEM);

    dim3 gEnc((H + BN - 1) / BN, NROWS / BM, 1);
    gemm_tf32_kernel<true><<<gEnc, 256>>>(
        E, word_indices + (L - 1), L,
        W_sent, b_sent, enc,
        nullptr, nullptr, nullptr,
        nullptr, nullptr, nullptr, H, W, W, W, W);

    // P, C (lrelu+bias) and Y2 = enc @ W2^T (linear; W2 rows inside W_r, ld=900)
    dim3 gPCY((H + BN - 1) / BN, NROWS / BM, 3);
    gemm_tf32_kernel<false><<<gPCY, 256>>>(
        enc, nullptr, 0,
        W_par,       b_par,   Pm,
        W_ch,        b_ch,    Cm,
        W_r + 300,   nullptr, Y2,
        H, H, H, H, 900);

    // scores + mask + column softmax -> A (in d_out); fri (jb==0), v2 (jb==1)
    scores_kernel<<<dim3(4, D), 256, SCORES_SMEM>>>(
        Pm, Cm, enc, w_root, b_root, W_r, root_embed, A_ptr, fri_ptr, v2);

    // fused ri + in-block G + rs + mean
    ri_mean_kernel<<<dim3(5, 32), 256>>>(enc, W_r, b_r, A_ptr, Y2, fri_ptr, v2, fin);

    cls_kernel<<<8, 512>>>(fin, W_cls, b_cls, out_ptr);
}

// round 10
// speedup vs baseline: 1.0030x; 1.0030x over previous
#include <cuda_runtime.h>

#define D 64
#define S 64
#define L 64
#define W 300
#define H 300
#define NROWS (D*S)          // 4096
#define NEGV (-9999999.0f)

// ---------------- device scratch (no allocation allowed) ----------------
__device__ float g_enc[NROWS * H];
__device__ float g_P  [NROWS * H];
__device__ float g_C  [NROWS * H];
__device__ float g_Y2 [NROWS * H];
__device__ float g_G  [NROWS * H];
__device__ float g_fin[D * H];
__device__ float g_v2 [H];

__device__ __forceinline__ float lrelu_f(float x) { return x > 0.f ? x : 0.01f * x; }

__device__ __forceinline__ unsigned f2tf32(float f) {
    unsigned u;
    asm("cvt.rna.tf32.f32 %0, %1;" : "=r"(u) : "f"(f));
    return u;
}
__device__ __forceinline__ uint4 cvt4(float4 v) {
    return make_uint4(f2tf32(v.x), f2tf32(v.y), f2tf32(v.z), f2tf32(v.w));
}

__device__ __forceinline__ void mma8(float* c, const unsigned* a, const unsigned* b) {
    asm volatile(
        "mma.sync.aligned.m16n8k8.row.col.f32.tf32.tf32.f32 "
        "{%0,%1,%2,%3}, {%4,%5,%6,%7}, {%8,%9}, {%0,%1,%2,%3};"
        : "+f"(c[0]), "+f"(c[1]), "+f"(c[2]), "+f"(c[3])
        : "r"(a[0]), "r"(a[1]), "r"(a[2]), "r"(a[3]), "r"(b[0]), "r"(b[1]));
}

#define BM 128
#define BN 64
#define BK 16
#define BKP 20

// =====================================================================
// TF32 GEMM (R5-proven): Out[M,N] = act( A[M,K] @ B[N,K(ld=ldb)]^T + b )
// z selects among 3 (B,bias,Out) triples; bias==nullptr => linear.
// =====================================================================
template<bool GATHER>
__global__ void gemm_tf32_kernel(
    const float* __restrict__ Abase, const int* __restrict__ idx, int idxStride,
    const float* __restrict__ B0, const float* __restrict__ bias0, float* __restrict__ Out0,
    const float* __restrict__ B1, const float* __restrict__ bias1, float* __restrict__ Out1,
    const float* __restrict__ B2, const float* __restrict__ bias2, float* __restrict__ Out2,
    int N, int K, int ldb0, int ldb1, int ldb2)
{
    const float* Bw   = B0;
    const float* bias = bias0;
    float*       Out  = Out0;
    int          ldb  = ldb0;
    if (blockIdx.z == 1) { Bw = B1; bias = bias1; Out = Out1; ldb = ldb1; }
    if (blockIdx.z == 2) { Bw = B2; bias = bias2; Out = Out2; ldb = ldb2; }
    const bool act = (bias != nullptr);

    __shared__ __align__(16) unsigned As[BM][BKP];
    __shared__ __align__(16) unsigned Bs[BN][BKP];

    const int tid  = threadIdx.x;
    const int lane = tid & 31;
    const int wid  = tid >> 5;
    const int wm   = wid >> 1;
    const int wn   = wid & 1;
    const int m0   = blockIdx.y * BM;
    const int n0   = blockIdx.x * BN;

    const int am0 = tid >> 2;
    const int ac  = (tid & 3) * 4;
    long aoff0, aoff1;
    if (GATHER) {
        aoff0 = (long)idx[(long)(m0 + am0) * idxStride] * K;
        aoff1 = (long)idx[(long)(m0 + am0 + 64) * idxStride] * K;
    } else {
        aoff0 = (long)(m0 + am0) * K;
        aoff1 = (long)(m0 + am0 + 64) * K;
    }
    const int  bn     = tid >> 2;
    const bool bvalid = (n0 + bn) < N;
    const long boff   = (long)(n0 + bn) * ldb;

    float acc[2][4][4];
    #pragma unroll
    for (int i = 0; i < 2; i++)
        #pragma unroll
        for (int j = 0; j < 4; j++)
            #pragma unroll
            for (int q = 0; q < 4; q++) acc[i][j][q] = 0.f;

    const int lr = lane >> 2;
    const int lc = lane & 3;

    for (int k0 = 0; k0 < K; k0 += BK) {
        if (k0 + BK <= K) {
            float4 a0 = *(const float4*)(Abase + aoff0 + k0 + ac);
            float4 a1 = *(const float4*)(Abase + aoff1 + k0 + ac);
            float4 bv = bvalid ? *(const float4*)(Bw + boff + k0 + ac)
                               : make_float4(0.f, 0.f, 0.f, 0.f);
            *(uint4*)&As[am0][ac]      = cvt4(a0);
            *(uint4*)&As[am0 + 64][ac] = cvt4(a1);
            *(uint4*)&Bs[bn][ac]       = cvt4(bv);
        } else {
            #pragma unroll
            for (int u = 0; u < 4; u++) {
                int k = k0 + ac + u;
                As[am0][ac + u]      = (k < K) ? f2tf32(Abase[aoff0 + k]) : 0u;
                As[am0 + 64][ac + u] = (k < K) ? f2tf32(Abase[aoff1 + k]) : 0u;
                Bs[bn][ac + u]       = (bvalid && k < K) ? f2tf32(Bw[boff + k]) : 0u;
            }
        }
        __syncthreads();
        #pragma unroll
        for (int ks = 0; ks < 2; ks++) {
            const int kb = ks * 8;
            unsigned a[2][4], b[4][2];
            #pragma unroll
            for (int mi = 0; mi < 2; mi++) {
                int r = wm * 32 + mi * 16 + lr;
                a[mi][0] = As[r][kb + lc];
                a[mi][1] = As[r + 8][kb + lc];
                a[mi][2] = As[r][kb + lc + 4];
                a[mi][3] = As[r + 8][kb + lc + 4];
            }
            #pragma unroll
            for (int ni = 0; ni < 4; ni++) {
                int c = wn * 32 + ni * 8 + lr;
                b[ni][0] = Bs[c][kb + lc];
                b[ni][1] = Bs[c][kb + lc + 4];
            }
            #pragma unroll
            for (int mi = 0; mi < 2; mi++)
                #pragma unroll
                for (int ni = 0; ni < 4; ni++)
                    mma8(acc[mi][ni], a[mi], b[ni]);
        }
        __syncthreads();
    }

    #pragma unroll
    for (int mi = 0; mi < 2; mi++) {
        int r = m0 + wm * 32 + mi * 16 + lr;
        #pragma unroll
        for (int ni = 0; ni < 4; ni++) {
            int cb = n0 + wn * 32 + ni * 8 + 2 * lc;
            #pragma unroll
            for (int q = 0; q < 2; q++) {
                int cc = cb + q;
                if (cc >= N) continue;
                float bv = act ? bias[cc] : 0.f;
                float v0 = acc[mi][ni][q]     + bv;
                float v1 = acc[mi][ni][q + 2] + bv;
                if (act) { v0 = lrelu_f(v0); v1 = lrelu_f(v1); }
                Out[(long)r * N + cc]       = v0;
                Out[(long)(r + 8) * N + cc] = v1;
            }
        }
    }
}

// =====================================================================
// Scores + diag mask + column softmax + G, grid (4, D), 256 thr.
// Block (jb, d): A[d, :, j0:j0+16] and then G[d, j0:j0+16, :]
// (G[d,i,h] = sum_k A[d,k,i] Y2[d,k,h]; the block's Sh slab IS the A
// it needs; Y2[d] is reloaded into the dead Pt buffer).
// Extras: jb==0 -> fri[d,:], jb==1 -> v2 slice (n = d*5..d*5+4).
// =====================================================================
#define SPAD 308
#define SCORES_SMEM ((80 * SPAD + 64 * 17) * 4)   // 102,912 B

__global__ void scores_kernel(const float* __restrict__ P,
                              const float* __restrict__ Cm,
                              const float* __restrict__ Y2,
                              const float* __restrict__ enc,
                              const float* __restrict__ w_root,
                              const float* __restrict__ b_root,
                              const float* __restrict__ W_r,
                              const float* __restrict__ root_embed,
                              float* __restrict__ A_out,
                              float* __restrict__ G_out,
                              float* __restrict__ fri_out,
                              float* __restrict__ v2_out)
{
    extern __shared__ unsigned sdyn[];
    unsigned* Pt = sdyn;                       // [64][SPAD]; later reused for Y2
    unsigned* Ct = sdyn + 64 * SPAD;           // [16][SPAD]
    float*    Sh = (float*)(sdyn + 80 * SPAD); // [64][17]
    __shared__ float sred[64];

    const int d  = blockIdx.y;
    const int j0 = blockIdx.x * 16;
    const int t = threadIdx.x;
    const int lane = t & 31;
    const int wid  = t >> 5;
    const int wm = wid >> 1;    // 0..3
    const int wn = wid & 1;     // 0..1
    const int lr = lane >> 2, lc = lane & 3;

    const float4* Pd4 = (const float4*)(P  + (long)d * S * H);   // 75 float4 per row
    const float4* Cd4 = (const float4*)(Cm + (long)d * S * H);

    for (int u = t; u < 64 * 76; u += 256) {
        int r = u / 76, c4 = u - r * 76;
        float4 v = make_float4(0.f, 0.f, 0.f, 0.f);
        if (c4 < 75) v = Pd4[r * 75 + c4];
        *(uint4*)&Pt[r * SPAD + c4 * 4] = cvt4(v);
    }
    for (int u = t; u < 16 * 76; u += 256) {
        int r = u / 76, c4 = u - r * 76;
        float4 v = make_float4(0.f, 0.f, 0.f, 0.f);
        if (c4 < 75) v = Cd4[(j0 + r) * 75 + c4];
        *(uint4*)&Ct[r * SPAD + c4 * 4] = cvt4(v);
    }
    __syncthreads();

    float acc[4] = {};
    {
        const int r = wm * 16 + lr;
        const int c = wn * 8 + lr;
        #pragma unroll
        for (int ks = 0; ks < 38; ks++) {
            const int kb = ks * 8;
            unsigned a[4], b[2];
            a[0] = Pt[r * SPAD + kb + lc];
            a[1] = Pt[(r + 8) * SPAD + kb + lc];
            a[2] = Pt[r * SPAD + kb + lc + 4];
            a[3] = Pt[(r + 8) * SPAD + kb + lc + 4];
            b[0] = Ct[c * SPAD + kb + lc];
            b[1] = Ct[c * SPAD + kb + lc + 4];
            mma8(acc, a, b);
        }
    }

    {
        int r = wm * 16 + lr;
        int cb = wn * 8 + 2 * lc;
        int gc = j0 + cb;
        Sh[r * 17 + cb]           = (r == gc)         ? NEGV : acc[0];
        Sh[r * 17 + cb + 1]       = (r == gc + 1)     ? NEGV : acc[1];
        Sh[(r + 8) * 17 + cb]     = (r + 8 == gc)     ? NEGV : acc[2];
        Sh[(r + 8) * 17 + cb + 1] = (r + 8 == gc + 1) ? NEGV : acc[3];
    }
    __syncthreads();

    #pragma unroll
    for (int cc = 0; cc < 2; cc++) {
        int c = wid * 2 + cc;
        float v0 = Sh[lane * 17 + c];
        float v1 = Sh[(lane + 32) * 17 + c];
        float m = fmaxf(v0, v1);
        #pragma unroll
        for (int o = 16; o; o >>= 1) m = fmaxf(m, __shfl_xor_sync(0xffffffffu, m, o));
        float e0 = __expf(v0 - m), e1 = __expf(v1 - m);
        float s = e0 + e1;
        #pragma unroll
        for (int o = 16; o; o >>= 1) s += __shfl_xor_sync(0xffffffffu, s, o);
        float inv = 1.f / s;
        Sh[lane * 17 + c]        = e0 * inv;
        Sh[(lane + 32) * 17 + c] = e1 * inv;
    }
    __syncthreads();   // Sh final; all mma reads of Pt long done

    // write A slab + reload Pt with Y2[d] (tf32), in the same pass
    for (int u = t; u < 64 * 16; u += 256) {
        int i = u >> 4, j = u & 15;
        A_out[(long)d * 4096 + i * 64 + j0 + j] = Sh[i * 17 + j];
    }
    {
        const float4* Yd4 = (const float4*)(Y2 + (long)d * S * H);
        for (int u = t; u < 64 * 76; u += 256) {
            int r = u / 76, c4 = u - r * 76;
            float4 v = make_float4(0.f, 0.f, 0.f, 0.f);
            if (c4 < 75) v = Yd4[r * 75 + c4];
            *(uint4*)&Pt[r * SPAD + c4 * 4] = cvt4(v);
        }
    }
    __syncthreads();

    // ---- G phase: one m16 tile (rows j0..j0+15), 38 n-tiles over 8 warps ----
    for (int nt = wid; nt < 38; nt += 8) {
        float gac[4] = {};
        #pragma unroll
        for (int ks = 0; ks < 8; ks++) {
            const int kb = ks * 8;
            unsigned a[4], b[2];
            a[0] = f2tf32(Sh[(kb + lc) * 17 + lr]);
            a[1] = f2tf32(Sh[(kb + lc) * 17 + lr + 8]);
            a[2] = f2tf32(Sh[(kb + lc + 4) * 17 + lr]);
            a[3] = f2tf32(Sh[(kb + lc + 4) * 17 + lr + 8]);
            int c = nt * 8 + lr;
            b[0] = Pt[(kb + lc) * SPAD + c];
            b[1] = Pt[(kb + lc + 4) * SPAD + c];
            mma8(gac, a, b);
        }
        #pragma unroll
        for (int q = 0; q < 2; q++) {
            int h = nt * 8 + 2 * lc + q;
            if (h < H) {
                G_out[(long)(d * 64 + j0 + lr) * H + h]     = gac[q];
                G_out[(long)(d * 64 + j0 + lr + 8) * H + h] = gac[q + 2];
            }
        }
    }

    // ---------- extras ----------
    if (blockIdx.x == 0) {
        const float* Ed = enc + (long)d * S * H;
        const float br0 = b_root[0];
        #pragma unroll
        for (int ss = 0; ss < 8; ss++) {
            int s = wid * 8 + ss;
            const float* e = Ed + s * H;
            float p = 0.f;
            for (int h = lane; h < H; h += 32) p += e[h] * w_root[h];
            #pragma unroll
            for (int o = 16; o; o >>= 1) p += __shfl_xor_sync(0xffffffffu, p, o);
            if (lane == 0) sred[s] = p + br0;
        }
        __syncthreads();
        float mye = 0.f;
        if (t < 64) {
            float m = -1e30f;
            for (int u = 0; u < 64; u++) m = fmaxf(m, sred[u]);
            mye = __expf(sred[t] - m);
        }
        __syncthreads();
        if (t < 64) sred[t] = mye;
        __syncthreads();
        if (t < 64) {
            float ssum = 0.f;
            for (int u = 0; u < 64; u++) ssum += sred[u];
            fri_out[d * 64 + t] = mye / ssum;
        }
    } else if (blockIdx.x == 1) {
        if (wid < 5) {
            int n = d * 5 + wid;
            if (n < H) {
                const float* w = W_r + (long)n * 900 + 300;
                float p = 0.f;
                for (int k = lane; k < H; k += 32) p += w[k] * root_embed[k];
                #pragma unroll
                for (int o = 16; o; o >>= 1) p += __shfl_xor_sync(0xffffffffu, p, o);
                if (lane == 0) v2_out[n] = p;
            }
        }
    }
}

// =====================================================================
// ri+mean (R8-proven core, rs computed in-block from A):
// fin[doc,n] = mean_s lrelu( enc@W1^T + rs*(enc@W3^T) + G + fri*v2 + b_r )
// =====================================================================
__global__ void ri_mean_kernel(const float* __restrict__ enc,
                               const float* __restrict__ W_r,   // [H, 900]
                               const float* __restrict__ b_r,
                               const float* __restrict__ G,
                               const float* __restrict__ A_in,
                               const float* __restrict__ fri,
                               const float* __restrict__ v2,
                               float* __restrict__ fin)
{
    __shared__ __align__(16) unsigned As[BM][BKP];
    __shared__ __align__(16) unsigned B1s[BN][BKP];
    __shared__ __align__(16) unsigned B3s[BN][BKP];
    __shared__ float red[2][BN];
    __shared__ float rs_sh[BM];

    const int K = H;
    const int N = H;
    const int tid  = threadIdx.x;
    const int lane = tid & 31;
    const int wid  = tid >> 5;
    const int wm = wid >> 1, wn = wid & 1;
    const int m0 = blockIdx.y * BM;
    const int n0 = blockIdx.x * BN;

    if (tid < 2 * BN) ((float*)red)[tid] = 0.f;

    // rs from fp32 A: thread-pair per row (proven in R9)
    {
        int rr   = tid >> 1;
        int half = tid & 1;
        int doc  = blockIdx.y * 2 + (rr >> 6);
        int rloc = rr & 63;
        const float* arow = A_in + (long)doc * 4096 + rloc * 64 + half * 32;
        float s = 0.f;
        #pragma unroll 8
        for (int j = 0; j < 32; j++) s += arow[j];
        s += __shfl_xor_sync(0xffffffffu, s, 1);
        if (half == 0) rs_sh[rr] = s;
    }

    const int am0 = tid >> 2;
    const int ac  = (tid & 3) * 4;
    const long aoff0 = (long)(m0 + am0) * K;
    const long aoff1 = (long)(m0 + am0 + 64) * K;
    const int  bn     = tid >> 2;
    const bool bvalid = (n0 + bn) < N;
    const long boff   = (long)(n0 + bn) * 900;

    float acc1[2][4][4], acc3[2][4][4];
    #pragma unroll
    for (int i = 0; i < 2; i++)
        #pragma unroll
        for (int j = 0; j < 4; j++)
            #pragma unroll
            for (int q = 0; q < 4; q++) { acc1[i][j][q] = 0.f; acc3[i][j][q] = 0.f; }

    const int lr = lane >> 2, lc = lane & 3;

    for (int k0 = 0; k0 < K; k0 += BK) {
        if (k0 + BK <= K) {
            float4 a0 = *(const float4*)(enc + aoff0 + k0 + ac);
            float4 a1 = *(const float4*)(enc + aoff1 + k0 + ac);
            float4 b1 = bvalid ? *(const float4*)(W_r + boff + k0 + ac) : make_float4(0,0,0,0);
            float4 b3 = bvalid ? *(const float4*)(W_r + boff + 600 + k0 + ac) : make_float4(0,0,0,0);
            *(uint4*)&As[am0][ac]      = cvt4(a0);
            *(uint4*)&As[am0 + 64][ac] = cvt4(a1);
            *(uint4*)&B1s[bn][ac]      = cvt4(b1);
            *(uint4*)&B3s[bn][ac]      = cvt4(b3);
        } else {
            #pragma unroll
            for (int u = 0; u < 4; u++) {
                int k = k0 + ac + u;
                bool kk = k < K;
                As[am0][ac + u]      = kk ? f2tf32(enc[aoff0 + k]) : 0u;
                As[am0 + 64][ac + u] = kk ? f2tf32(enc[aoff1 + k]) : 0u;
                B1s[bn][ac + u]      = (bvalid && kk) ? f2tf32(W_r[boff + k]) : 0u;
                B3s[bn][ac + u]      = (bvalid && kk) ? f2tf32(W_r[boff + 600 + k]) : 0u;
            }
        }
        __syncthreads();
        #pragma unroll
        for (int ks = 0; ks < 2; ks++) {
            const int kb = ks * 8;
            unsigned a[2][4], b1[4][2], b3[4][2];
            #pragma unroll
            for (int mi = 0; mi < 2; mi++) {
                int r = wm * 32 + mi * 16 + lr;
                a[mi][0] = As[r][kb + lc];
                a[mi][1] = As[r + 8][kb + lc];
                a[mi][2] = As[r][kb + lc + 4];
                a[mi][3] = As[r + 8][kb + lc + 4];
            }
            #pragma unroll
            for (int ni = 0; ni < 4; ni++) {
                int c = wn * 32 + ni * 8 + lr;
                b1[ni][0] = B1s[c][kb + lc];
                b1[ni][1] = B1s[c][kb + lc + 4];
                b3[ni][0] = B3s[c][kb + lc];
                b3[ni][1] = B3s[c][kb + lc + 4];
            }
            #pragma unroll
            for (int mi = 0; mi < 2; mi++)
                #pragma unroll
                for (int ni = 0; ni < 4; ni++) {
                    mma8(acc1[mi][ni], a[mi], b1[ni]);
                    mma8(acc3[mi][ni], a[mi], b3[ni]);
                }
        }
        __syncthreads();
    }

    const int dl = wm >> 1;
    #pragma unroll
    for (int ni = 0; ni < 4; ni++) {
        int cb = n0 + wn * 32 + ni * 8 + 2 * lc;
        float s0 = 0.f, s1 = 0.f;
        #pragma unroll
        for (int mi = 0; mi < 2; mi++) {
            int rl = wm * 32 + mi * 16 + lr;
            #pragma unroll
            for (int half = 0; half < 2; half++) {
                int rloc = rl + half * 8;
                int m = m0 + rloc;
                float rsm = rs_sh[rloc], frm = fri[m];
                if (cb < N) {
                    float v = acc1[mi][ni][half * 2] + rsm * acc3[mi][ni][half * 2]
                            + G[(long)m * H + cb] + frm * v2[cb] + b_r[cb];
                    s0 += lrelu_f(v);
                }
                if (cb + 1 < N) {
                    float v = acc1[mi][ni][half * 2 + 1] + rsm * acc3[mi][ni][half * 2 + 1]
                            + G[(long)m * H + cb + 1] + frm * v2[cb + 1] + b_r[cb + 1];
                    s1 += lrelu_f(v);
                }
            }
        }
        #pragma unroll
        for (int o = 4; o < 32; o <<= 1) {
            s0 += __shfl_xor_sync(0xffffffffu, s0, o);
            s1 += __shfl_xor_sync(0xffffffffu, s1, o);
        }
        if (lane < 4) {
            atomicAdd(&red[dl][wn * 32 + ni * 8 + 2 * lc],     s0);
            atomicAdd(&red[dl][wn * 32 + ni * 8 + 2 * lc + 1], s1);
        }
    }
    __syncthreads();
    if (tid < 128) {
        int dloc = tid >> 6, c = tid & 63;
        int col = n0 + c;
        if (col < N)
            fin[(long)(blockIdx.y * 2 + dloc) * H + col] = red[dloc][c] * (1.f / 64.f);
    }
}

// out[d,c]: one warp per output
__global__ void cls_kernel(const float* __restrict__ fin,
                           const float* __restrict__ Wc,
                           const float* __restrict__ bc,
                           float* __restrict__ out)
{
    int gw = blockIdx.x * (blockDim.x >> 5) + (threadIdx.x >> 5);
    int lane = threadIdx.x & 31;
    if (gw >= 128) return;
    int d = gw >> 1, c = gw & 1;
    const float* f = fin + d * H;
    const float* w = Wc + c * H;
    float p = 0.f;
    for (int h = lane; h < H; h += 32) p += f[h] * w[h];
    #pragma unroll
    for (int o = 16; o; o >>= 1) p += __shfl_xor_sync(0xffffffffu, p, o);
    if (lane == 0) out[d * 2 + c] = p + bc[c];
}

// =====================================================================
extern "C" void kernel_launch(void* const* d_in, const int* in_sizes, int n_in,
                              void* d_out, int out_size)
{
    const int*   word_indices = (const int*)  d_in[0];
    const float* E            = (const float*)d_in[1];
    const float* W_sent       = (const float*)d_in[2];
    const float* b_sent       = (const float*)d_in[3];
    const float* W_par        = (const float*)d_in[4];
    const float* b_par        = (const float*)d_in[5];
    const float* W_ch         = (const float*)d_in[6];
    const float* b_ch         = (const float*)d_in[7];
    const float* w_root       = (const float*)d_in[8];
    const float* b_root       = (const float*)d_in[9];
    const float* root_embed   = (const float*)d_in[10];
    const float* W_r          = (const float*)d_in[11];
    const float* b_r          = (const float*)d_in[12];
    const float* W_cls        = (const float*)d_in[13];
    const float* b_cls        = (const float*)d_in[14];

    float* out_ptr = (float*)d_out;
    float* A_ptr   = out_ptr + D * 2;
    float* fri_ptr = A_ptr + D * S * S;

    float *enc, *Pm, *Cm, *Y2, *G, *fin, *v2;
    cudaGetSymbolAddress((void**)&enc, g_enc);
    cudaGetSymbolAddress((void**)&Pm,  g_P);
    cudaGetSymbolAddress((void**)&Cm,  g_C);
    cudaGetSymbolAddress((void**)&Y2,  g_Y2);
    cudaGetSymbolAddress((void**)&G,   g_G);
    cudaGetSymbolAddress((void**)&fin, g_fin);
    cudaGetSymbolAddress((void**)&v2,  g_v2);

    cudaFuncSetAttribute(scores_kernel,
                         cudaFuncAttributeMaxDynamicSharedMemorySize, SCORES_SMEM);

    dim3 gEnc((H + BN - 1) / BN, NROWS / BM, 1);
    gemm_tf32_kernel<true><<<gEnc, 256>>>(
        E, word_indices + (L - 1), L,
        W_sent, b_sent, enc,
        nullptr, nullptr, nullptr,
        nullptr, nullptr, nullptr, H, W, W, W, W);

    // P, C (lrelu+bias) and Y2 = enc @ W2^T (linear; W2 rows inside W_r, ld=900)
    dim3 gPCY((H + BN - 1) / BN, NROWS / BM, 3);
    gemm_tf32_kernel<false><<<gPCY, 256>>>(
        enc, nullptr, 0,
        W_par,       b_par,   Pm,
        W_ch,        b_ch,    Cm,
        W_r + 300,   nullptr, Y2,
        H, H, H, H, 900);

    // scores + mask + softmax -> A (d_out), then G in-block; fri/v2 extras
    scores_kernel<<<dim3(4, D), 256, SCORES_SMEM>>>(
        Pm, Cm, Y2, enc, w_root, b_root, W_r, root_embed,
        A_ptr, G, fri_ptr, v2);

    // ri + mean (rs computed in-block from A)
    ri_mean_kernel<<<dim3(5, 32), 256>>>(enc, W_r, b_r, G, A_ptr, fri_ptr, v2, fin);

    cls_kernel<<<8, 512>>>(fin, W_cls, b_cls, out_ptr);
}

// round 12
// speedup vs baseline: 1.0944x; 1.0911x over previous
#include <cuda_runtime.h>

#define D 64
#define S 64
#define L 64
#define W 300
#define H 300
#define NROWS (D*S)          // 4096
#define NEGV (-9999999.0f)

// ---------------- device scratch (no allocation allowed) ----------------
__device__ float g_enc[NROWS * H];
__device__ float g_P  [NROWS * H];
__device__ float g_C  [NROWS * H];
__device__ float g_Y2 [NROWS * H];
__device__ float g_G  [NROWS * H];
__device__ float g_rs [NROWS];
__device__ float g_fin[D * H];
__device__ float g_v2 [H];

__device__ __forceinline__ float lrelu_f(float x) { return x > 0.f ? x : 0.01f * x; }

__device__ __forceinline__ unsigned f2tf32(float f) {
    unsigned u;
    asm("cvt.rna.tf32.f32 %0, %1;" : "=r"(u) : "f"(f));
    return u;
}
// round raw fp32 bits (stored in smem as unsigned) to tf32
__device__ __forceinline__ unsigned r2tf32(unsigned raw) {
    return f2tf32(__uint_as_float(raw));
}
__device__ __forceinline__ uint4 cvt4(float4 v) {
    return make_uint4(f2tf32(v.x), f2tf32(v.y), f2tf32(v.z), f2tf32(v.w));
}

__device__ __forceinline__ void mma8(float* c, const unsigned* a, const unsigned* b) {
    asm volatile(
        "mma.sync.aligned.m16n8k8.row.col.f32.tf32.tf32.f32 "
        "{%0,%1,%2,%3}, {%4,%5,%6,%7}, {%8,%9}, {%0,%1,%2,%3};"
        : "+f"(c[0]), "+f"(c[1]), "+f"(c[2]), "+f"(c[3])
        : "r"(a[0]), "r"(a[1]), "r"(a[2]), "r"(a[3]), "r"(b[0]), "r"(b[1]));
}

// cp.async 16B with zero-fill when srcsize==0
__device__ __forceinline__ void cp_async16(unsigned smem_addr, const void* gptr, int srcsize) {
    asm volatile("cp.async.ca.shared.global [%0], [%1], 16, %2;"
                 :: "r"(smem_addr), "l"(gptr), "r"(srcsize));
}
__device__ __forceinline__ void cp_commit() {
    asm volatile("cp.async.commit_group;");
}
template<int N>
__device__ __forceinline__ void cp_wait() {
    asm volatile("cp.async.wait_group %0;" :: "n"(N));
}

#define BM 128
#define BN 64
#define BK 16
#define BKP 20

// =====================================================================
// TF32 GEMM, cp.async depth-2 pipeline, round-to-nearest tf32 applied
// at fragment read (bit-identical math to the R8 baseline).
// Out[M,N] = act( A[M,K] @ B[N,K(ld=ldb)]^T + bias[N] )
// z selects among 3 (B,bias,Out) triples; bias==nullptr => linear.
// =====================================================================
template<bool GATHER>
__global__ void gemm_tf32_kernel(
    const float* __restrict__ Abase, const int* __restrict__ idx, int idxStride,
    const float* __restrict__ B0, const float* __restrict__ bias0, float* __restrict__ Out0,
    const float* __restrict__ B1, const float* __restrict__ bias1, float* __restrict__ Out1,
    const float* __restrict__ B2, const float* __restrict__ bias2, float* __restrict__ Out2,
    int N, int K, int ldb0, int ldb1, int ldb2)
{
    const float* Bw   = B0;
    const float* bias = bias0;
    float*       Out  = Out0;
    int          ldb  = ldb0;
    if (blockIdx.z == 1) { Bw = B1; bias = bias1; Out = Out1; ldb = ldb1; }
    if (blockIdx.z == 2) { Bw = B2; bias = bias2; Out = Out2; ldb = ldb2; }
    const bool act = (bias != nullptr);

    __shared__ __align__(16) unsigned As[2][BM][BKP];
    __shared__ __align__(16) unsigned Bs[2][BN][BKP];

    const int tid  = threadIdx.x;
    const int lane = tid & 31;
    const int wid  = tid >> 5;
    const int wm   = wid >> 1;
    const int wn   = wid & 1;
    const int m0   = blockIdx.y * BM;
    const int n0   = blockIdx.x * BN;

    const int am0 = tid >> 2;
    const int ac  = (tid & 3) * 4;
    long aoff0, aoff1;
    if (GATHER) {
        aoff0 = (long)idx[(long)(m0 + am0) * idxStride] * K;
        aoff1 = (long)idx[(long)(m0 + am0 + 64) * idxStride] * K;
    } else {
        aoff0 = (long)(m0 + am0) * K;
        aoff1 = (long)(m0 + am0 + 64) * K;
    }
    const int  bn     = tid >> 2;
    const bool bvalid = (n0 + bn) < N;
    const long boff   = bvalid ? (long)(n0 + bn) * ldb : 0;

    unsigned sa0[2], sa1[2], sb[2];
    sa0[0] = (unsigned)__cvta_generic_to_shared(&As[0][am0][ac]);
    sa0[1] = (unsigned)__cvta_generic_to_shared(&As[1][am0][ac]);
    sa1[0] = (unsigned)__cvta_generic_to_shared(&As[0][am0 + 64][ac]);
    sa1[1] = (unsigned)__cvta_generic_to_shared(&As[1][am0 + 64][ac]);
    sb[0]  = (unsigned)__cvta_generic_to_shared(&Bs[0][bn][ac]);
    sb[1]  = (unsigned)__cvta_generic_to_shared(&Bs[1][bn][ac]);

    const int nIter = (K + BK - 1) / BK;

    {
        int k = ac;
        int szA = (k + 4 <= K) ? 16 : 0;
        int szB = (bvalid && k + 4 <= K) ? 16 : 0;
        cp_async16(sa0[0], Abase + aoff0 + k, szA);
        cp_async16(sa1[0], Abase + aoff1 + k, szA);
        cp_async16(sb[0],  Bw + boff + k,     szB);
    }
    cp_commit();

    float acc[2][4][4];
    #pragma unroll
    for (int i = 0; i < 2; i++)
        #pragma unroll
        for (int j = 0; j < 4; j++)
            #pragma unroll
            for (int q = 0; q < 4; q++) acc[i][j][q] = 0.f;

    const int lr = lane >> 2;
    const int lc = lane & 3;

    for (int it = 0; it < nIter; it++) {
        const int cur = it & 1;
        if (it + 1 < nIter) {
            int k = (it + 1) * BK + ac;
            int szA = (k + 4 <= K) ? 16 : 0;
            int szB = (bvalid && k + 4 <= K) ? 16 : 0;
            const float* pa0 = Abase + aoff0 + (szA ? k : 0);
            const float* pa1 = Abase + aoff1 + (szA ? k : 0);
            const float* pb  = Bw + boff + (szB ? k : 0);
            cp_async16(sa0[cur ^ 1], pa0, szA);
            cp_async16(sa1[cur ^ 1], pa1, szA);
            cp_async16(sb[cur ^ 1],  pb,  szB);
            cp_commit();
            cp_wait<1>();
        } else {
            cp_wait<0>();
        }
        __syncthreads();

        #pragma unroll
        for (int ks = 0; ks < 2; ks++) {
            const int kb = ks * 8;
            unsigned a[2][4], b[4][2];
            #pragma unroll
            for (int mi = 0; mi < 2; mi++) {
                int r = wm * 32 + mi * 16 + lr;
                a[mi][0] = r2tf32(As[cur][r][kb + lc]);
                a[mi][1] = r2tf32(As[cur][r + 8][kb + lc]);
                a[mi][2] = r2tf32(As[cur][r][kb + lc + 4]);
                a[mi][3] = r2tf32(As[cur][r + 8][kb + lc + 4]);
            }
            #pragma unroll
            for (int ni = 0; ni < 4; ni++) {
                int c = wn * 32 + ni * 8 + lr;
                b[ni][0] = r2tf32(Bs[cur][c][kb + lc]);
                b[ni][1] = r2tf32(Bs[cur][c][kb + lc + 4]);
            }
            #pragma unroll
            for (int mi = 0; mi < 2; mi++)
                #pragma unroll
                for (int ni = 0; ni < 4; ni++)
                    mma8(acc[mi][ni], a[mi], b[ni]);
        }
        __syncthreads();
    }

    #pragma unroll
    for (int mi = 0; mi < 2; mi++) {
        int r = m0 + wm * 32 + mi * 16 + lr;
        #pragma unroll
        for (int ni = 0; ni < 4; ni++) {
            int cb = n0 + wn * 32 + ni * 8 + 2 * lc;
            #pragma unroll
            for (int q = 0; q < 2; q++) {
                int cc = cb + q;
                if (cc >= N) continue;
                float bv = act ? bias[cc] : 0.f;
                float v0 = acc[mi][ni][q]     + bv;
                float v1 = acc[mi][ni][q + 2] + bv;
                if (act) { v0 = lrelu_f(v0); v1 = lrelu_f(v1); }
                Out[(long)r * N + cc]       = v0;
                Out[(long)(r + 8) * N + cc] = v1;
            }
        }
    }
}

// =====================================================================
// Scores + diag mask + column softmax, grid (4, D), 256 thr (R8-proven).
// =====================================================================
#define SPAD 308
#define SCORES_SMEM ((80 * SPAD + 64 * 17) * 4)   // 102,912 B

__global__ void scores_kernel(const float* __restrict__ P,
                              const float* __restrict__ Cm,
                              float* __restrict__ A_out)
{
    extern __shared__ unsigned sdyn[];
    unsigned* Pt = sdyn;                       // [64][SPAD]
    unsigned* Ct = sdyn + 64 * SPAD;           // [16][SPAD]
    float*    Sh = (float*)(sdyn + 80 * SPAD); // [64][17]

    const int d  = blockIdx.y;
    const int j0 = blockIdx.x * 16;
    const int t = threadIdx.x;
    const int lane = t & 31;
    const int wid  = t >> 5;
    const int wm = wid >> 1;
    const int wn = wid & 1;
    const int lr = lane >> 2, lc = lane & 3;

    const float4* Pd4 = (const float4*)(P  + (long)d * S * H);
    const float4* Cd4 = (const float4*)(Cm + (long)d * S * H);

    for (int u = t; u < 64 * 76; u += 256) {
        int r = u / 76, c4 = u - r * 76;
        float4 v = make_float4(0.f, 0.f, 0.f, 0.f);
        if (c4 < 75) v = Pd4[r * 75 + c4];
        *(uint4*)&Pt[r * SPAD + c4 * 4] = cvt4(v);
    }
    for (int u = t; u < 16 * 76; u += 256) {
        int r = u / 76, c4 = u - r * 76;
        float4 v = make_float4(0.f, 0.f, 0.f, 0.f);
        if (c4 < 75) v = Cd4[(j0 + r) * 75 + c4];
        *(uint4*)&Ct[r * SPAD + c4 * 4] = cvt4(v);
    }
    __syncthreads();

    float acc[4] = {};
    {
        const int r = wm * 16 + lr;
        const int c = wn * 8 + lr;
        #pragma unroll
        for (int ks = 0; ks < 38; ks++) {
            const int kb = ks * 8;
            unsigned a[4], b[2];
            a[0] = Pt[r * SPAD + kb + lc];
            a[1] = Pt[(r + 8) * SPAD + kb + lc];
            a[2] = Pt[r * SPAD + kb + lc + 4];
            a[3] = Pt[(r + 8) * SPAD + kb + lc + 4];
            b[0] = Ct[c * SPAD + kb + lc];
            b[1] = Ct[c * SPAD + kb + lc + 4];
            mma8(acc, a, b);
        }
    }

    {
        int r = wm * 16 + lr;
        int cb = wn * 8 + 2 * lc;
        int gc = j0 + cb;
        Sh[r * 17 + cb]           = (r == gc)         ? NEGV : acc[0];
        Sh[r * 17 + cb + 1]       = (r == gc + 1)     ? NEGV : acc[1];
        Sh[(r + 8) * 17 + cb]     = (r + 8 == gc)     ? NEGV : acc[2];
        Sh[(r + 8) * 17 + cb + 1] = (r + 8 == gc + 1) ? NEGV : acc[3];
    }
    __syncthreads();

    #pragma unroll
    for (int cc = 0; cc < 2; cc++) {
        int c = wid * 2 + cc;
        float v0 = Sh[lane * 17 + c];
        float v1 = Sh[(lane + 32) * 17 + c];
        float m = fmaxf(v0, v1);
        #pragma unroll
        for (int o = 16; o; o >>= 1) m = fmaxf(m, __shfl_xor_sync(0xffffffffu, m, o));
        float e0 = __expf(v0 - m), e1 = __expf(v1 - m);
        float s = e0 + e1;
        #pragma unroll
        for (int o = 16; o; o >>= 1) s += __shfl_xor_sync(0xffffffffu, s, o);
        float inv = 1.f / s;
        Sh[lane * 17 + c]        = e0 * inv;
        Sh[(lane + 32) * 17 + c] = e1 * inv;
    }
    __syncthreads();

    for (int u = t; u < 64 * 16; u += 256) {
        int i = u >> 4, j = u & 15;
        A_out[(long)d * 4096 + i * 64 + j0 + j] = Sh[i * 17 + j];
    }
}

// =====================================================================
// G[d,i,h] = sum_k A[d,k,i] * Y2[d*64+k, h]  (tf32 mma), grid (5, D).
// Extras: x==0 -> rs[d,:], x==1 -> fri[d,:], x==2 -> v2 slice (5 cols/d).
// (R8-proven.)
// =====================================================================
__global__ void g_kernel(const float* __restrict__ A_in,
                         const float* __restrict__ Y2,
                         const float* __restrict__ enc,
                         const float* __restrict__ w_root,
                         const float* __restrict__ b_root,
                         const float* __restrict__ W_r,
                         const float* __restrict__ root_embed,
                         float* __restrict__ G,
                         float* __restrict__ rs_out,
                         float* __restrict__ fri_out,
                         float* __restrict__ v2_out)
{
    const int d  = blockIdx.y;
    const int h0 = blockIdx.x * 64;
    const int t = threadIdx.x;
    const int lane = t & 31;
    const int wid  = t >> 5;
    const int wm = wid >> 1, wn = wid & 1;
    const int lr = lane >> 2, lc = lane & 3;

    __shared__ __align__(16) unsigned Ak[64][65];
    __shared__ __align__(16) unsigned Ys[64][65];
    __shared__ float sred[64];

    const float* Ad = A_in + (long)d * 4096;
    const float* Yd = Y2 + (long)d * 64 * H;
    const float* Ed = enc + (long)d * S * H;

    for (int u = t; u < 1024; u += 256) {
        float4 v = ((const float4*)Ad)[u];
        int k = u >> 4, i = (u & 15) * 4;
        Ak[k][i]     = f2tf32(v.x);
        Ak[k][i + 1] = f2tf32(v.y);
        Ak[k][i + 2] = f2tf32(v.z);
        Ak[k][i + 3] = f2tf32(v.w);
    }
    for (int u = t; u < 1024; u += 256) {
        int k = u >> 4, i = (u & 15) * 4;
        int h = h0 + i;
        float4 v = make_float4(0.f, 0.f, 0.f, 0.f);
        if (h < H) v = *(const float4*)(Yd + k * H + h);
        Ys[k][i]     = f2tf32(v.x);
        Ys[k][i + 1] = f2tf32(v.y);
        Ys[k][i + 2] = f2tf32(v.z);
        Ys[k][i + 3] = f2tf32(v.w);
    }
    __syncthreads();

    float acc[4][4] = {};
    #pragma unroll
    for (int ks = 0; ks < 8; ks++) {
        const int kb = ks * 8;
        unsigned a[4], b[4][2];
        int r = wm * 16 + lr;
        a[0] = Ak[kb + lc][r];
        a[1] = Ak[kb + lc][r + 8];
        a[2] = Ak[kb + lc + 4][r];
        a[3] = Ak[kb + lc + 4][r + 8];
        #pragma unroll
        for (int ni = 0; ni < 4; ni++) {
            int c = wn * 32 + ni * 8 + lr;
            b[ni][0] = Ys[kb + lc][c];
            b[ni][1] = Ys[kb + lc + 4][c];
        }
        #pragma unroll
        for (int ni = 0; ni < 4; ni++)
            mma8(acc[ni], a, b[ni]);
    }

    {
        int r = wm * 16 + lr;
        #pragma unroll
        for (int ni = 0; ni < 4; ni++) {
            int cb = wn * 32 + ni * 8 + 2 * lc;
            #pragma unroll
            for (int q = 0; q < 2; q++) {
                int h = h0 + cb + q;
                if (h >= H) continue;
                G[(long)(d * 64 + r) * H + h]     = acc[ni][q];
                G[(long)(d * 64 + r + 8) * H + h] = acc[ni][q + 2];
            }
        }
    }

    if (blockIdx.x == 0) {
        #pragma unroll
        for (int rr = 0; rr < 8; rr++) {
            int r = wid * 8 + rr;
            float s = Ad[r * 64 + lane] + Ad[r * 64 + lane + 32];
            #pragma unroll
            for (int o = 16; o; o >>= 1) s += __shfl_xor_sync(0xffffffffu, s, o);
            if (lane == 0) rs_out[d * 64 + r] = s;
        }
    } else if (blockIdx.x == 1) {
        const float br0 = b_root[0];
        #pragma unroll
        for (int ss = 0; ss < 8; ss++) {
            int s = wid * 8 + ss;
            const float* e = Ed + s * H;
            float p = 0.f;
            for (int h = lane; h < H; h += 32) p += e[h] * w_root[h];
            #pragma unroll
            for (int o = 16; o; o >>= 1) p += __shfl_xor_sync(0xffffffffu, p, o);
            if (lane == 0) sred[s] = p + br0;
        }
        __syncthreads();
        float mye = 0.f;
        if (t < 64) {
            float m = -1e30f;
            for (int u = 0; u < 64; u++) m = fmaxf(m, sred[u]);
            mye = __expf(sred[t] - m);
        }
        __syncthreads();
        if (t < 64) sred[t] = mye;
        __syncthreads();
        if (t < 64) {
            float ssum = 0.f;
            for (int u = 0; u < 64; u++) ssum += sred[u];
            fri_out[d * 64 + t] = mye / ssum;
        }
    } else if (blockIdx.x == 2) {
        if (wid < 5) {
            int n = d * 5 + wid;
            if (n < H) {
                const float* w = W_r + (long)n * 900 + 300;
                float p = 0.f;
                for (int k = lane; k < H; k += 32) p += w[k] * root_embed[k];
                #pragma unroll
                for (int o = 16; o; o >>= 1) p += __shfl_xor_sync(0xffffffffu, p, o);
                if (lane == 0) v2_out[n] = p;
            }
        }
    }
}

// =====================================================================
// ri+mean (R8-proven): fin[doc,n] = mean_s lrelu( enc@W1^T +
//        rs*(enc@W3^T) + G + fri*v2 + b_r )
// =====================================================================
__global__ void ri_mean_kernel(const float* __restrict__ enc,
                               const float* __restrict__ W_r,   // [H, 900]
                               const float* __restrict__ b_r,
                               const float* __restrict__ G,
                               const float* __restrict__ rs,
                               const float* __restrict__ fri,
                               const float* __restrict__ v2,
                               float* __restrict__ fin)
{
    __shared__ __align__(16) unsigned As[BM][BKP];
    __shared__ __align__(16) unsigned B1s[BN][BKP];
    __shared__ __align__(16) unsigned B3s[BN][BKP];
    __shared__ float red[2][BN];

    const int K = H;
    const int N = H;
    const int tid  = threadIdx.x;
    const int lane = tid & 31;
    const int wid  = tid >> 5;
    const int wm = wid >> 1, wn = wid & 1;
    const int m0 = blockIdx.y * BM;
    const int n0 = blockIdx.x * BN;

    if (tid < 2 * BN) ((float*)red)[tid] = 0.f;

    const int am0 = tid >> 2;
    const int ac  = (tid & 3) * 4;
    const long aoff0 = (long)(m0 + am0) * K;
    const long aoff1 = (long)(m0 + am0 + 64) * K;
    const int  bn     = tid >> 2;
    const bool bvalid = (n0 + bn) < N;
    const long boff   = (long)(n0 + bn) * 900;

    float acc1[2][4][4], acc3[2][4][4];
    #pragma unroll
    for (int i = 0; i < 2; i++)
        #pragma unroll
        for (int j = 0; j < 4; j++)
            #pragma unroll
            for (int q = 0; q < 4; q++) { acc1[i][j][q] = 0.f; acc3[i][j][q] = 0.f; }

    const int lr = lane >> 2, lc = lane & 3;

    for (int k0 = 0; k0 < K; k0 += BK) {
        if (k0 + BK <= K) {
            float4 a0 = *(const float4*)(enc + aoff0 + k0 + ac);
            float4 a1 = *(const float4*)(enc + aoff1 + k0 + ac);
            float4 b1 = bvalid ? *(const float4*)(W_r + boff + k0 + ac) : make_float4(0,0,0,0);
            float4 b3 = bvalid ? *(const float4*)(W_r + boff + 600 + k0 + ac) : make_float4(0,0,0,0);
            *(uint4*)&As[am0][ac]      = cvt4(a0);
            *(uint4*)&As[am0 + 64][ac] = cvt4(a1);
            *(uint4*)&B1s[bn][ac]      = cvt4(b1);
            *(uint4*)&B3s[bn][ac]      = cvt4(b3);
        } else {
            #pragma unroll
            for (int u = 0; u < 4; u++) {
                int k = k0 + ac + u;
                bool kk = k < K;
                As[am0][ac + u]      = kk ? f2tf32(enc[aoff0 + k]) : 0u;
                As[am0 + 64][ac + u] = kk ? f2tf32(enc[aoff1 + k]) : 0u;
                B1s[bn][ac + u]      = (bvalid && kk) ? f2tf32(W_r[boff + k]) : 0u;
                B3s[bn][ac + u]      = (bvalid && kk) ? f2tf32(W_r[boff + 600 + k]) : 0u;
            }
        }
        __syncthreads();
        #pragma unroll
        for (int ks = 0; ks < 2; ks++) {
            const int kb = ks * 8;
            unsigned a[2][4], b1[4][2], b3[4][2];
            #pragma unroll
            for (int mi = 0; mi < 2; mi++) {
                int r = wm * 32 + mi * 16 + lr;
                a[mi][0] = As[r][kb + lc];
                a[mi][1] = As[r + 8][kb + lc];
                a[mi][2] = As[r][kb + lc + 4];
                a[mi][3] = As[r + 8][kb + lc + 4];
            }
            #pragma unroll
            for (int ni = 0; ni < 4; ni++) {
                int c = wn * 32 + ni * 8 + lr;
                b1[ni][0] = B1s[c][kb + lc];
                b1[ni][1] = B1s[c][kb + lc + 4];
                b3[ni][0] = B3s[c][kb + lc];
                b3[ni][1] = B3s[c][kb + lc + 4];
            }
            #pragma unroll
            for (int mi = 0; mi < 2; mi++)
                #pragma unroll
                for (int ni = 0; ni < 4; ni++) {
                    mma8(acc1[mi][ni], a[mi], b1[ni]);
                    mma8(acc3[mi][ni], a[mi], b3[ni]);
                }
        }
        __syncthreads();
    }

    const int dl = wm >> 1;
    #pragma unroll
    for (int ni = 0; ni < 4; ni++) {
        int cb = n0 + wn * 32 + ni * 8 + 2 * lc;
        float s0 = 0.f, s1 = 0.f;
        #pragma unroll
        for (int mi = 0; mi < 2; mi++) {
            int r = m0 + wm * 32 + mi * 16 + lr;
            #pragma unroll
            for (int half = 0; half < 2; half++) {
                int m = r + half * 8;
                float rsm = rs[m], frm = fri[m];
                if (cb < N) {
                    float v = acc1[mi][ni][half * 2] + rsm * acc3[mi][ni][half * 2]
                            + G[(long)m * H + cb] + frm * v2[cb] + b_r[cb];
                    s0 += lrelu_f(v);
                }
                if (cb + 1 < N) {
                    float v = acc1[mi][ni][half * 2 + 1] + rsm * acc3[mi][ni][half * 2 + 1]
                            + G[(long)m * H + cb + 1] + frm * v2[cb + 1] + b_r[cb + 1];
                    s1 += lrelu_f(v);
                }
            }
        }
        #pragma unroll
        for (int o = 4; o < 32; o <<= 1) {
            s0 += __shfl_xor_sync(0xffffffffu, s0, o);
            s1 += __shfl_xor_sync(0xffffffffu, s1, o);
        }
        if (lane < 4) {
            atomicAdd(&red[dl][wn * 32 + ni * 8 + 2 * lc],     s0);
            atomicAdd(&red[dl][wn * 32 + ni * 8 + 2 * lc + 1], s1);
        }
    }
    __syncthreads();
    if (tid < 128) {
        int dloc = tid >> 6, c = tid & 63;
        int col = n0 + c;
        if (col < N)
            fin[(long)(blockIdx.y * 2 + dloc) * H + col] = red[dloc][c] * (1.f / 64.f);
    }
}

// out[d,c]: one warp per output
__global__ void cls_kernel(const float* __restrict__ fin,
                           const float* __restrict__ Wc,
                           const float* __restrict__ bc,
                           float* __restrict__ out)
{
    int gw = blockIdx.x * (blockDim.x >> 5) + (threadIdx.x >> 5);
    int lane = threadIdx.x & 31;
    if (gw >= 128) return;
    int d = gw >> 1, c = gw & 1;
    const float* f = fin + d * H;
    const float* w = Wc + c * H;
    float p = 0.f;
    for (int h = lane; h < H; h += 32) p += f[h] * w[h];
    #pragma unroll
    for (int o = 16; o; o >>= 1) p += __shfl_xor_sync(0xffffffffu, p, o);
    if (lane == 0) out[d * 2 + c] = p + bc[c];
}

// =====================================================================
extern "C" void kernel_launch(void* const* d_in, const int* in_sizes, int n_in,
                              void* d_out, int out_size)
{
    const int*   word_indices = (const int*)  d_in[0];
    const float* E            = (const float*)d_in[1];
    const float* W_sent       = (const float*)d_in[2];
    const float* b_sent       = (const float*)d_in[3];
    const float* W_par        = (const float*)d_in[4];
    const float* b_par        = (const float*)d_in[5];
    const float* W_ch         = (const float*)d_in[6];
    const float* b_ch         = (const float*)d_in[7];
    const float* w_root       = (const float*)d_in[8];
    const float* b_root       = (const float*)d_in[9];
    const float* root_embed   = (const float*)d_in[10];
    const float* W_r          = (const float*)d_in[11];
    const float* b_r          = (const float*)d_in[12];
    const float* W_cls        = (const float*)d_in[13];
    const float* b_cls        = (const float*)d_in[14];

    float* out_ptr = (float*)d_out;
    float* A_ptr   = out_ptr + D * 2;
    float* fri_ptr = A_ptr + D * S * S;

    float *enc, *Pm, *Cm, *Y2, *G, *rs, *fin, *v2;
    cudaGetSymbolAddress((void**)&enc, g_enc);
    cudaGetSymbolAddress((void**)&Pm,  g_P);
    cudaGetSymbolAddress((void**)&Cm,  g_C);
    cudaGetSymbolAddress((void**)&Y2,  g_Y2);
    cudaGetSymbolAddress((void**)&G,   g_G);
    cudaGetSymbolAddress((void**)&rs,  g_rs);
    cudaGetSymbolAddress((void**)&fin, g_fin);
    cudaGetSymbolAddress((void**)&v2,  g_v2);

    cudaFuncSetAttribute(scores_kernel,
                         cudaFuncAttributeMaxDynamicSharedMemorySize, SCORES_SMEM);

    dim3 gEnc((H + BN - 1) / BN, NROWS / BM, 1);
    gemm_tf32_kernel<true><<<gEnc, 256>>>(
        E, word_indices + (L - 1), L,
        W_sent, b_sent, enc,
        nullptr, nullptr, nullptr,
        nullptr, nullptr, nullptr, H, W, W, W, W);

    // P, C (lrelu+bias) and Y2 = enc @ W2^T (linear; W2 rows inside W_r, ld=900)
    dim3 gPCY((H + BN - 1) / BN, NROWS / BM, 3);
    gemm_tf32_kernel<false><<<gPCY, 256>>>(
        enc, nullptr, 0,
        W_par,       b_par,   Pm,
        W_ch,        b_ch,    Cm,
        W_r + 300,   nullptr, Y2,
        H, H, H, H, 900);

    // scores + mask + column softmax -> A (in d_out)
    scores_kernel<<<dim3(4, D), 256, SCORES_SMEM>>>(Pm, Cm, A_ptr);

    // G = A^T @ Y2 per doc; also rs (x==0), fri (x==1), v2 slice (x==2)
    g_kernel<<<dim3(5, D), 256>>>(A_ptr, Y2, enc, w_root, b_root,
                                  W_r, root_embed, G, rs, fri_ptr, v2);

    ri_mean_kernel<<<dim3(5, 32), 256>>>(enc, W_r, b_r, G, rs, fri_ptr, v2, fin);

    cls_kernel<<<8, 512>>>(fin, W_cls, b_cls, out_ptr);
}

// round 13
// speedup vs baseline: 1.1102x; 1.0145x over previous
#include <cuda_runtime.h>

#define D 64
#define S 64
#define L 64
#define W 300
#define H 300
#define NROWS (D*S)          // 4096
#define NEGV (-9999999.0f)

// ---------------- device scratch (no allocation allowed) ----------------
__device__ float g_enc[NROWS * H];
__device__ float g_P  [NROWS * H];
__device__ float g_C  [NROWS * H];
__device__ float g_Y2 [NROWS * H];
__device__ float g_G  [NROWS * H];
__device__ float g_rs [NROWS];
__device__ float g_fin[D * H];
__device__ float g_v2 [H];

__device__ __forceinline__ float lrelu_f(float x) { return x > 0.f ? x : 0.01f * x; }

__device__ __forceinline__ unsigned f2tf32(float f) {
    unsigned u;
    asm("cvt.rna.tf32.f32 %0, %1;" : "=r"(u) : "f"(f));
    return u;
}
// round raw fp32 bits (stored in smem as unsigned) to tf32
__device__ __forceinline__ unsigned r2tf32(unsigned raw) {
    return f2tf32(__uint_as_float(raw));
}
__device__ __forceinline__ uint4 cvt4(float4 v) {
    return make_uint4(f2tf32(v.x), f2tf32(v.y), f2tf32(v.z), f2tf32(v.w));
}

__device__ __forceinline__ void mma8(float* c, const unsigned* a, const unsigned* b) {
    asm volatile(
        "mma.sync.aligned.m16n8k8.row.col.f32.tf32.tf32.f32 "
        "{%0,%1,%2,%3}, {%4,%5,%6,%7}, {%8,%9}, {%0,%1,%2,%3};"
        : "+f"(c[0]), "+f"(c[1]), "+f"(c[2]), "+f"(c[3])
        : "r"(a[0]), "r"(a[1]), "r"(a[2]), "r"(a[3]), "r"(b[0]), "r"(b[1]));
}

// cp.async 16B with zero-fill when srcsize==0
__device__ __forceinline__ void cp_async16(unsigned smem_addr, const void* gptr, int srcsize) {
    asm volatile("cp.async.ca.shared.global [%0], [%1], 16, %2;"
                 :: "r"(smem_addr), "l"(gptr), "r"(srcsize));
}
__device__ __forceinline__ void cp_commit() {
    asm volatile("cp.async.commit_group;");
}
template<int N>
__device__ __forceinline__ void cp_wait() {
    asm volatile("cp.async.wait_group %0;" :: "n"(N));
}

#define BM 128
#define BN 64
#define BK 16
#define BKP 20

// =====================================================================
// TF32 GEMM, cp.async depth-2 pipeline, rna tf32 at fragment read
// (R12-proven). Out[M,N] = act( A[M,K] @ B[N,K(ld=ldb)]^T + bias[N] ).
// z selects among 3 (B,bias,Out) triples; bias==nullptr => linear.
// =====================================================================
template<bool GATHER>
__global__ void gemm_tf32_kernel(
    const float* __restrict__ Abase, const int* __restrict__ idx, int idxStride,
    const float* __restrict__ B0, const float* __restrict__ bias0, float* __restrict__ Out0,
    const float* __restrict__ B1, const float* __restrict__ bias1, float* __restrict__ Out1,
    const float* __restrict__ B2, const float* __restrict__ bias2, float* __restrict__ Out2,
    int N, int K, int ldb0, int ldb1, int ldb2)
{
    const float* Bw   = B0;
    const float* bias = bias0;
    float*       Out  = Out0;
    int          ldb  = ldb0;
    if (blockIdx.z == 1) { Bw = B1; bias = bias1; Out = Out1; ldb = ldb1; }
    if (blockIdx.z == 2) { Bw = B2; bias = bias2; Out = Out2; ldb = ldb2; }
    const bool act = (bias != nullptr);

    __shared__ __align__(16) unsigned As[2][BM][BKP];
    __shared__ __align__(16) unsigned Bs[2][BN][BKP];

    const int tid  = threadIdx.x;
    const int lane = tid & 31;
    const int wid  = tid >> 5;
    const int wm   = wid >> 1;
    const int wn   = wid & 1;
    const int m0   = blockIdx.y * BM;
    const int n0   = blockIdx.x * BN;

    const int am0 = tid >> 2;
    const int ac  = (tid & 3) * 4;
    long aoff0, aoff1;
    if (GATHER) {
        aoff0 = (long)idx[(long)(m0 + am0) * idxStride] * K;
        aoff1 = (long)idx[(long)(m0 + am0 + 64) * idxStride] * K;
    } else {
        aoff0 = (long)(m0 + am0) * K;
        aoff1 = (long)(m0 + am0 + 64) * K;
    }
    const int  bn     = tid >> 2;
    const bool bvalid = (n0 + bn) < N;
    const long boff   = bvalid ? (long)(n0 + bn) * ldb : 0;

    unsigned sa0[2], sa1[2], sb[2];
    sa0[0] = (unsigned)__cvta_generic_to_shared(&As[0][am0][ac]);
    sa0[1] = (unsigned)__cvta_generic_to_shared(&As[1][am0][ac]);
    sa1[0] = (unsigned)__cvta_generic_to_shared(&As[0][am0 + 64][ac]);
    sa1[1] = (unsigned)__cvta_generic_to_shared(&As[1][am0 + 64][ac]);
    sb[0]  = (unsigned)__cvta_generic_to_shared(&Bs[0][bn][ac]);
    sb[1]  = (unsigned)__cvta_generic_to_shared(&Bs[1][bn][ac]);

    const int nIter = (K + BK - 1) / BK;

    {
        int k = ac;
        int szA = (k + 4 <= K) ? 16 : 0;
        int szB = (bvalid && k + 4 <= K) ? 16 : 0;
        cp_async16(sa0[0], Abase + aoff0 + k, szA);
        cp_async16(sa1[0], Abase + aoff1 + k, szA);
        cp_async16(sb[0],  Bw + boff + k,     szB);
    }
    cp_commit();

    float acc[2][4][4];
    #pragma unroll
    for (int i = 0; i < 2; i++)
        #pragma unroll
        for (int j = 0; j < 4; j++)
            #pragma unroll
            for (int q = 0; q < 4; q++) acc[i][j][q] = 0.f;

    const int lr = lane >> 2;
    const int lc = lane & 3;

    for (int it = 0; it < nIter; it++) {
        const int cur = it & 1;
        if (it + 1 < nIter) {
            int k = (it + 1) * BK + ac;
            int szA = (k + 4 <= K) ? 16 : 0;
            int szB = (bvalid && k + 4 <= K) ? 16 : 0;
            const float* pa0 = Abase + aoff0 + (szA ? k : 0);
            const float* pa1 = Abase + aoff1 + (szA ? k : 0);
            const float* pb  = Bw + boff + (szB ? k : 0);
            cp_async16(sa0[cur ^ 1], pa0, szA);
            cp_async16(sa1[cur ^ 1], pa1, szA);
            cp_async16(sb[cur ^ 1],  pb,  szB);
            cp_commit();
            cp_wait<1>();
        } else {
            cp_wait<0>();
        }
        __syncthreads();

        #pragma unroll
        for (int ks = 0; ks < 2; ks++) {
            const int kb = ks * 8;
            unsigned a[2][4], b[4][2];
            #pragma unroll
            for (int mi = 0; mi < 2; mi++) {
                int r = wm * 32 + mi * 16 + lr;
                a[mi][0] = r2tf32(As[cur][r][kb + lc]);
                a[mi][1] = r2tf32(As[cur][r + 8][kb + lc]);
                a[mi][2] = r2tf32(As[cur][r][kb + lc + 4]);
                a[mi][3] = r2tf32(As[cur][r + 8][kb + lc + 4]);
            }
            #pragma unroll
            for (int ni = 0; ni < 4; ni++) {
                int c = wn * 32 + ni * 8 + lr;
                b[ni][0] = r2tf32(Bs[cur][c][kb + lc]);
                b[ni][1] = r2tf32(Bs[cur][c][kb + lc + 4]);
            }
            #pragma unroll
            for (int mi = 0; mi < 2; mi++)
                #pragma unroll
                for (int ni = 0; ni < 4; ni++)
                    mma8(acc[mi][ni], a[mi], b[ni]);
        }
        __syncthreads();
    }

    #pragma unroll
    for (int mi = 0; mi < 2; mi++) {
        int r = m0 + wm * 32 + mi * 16 + lr;
        #pragma unroll
        for (int ni = 0; ni < 4; ni++) {
            int cb = n0 + wn * 32 + ni * 8 + 2 * lc;
            #pragma unroll
            for (int q = 0; q < 2; q++) {
                int cc = cb + q;
                if (cc >= N) continue;
                float bv = act ? bias[cc] : 0.f;
                float v0 = acc[mi][ni][q]     + bv;
                float v1 = acc[mi][ni][q + 2] + bv;
                if (act) { v0 = lrelu_f(v0); v1 = lrelu_f(v1); }
                Out[(long)r * N + cc]       = v0;
                Out[(long)(r + 8) * N + cc] = v1;
            }
        }
    }
}

// =====================================================================
// Scores + diag mask + column softmax, grid (4, D), 256 thr (R8-proven).
// =====================================================================
#define SPAD 308
#define SCORES_SMEM ((80 * SPAD + 64 * 17) * 4)   // 102,912 B

__global__ void scores_kernel(const float* __restrict__ P,
                              const float* __restrict__ Cm,
                              float* __restrict__ A_out)
{
    extern __shared__ unsigned sdyn[];
    unsigned* Pt = sdyn;                       // [64][SPAD]
    unsigned* Ct = sdyn + 64 * SPAD;           // [16][SPAD]
    float*    Sh = (float*)(sdyn + 80 * SPAD); // [64][17]

    const int d  = blockIdx.y;
    const int j0 = blockIdx.x * 16;
    const int t = threadIdx.x;
    const int lane = t & 31;
    const int wid  = t >> 5;
    const int wm = wid >> 1;
    const int wn = wid & 1;
    const int lr = lane >> 2, lc = lane & 3;

    const float4* Pd4 = (const float4*)(P  + (long)d * S * H);
    const float4* Cd4 = (const float4*)(Cm + (long)d * S * H);

    for (int u = t; u < 64 * 76; u += 256) {
        int r = u / 76, c4 = u - r * 76;
        float4 v = make_float4(0.f, 0.f, 0.f, 0.f);
        if (c4 < 75) v = Pd4[r * 75 + c4];
        *(uint4*)&Pt[r * SPAD + c4 * 4] = cvt4(v);
    }
    for (int u = t; u < 16 * 76; u += 256) {
        int r = u / 76, c4 = u - r * 76;
        float4 v = make_float4(0.f, 0.f, 0.f, 0.f);
        if (c4 < 75) v = Cd4[(j0 + r) * 75 + c4];
        *(uint4*)&Ct[r * SPAD + c4 * 4] = cvt4(v);
    }
    __syncthreads();

    float acc[4] = {};
    {
        const int r = wm * 16 + lr;
        const int c = wn * 8 + lr;
        #pragma unroll
        for (int ks = 0; ks < 38; ks++) {
            const int kb = ks * 8;
            unsigned a[4], b[2];
            a[0] = Pt[r * SPAD + kb + lc];
            a[1] = Pt[(r + 8) * SPAD + kb + lc];
            a[2] = Pt[r * SPAD + kb + lc + 4];
            a[3] = Pt[(r + 8) * SPAD + kb + lc + 4];
            b[0] = Ct[c * SPAD + kb + lc];
            b[1] = Ct[c * SPAD + kb + lc + 4];
            mma8(acc, a, b);
        }
    }

    {
        int r = wm * 16 + lr;
        int cb = wn * 8 + 2 * lc;
        int gc = j0 + cb;
        Sh[r * 17 + cb]           = (r == gc)         ? NEGV : acc[0];
        Sh[r * 17 + cb + 1]       = (r == gc + 1)     ? NEGV : acc[1];
        Sh[(r + 8) * 17 + cb]     = (r + 8 == gc)     ? NEGV : acc[2];
        Sh[(r + 8) * 17 + cb + 1] = (r + 8 == gc + 1) ? NEGV : acc[3];
    }
    __syncthreads();

    #pragma unroll
    for (int cc = 0; cc < 2; cc++) {
        int c = wid * 2 + cc;
        float v0 = Sh[lane * 17 + c];
        float v1 = Sh[(lane + 32) * 17 + c];
        float m = fmaxf(v0, v1);
        #pragma unroll
        for (int o = 16; o; o >>= 1) m = fmaxf(m, __shfl_xor_sync(0xffffffffu, m, o));
        float e0 = __expf(v0 - m), e1 = __expf(v1 - m);
        float s = e0 + e1;
        #pragma unroll
        for (int o = 16; o; o >>= 1) s += __shfl_xor_sync(0xffffffffu, s, o);
        float inv = 1.f / s;
        Sh[lane * 17 + c]        = e0 * inv;
        Sh[(lane + 32) * 17 + c] = e1 * inv;
    }
    __syncthreads();

    for (int u = t; u < 64 * 16; u += 256) {
        int i = u >> 4, j = u & 15;
        A_out[(long)d * 4096 + i * 64 + j0 + j] = Sh[i * 17 + j];
    }
}

// =====================================================================
// G[d,i,h] = sum_k A[d,k,i] * Y2[d*64+k, h]  (tf32 mma), grid (5, D).
// cp.async raw loads + rna at fragment read; pad 68 for 16B-aligned
// cp.async destinations. Extras: x==0 -> rs, x==1 -> fri, x==2 -> v2.
// =====================================================================
#define GP 68

__global__ void g_kernel(const float* __restrict__ A_in,
                         const float* __restrict__ Y2,
                         const float* __restrict__ enc,
                         const float* __restrict__ w_root,
                         const float* __restrict__ b_root,
                         const float* __restrict__ W_r,
                         const float* __restrict__ root_embed,
                         float* __restrict__ G,
                         float* __restrict__ rs_out,
                         float* __restrict__ fri_out,
                         float* __restrict__ v2_out)
{
    const int d  = blockIdx.y;
    const int h0 = blockIdx.x * 64;
    const int t = threadIdx.x;
    const int lane = t & 31;
    const int wid  = t >> 5;
    const int wm = wid >> 1, wn = wid & 1;
    const int lr = lane >> 2, lc = lane & 3;

    __shared__ __align__(16) unsigned Ak[64][GP];   // Ak[k][i] raw fp32 bits
    __shared__ __align__(16) unsigned Ys[64][GP];   // Ys[k][h] raw fp32 bits
    __shared__ float sred[64];

    const float* Ad = A_in + (long)d * 4096;
    const float* Yd = Y2 + (long)d * 64 * H;
    const float* Ed = enc + (long)d * S * H;

    // async loads: 4 x 16B for A, 4 x 16B for Y2 slab, per thread
    #pragma unroll
    for (int j = 0; j < 4; j++) {
        int u = t + 256 * j;            // 0..1023
        int k = u >> 4, i = (u & 15) * 4;
        unsigned da = (unsigned)__cvta_generic_to_shared(&Ak[k][i]);
        cp_async16(da, Ad + k * 64 + i, 16);
        unsigned dy = (unsigned)__cvta_generic_to_shared(&Ys[k][i]);
        int h = h0 + i;
        int sz = (h + 4 <= H) ? 16 : 0;
        cp_async16(dy, Yd + (long)k * H + (sz ? h : 0), sz);
    }
    cp_commit();
    cp_wait<0>();
    __syncthreads();

    float acc[4][4] = {};
    #pragma unroll
    for (int ks = 0; ks < 8; ks++) {
        const int kb = ks * 8;
        unsigned a[4], b[4][2];
        int r = wm * 16 + lr;
        a[0] = r2tf32(Ak[kb + lc][r]);
        a[1] = r2tf32(Ak[kb + lc][r + 8]);
        a[2] = r2tf32(Ak[kb + lc + 4][r]);
        a[3] = r2tf32(Ak[kb + lc + 4][r + 8]);
        #pragma unroll
        for (int ni = 0; ni < 4; ni++) {
            int c = wn * 32 + ni * 8 + lr;
            b[ni][0] = r2tf32(Ys[kb + lc][c]);
            b[ni][1] = r2tf32(Ys[kb + lc + 4][c]);
        }
        #pragma unroll
        for (int ni = 0; ni < 4; ni++)
            mma8(acc[ni], a, b[ni]);
    }

    {
        int r = wm * 16 + lr;
        #pragma unroll
        for (int ni = 0; ni < 4; ni++) {
            int cb = wn * 32 + ni * 8 + 2 * lc;
            #pragma unroll
            for (int q = 0; q < 2; q++) {
                int h = h0 + cb + q;
                if (h >= H) continue;
                G[(long)(d * 64 + r) * H + h]     = acc[ni][q];
                G[(long)(d * 64 + r + 8) * H + h] = acc[ni][q + 2];
            }
        }
    }

    if (blockIdx.x == 0) {
        #pragma unroll
        for (int rr = 0; rr < 8; rr++) {
            int r = wid * 8 + rr;
            float s = Ad[r * 64 + lane] + Ad[r * 64 + lane + 32];
            #pragma unroll
            for (int o = 16; o; o >>= 1) s += __shfl_xor_sync(0xffffffffu, s, o);
            if (lane == 0) rs_out[d * 64 + r] = s;
        }
    } else if (blockIdx.x == 1) {
        const float br0 = b_root[0];
        #pragma unroll
        for (int ss = 0; ss < 8; ss++) {
            int s = wid * 8 + ss;
            const float* e = Ed + s * H;
            float p = 0.f;
            for (int h = lane; h < H; h += 32) p += e[h] * w_root[h];
            #pragma unroll
            for (int o = 16; o; o >>= 1) p += __shfl_xor_sync(0xffffffffu, p, o);
            if (lane == 0) sred[s] = p + br0;
        }
        __syncthreads();
        float mye = 0.f;
        if (t < 64) {
            float m = -1e30f;
            for (int u = 0; u < 64; u++) m = fmaxf(m, sred[u]);
            mye = __expf(sred[t] - m);
        }
        __syncthreads();
        if (t < 64) sred[t] = mye;
        __syncthreads();
        if (t < 64) {
            float ssum = 0.f;
            for (int u = 0; u < 64; u++) ssum += sred[u];
            fri_out[d * 64 + t] = mye / ssum;
        }
    } else if (blockIdx.x == 2) {
        if (wid < 5) {
            int n = d * 5 + wid;
            if (n < H) {
                const float* w = W_r + (long)n * 900 + 300;
                float p = 0.f;
                for (int k = lane; k < H; k += 32) p += w[k] * root_embed[k];
                #pragma unroll
                for (int o = 16; o; o >>= 1) p += __shfl_xor_sync(0xffffffffu, p, o);
                if (lane == 0) v2_out[n] = p;
            }
        }
    }
}

// =====================================================================
// ri+mean (R8-proven): fin[doc,n] = mean_s lrelu( enc@W1^T +
//        rs*(enc@W3^T) + G + fri*v2 + b_r )
// =====================================================================
__global__ void ri_mean_kernel(const float* __restrict__ enc,
                               const float* __restrict__ W_r,   // [H, 900]
                               const float* __restrict__ b_r,
                               const float* __restrict__ G,
                               const float* __restrict__ rs,
                               const float* __restrict__ fri,
                               const float* __restrict__ v2,
                               float* __restrict__ fin)
{
    __shared__ __align__(16) unsigned As[BM][BKP];
    __shared__ __align__(16) unsigned B1s[BN][BKP];
    __shared__ __align__(16) unsigned B3s[BN][BKP];
    __shared__ float red[2][BN];

    const int K = H;
    const int N = H;
    const int tid  = threadIdx.x;
    const int lane = tid & 31;
    const int wid  = tid >> 5;
    const int wm = wid >> 1, wn = wid & 1;
    const int m0 = blockIdx.y * BM;
    const int n0 = blockIdx.x * BN;

    if (tid < 2 * BN) ((float*)red)[tid] = 0.f;

    const int am0 = tid >> 2;
    const int ac  = (tid & 3) * 4;
    const long aoff0 = (long)(m0 + am0) * K;
    const long aoff1 = (long)(m0 + am0 + 64) * K;
    const int  bn     = tid >> 2;
    const bool bvalid = (n0 + bn) < N;
    const long boff   = (long)(n0 + bn) * 900;

    float acc1[2][4][4], acc3[2][4][4];
    #pragma unroll
    for (int i = 0; i < 2; i++)
        #pragma unroll
        for (int j = 0; j < 4; j++)
            #pragma unroll
            for (int q = 0; q < 4; q++) { acc1[i][j][q] = 0.f; acc3[i][j][q] = 0.f; }

    const int lr = lane >> 2, lc = lane & 3;

    for (int k0 = 0; k0 < K; k0 += BK) {
        if (k0 + BK <= K) {
            float4 a0 = *(const float4*)(enc + aoff0 + k0 + ac);
            float4 a1 = *(const float4*)(enc + aoff1 + k0 + ac);
            float4 b1 = bvalid ? *(const float4*)(W_r + boff + k0 + ac) : make_float4(0,0,0,0);
            float4 b3 = bvalid ? *(const float4*)(W_r + boff + 600 + k0 + ac) : make_float4(0,0,0,0);
            *(uint4*)&As[am0][ac]      = cvt4(a0);
            *(uint4*)&As[am0 + 64][ac] = cvt4(a1);
            *(uint4*)&B1s[bn][ac]      = cvt4(b1);
            *(uint4*)&B3s[bn][ac]      = cvt4(b3);
        } else {
            #pragma unroll
            for (int u = 0; u < 4; u++) {
                int k = k0 + ac + u;
                bool kk = k < K;
                As[am0][ac + u]      = kk ? f2tf32(enc[aoff0 + k]) : 0u;
                As[am0 + 64][ac + u] = kk ? f2tf32(enc[aoff1 + k]) : 0u;
                B1s[bn][ac + u]      = (bvalid && kk) ? f2tf32(W_r[boff + k]) : 0u;
                B3s[bn][ac + u]      = (bvalid && kk) ? f2tf32(W_r[boff + 600 + k]) : 0u;
            }
        }
        __syncthreads();
        #pragma unroll
        for (int ks = 0; ks < 2; ks++) {
            const int kb = ks * 8;
            unsigned a[2][4], b1[4][2], b3[4][2];
            #pragma unroll
            for (int mi = 0; mi < 2; mi++) {
                int r = wm * 32 + mi * 16 + lr;
                a[mi][0] = As[r][kb + lc];
                a[mi][1] = As[r + 8][kb + lc];
                a[mi][2] = As[r][kb + lc + 4];
                a[mi][3] = As[r + 8][kb + lc + 4];
            }
            #pragma unroll
            for (int ni = 0; ni < 4; ni++) {
                int c = wn * 32 + ni * 8 + lr;
                b1[ni][0] = B1s[c][kb + lc];
                b1[ni][1] = B1s[c][kb + lc + 4];
                b3[ni][0] = B3s[c][kb + lc];
                b3[ni][1] = B3s[c][kb + lc + 4];
            }
            #pragma unroll
            for (int mi = 0; mi < 2; mi++)
                #pragma unroll
                for (int ni = 0; ni < 4; ni++) {
                    mma8(acc1[mi][ni], a[mi], b1[ni]);
                    mma8(acc3[mi][ni], a[mi], b3[ni]);
                }
        }
        __syncthreads();
    }

    const int dl = wm >> 1;
    #pragma unroll
    for (int ni = 0; ni < 4; ni++) {
        int cb = n0 + wn * 32 + ni * 8 + 2 * lc;
        float s0 = 0.f, s1 = 0.f;
        #pragma unroll
        for (int mi = 0; mi < 2; mi++) {
            int r = m0 + wm * 32 + mi * 16 + lr;
            #pragma unroll
            for (int half = 0; half < 2; half++) {
                int m = r + half * 8;
                float rsm = rs[m], frm = fri[m];
                if (cb < N) {
                    float v = acc1[mi][ni][half * 2] + rsm * acc3[mi][ni][half * 2]
                            + G[(long)m * H + cb] + frm * v2[cb] + b_r[cb];
                    s0 += lrelu_f(v);
                }
                if (cb + 1 < N) {
                    float v = acc1[mi][ni][half * 2 + 1] + rsm * acc3[mi][ni][half * 2 + 1]
                            + G[(long)m * H + cb + 1] + frm * v2[cb + 1] + b_r[cb + 1];
                    s1 += lrelu_f(v);
                }
            }
        }
        #pragma unroll
        for (int o = 4; o < 32; o <<= 1) {
            s0 += __shfl_xor_sync(0xffffffffu, s0, o);
            s1 += __shfl_xor_sync(0xffffffffu, s1, o);
        }
        if (lane < 4) {
            atomicAdd(&red[dl][wn * 32 + ni * 8 + 2 * lc],     s0);
            atomicAdd(&red[dl][wn * 32 + ni * 8 + 2 * lc + 1], s1);
        }
    }
    __syncthreads();
    if (tid < 128) {
        int dloc = tid >> 6, c = tid & 63;
        int col = n0 + c;
        if (col < N)
            fin[(long)(blockIdx.y * 2 + dloc) * H + col] = red[dloc][c] * (1.f / 64.f);
    }
}

// out[d,c]: one warp per output
__global__ void cls_kernel(const float* __restrict__ fin,
                           const float* __restrict__ Wc,
                           const float* __restrict__ bc,
                           float* __restrict__ out)
{
    int gw = blockIdx.x * (blockDim.x >> 5) + (threadIdx.x >> 5);
    int lane = threadIdx.x & 31;
    if (gw >= 128) return;
    int d = gw >> 1, c = gw & 1;
    const float* f = fin + d * H;
    const float* w = Wc + c * H;
    float p = 0.f;
    for (int h = lane; h < H; h += 32) p += f[h] * w[h];
    #pragma unroll
    for (int o = 16; o; o >>= 1) p += __shfl_xor_sync(0xffffffffu, p, o);
    if (lane == 0) out[d * 2 + c] = p + bc[c];
}

// =====================================================================
extern "C" void kernel_launch(void* const* d_in, const int* in_sizes, int n_in,
                              void* d_out, int out_size)
{
    const int*   word_indices = (const int*)  d_in[0];
    const float* E            = (const float*)d_in[1];
    const float* W_sent       = (const float*)d_in[2];
    const float* b_sent       = (const float*)d_in[3];
    const float* W_par        = (const float*)d_in[4];
    const float* b_par        = (const float*)d_in[5];
    const float* W_ch         = (const float*)d_in[6];
    const float* b_ch         = (const float*)d_in[7];
    const float* w_root       = (const float*)d_in[8];
    const float* b_root       = (const float*)d_in[9];
    const float* root_embed   = (const float*)d_in[10];
    const float* W_r          = (const float*)d_in[11];
    const float* b_r          = (const float*)d_in[12];
    const float* W_cls        = (const float*)d_in[13];
    const float* b_cls        = (const float*)d_in[14];

    float* out_ptr = (float*)d_out;
    float* A_ptr   = out_ptr + D * 2;
    float* fri_ptr = A_ptr + D * S * S;

    float *enc, *Pm, *Cm, *Y2, *G, *rs, *fin, *v2;
    cudaGetSymbolAddress((void**)&enc, g_enc);
    cudaGetSymbolAddress((void**)&Pm,  g_P);
    cudaGetSymbolAddress((void**)&Cm,  g_C);
    cudaGetSymbolAddress((void**)&Y2,  g_Y2);
    cudaGetSymbolAddress((void**)&G,   g_G);
    cudaGetSymbolAddress((void**)&rs,  g_rs);
    cudaGetSymbolAddress((void**)&fin, g_fin);
    cudaGetSymbolAddress((void**)&v2,  g_v2);

    cudaFuncSetAttribute(scores_kernel,
                         cudaFuncAttributeMaxDynamicSharedMemorySize, SCORES_SMEM);

    dim3 gEnc((H + BN - 1) / BN, NROWS / BM, 1);
    gemm_tf32_kernel<true><<<gEnc, 256>>>(
        E, word_indices + (L - 1), L,
        W_sent, b_sent, enc,
        nullptr, nullptr, nullptr,
        nullptr, nullptr, nullptr, H, W, W, W, W);

    // P, C (lrelu+bias) and Y2 = enc @ W2^T (linear; W2 rows inside W_r, ld=900)
    dim3 gPCY((H + BN - 1) / BN, NROWS / BM, 3);
    gemm_tf32_kernel<false><<<gPCY, 256>>>(
        enc, nullptr, 0,
        W_par,       b_par,   Pm,
        W_ch,        b_ch,    Cm,
        W_r + 300,   nullptr, Y2,
        H, H, H, H, 900);

    // scores + mask + column softmax -> A (in d_out)
    scores_kernel<<<dim3(4, D), 256, SCORES_SMEM>>>(Pm, Cm, A_ptr);

    // G = A^T @ Y2 per doc; also rs (x==0), fri (x==1), v2 slice (x==2)
    g_kernel<<<dim3(5, D), 256>>>(A_ptr, Y2, enc, w_root, b_root,
                                  W_r, root_embed, G, rs, fri_ptr, v2);

    ri_mean_kernel<<<dim3(5, 32), 256>>>(enc, W_r, b_r, G, rs, fri_ptr, v2, fin);

    cls_kernel<<<8, 512>>>(fin, W_cls, b_cls, out_ptr);
}

// round 14
// speedup vs baseline: 1.1551x; 1.0404x over previous
#include <cuda_runtime.h>

#define D 64
#define S 64
#define L 64
#define W 300
#define H 300
#define NROWS (D*S)          // 4096
#define NEGV (-9999999.0f)

// ---------------- device scratch (no allocation allowed) ----------------
__device__ float g_enc[NROWS * H];
__device__ float g_P  [NROWS * H];
__device__ float g_C  [NROWS * H];
__device__ float g_Y2 [NROWS * H];
__device__ float g_G  [NROWS * H];
__device__ float g_rs [NROWS];
__device__ float g_fin[D * H];
__device__ float g_v2 [H];

__device__ __forceinline__ float lrelu_f(float x) { return x > 0.f ? x : 0.01f * x; }

__device__ __forceinline__ unsigned f2tf32(float f) {
    unsigned u;
    asm("cvt.rna.tf32.f32 %0, %1;" : "=r"(u) : "f"(f));
    return u;
}
// round raw fp32 bits (stored in smem as unsigned) to tf32
__device__ __forceinline__ unsigned r2tf32(unsigned raw) {
    return f2tf32(__uint_as_float(raw));
}
__device__ __forceinline__ uint4 cvt4(float4 v) {
    return make_uint4(f2tf32(v.x), f2tf32(v.y), f2tf32(v.z), f2tf32(v.w));
}

__device__ __forceinline__ void mma8(float* c, const unsigned* a, const unsigned* b) {
    asm volatile(
        "mma.sync.aligned.m16n8k8.row.col.f32.tf32.tf32.f32 "
        "{%0,%1,%2,%3}, {%4,%5,%6,%7}, {%8,%9}, {%0,%1,%2,%3};"
        : "+f"(c[0]), "+f"(c[1]), "+f"(c[2]), "+f"(c[3])
        : "r"(a[0]), "r"(a[1]), "r"(a[2]), "r"(a[3]), "r"(b[0]), "r"(b[1]));
}

// cp.async 16B with zero-fill when srcsize==0
__device__ __forceinline__ void cp_async16(unsigned smem_addr, const void* gptr, int srcsize) {
    asm volatile("cp.async.ca.shared.global [%0], [%1], 16, %2;"
                 :: "r"(smem_addr), "l"(gptr), "r"(srcsize));
}
__device__ __forceinline__ void cp_commit() {
    asm volatile("cp.async.commit_group;");
}
template<int N>
__device__ __forceinline__ void cp_wait() {
    asm volatile("cp.async.wait_group %0;" :: "n"(N));
}

#define BM 128
#define BN 64
#define BK 16
#define BKP 20

// =====================================================================
// TF32 GEMM, cp.async depth-2 pipeline, rna tf32 at fragment read
// (R12-proven). Out[M,N] = act( A[M,K] @ B[N,K(ld=ldb)]^T + bias[N] ).
// z selects among 3 (B,bias,Out) triples; bias==nullptr => linear.
// =====================================================================
template<bool GATHER>
__global__ void gemm_tf32_kernel(
    const float* __restrict__ Abase, const int* __restrict__ idx, int idxStride,
    const float* __restrict__ B0, const float* __restrict__ bias0, float* __restrict__ Out0,
    const float* __restrict__ B1, const float* __restrict__ bias1, float* __restrict__ Out1,
    const float* __restrict__ B2, const float* __restrict__ bias2, float* __restrict__ Out2,
    int N, int K, int ldb0, int ldb1, int ldb2)
{
    const float* Bw   = B0;
    const float* bias = bias0;
    float*       Out  = Out0;
    int          ldb  = ldb0;
    if (blockIdx.z == 1) { Bw = B1; bias = bias1; Out = Out1; ldb = ldb1; }
    if (blockIdx.z == 2) { Bw = B2; bias = bias2; Out = Out2; ldb = ldb2; }
    const bool act = (bias != nullptr);

    __shared__ __align__(16) unsigned As[2][BM][BKP];
    __shared__ __align__(16) unsigned Bs[2][BN][BKP];

    const int tid  = threadIdx.x;
    const int lane = tid & 31;
    const int wid  = tid >> 5;
    const int wm   = wid >> 1;
    const int wn   = wid & 1;
    const int m0   = blockIdx.y * BM;
    const int n0   = blockIdx.x * BN;

    const int am0 = tid >> 2;
    const int ac  = (tid & 3) * 4;
    long aoff0, aoff1;
    if (GATHER) {
        aoff0 = (long)idx[(long)(m0 + am0) * idxStride] * K;
        aoff1 = (long)idx[(long)(m0 + am0 + 64) * idxStride] * K;
    } else {
        aoff0 = (long)(m0 + am0) * K;
        aoff1 = (long)(m0 + am0 + 64) * K;
    }
    const int  bn     = tid >> 2;
    const bool bvalid = (n0 + bn) < N;
    const long boff   = bvalid ? (long)(n0 + bn) * ldb : 0;

    unsigned sa0[2], sa1[2], sb[2];
    sa0[0] = (unsigned)__cvta_generic_to_shared(&As[0][am0][ac]);
    sa0[1] = (unsigned)__cvta_generic_to_shared(&As[1][am0][ac]);
    sa1[0] = (unsigned)__cvta_generic_to_shared(&As[0][am0 + 64][ac]);
    sa1[1] = (unsigned)__cvta_generic_to_shared(&As[1][am0 + 64][ac]);
    sb[0]  = (unsigned)__cvta_generic_to_shared(&Bs[0][bn][ac]);
    sb[1]  = (unsigned)__cvta_generic_to_shared(&Bs[1][bn][ac]);

    const int nIter = (K + BK - 1) / BK;

    {
        int k = ac;
        int szA = (k + 4 <= K) ? 16 : 0;
        int szB = (bvalid && k + 4 <= K) ? 16 : 0;
        cp_async16(sa0[0], Abase + aoff0 + k, szA);
        cp_async16(sa1[0], Abase + aoff1 + k, szA);
        cp_async16(sb[0],  Bw + boff + k,     szB);
    }
    cp_commit();

    float acc[2][4][4];
    #pragma unroll
    for (int i = 0; i < 2; i++)
        #pragma unroll
        for (int j = 0; j < 4; j++)
            #pragma unroll
            for (int q = 0; q < 4; q++) acc[i][j][q] = 0.f;

    const int lr = lane >> 2;
    const int lc = lane & 3;

    for (int it = 0; it < nIter; it++) {
        const int cur = it & 1;
        if (it + 1 < nIter) {
            int k = (it + 1) * BK + ac;
            int szA = (k + 4 <= K) ? 16 : 0;
            int szB = (bvalid && k + 4 <= K) ? 16 : 0;
            const float* pa0 = Abase + aoff0 + (szA ? k : 0);
            const float* pa1 = Abase + aoff1 + (szA ? k : 0);
            const float* pb  = Bw + boff + (szB ? k : 0);
            cp_async16(sa0[cur ^ 1], pa0, szA);
            cp_async16(sa1[cur ^ 1], pa1, szA);
            cp_async16(sb[cur ^ 1],  pb,  szB);
            cp_commit();
            cp_wait<1>();
        } else {
            cp_wait<0>();
        }
        __syncthreads();

        #pragma unroll
        for (int ks = 0; ks < 2; ks++) {
            const int kb = ks * 8;
            unsigned a[2][4], b[4][2];
            #pragma unroll
            for (int mi = 0; mi < 2; mi++) {
                int r = wm * 32 + mi * 16 + lr;
                a[mi][0] = r2tf32(As[cur][r][kb + lc]);
                a[mi][1] = r2tf32(As[cur][r + 8][kb + lc]);
                a[mi][2] = r2tf32(As[cur][r][kb + lc + 4]);
                a[mi][3] = r2tf32(As[cur][r + 8][kb + lc + 4]);
            }
            #pragma unroll
            for (int ni = 0; ni < 4; ni++) {
                int c = wn * 32 + ni * 8 + lr;
                b[ni][0] = r2tf32(Bs[cur][c][kb + lc]);
                b[ni][1] = r2tf32(Bs[cur][c][kb + lc + 4]);
            }
            #pragma unroll
            for (int mi = 0; mi < 2; mi++)
                #pragma unroll
                for (int ni = 0; ni < 4; ni++)
                    mma8(acc[mi][ni], a[mi], b[ni]);
        }
        __syncthreads();
    }

    #pragma unroll
    for (int mi = 0; mi < 2; mi++) {
        int r = m0 + wm * 32 + mi * 16 + lr;
        #pragma unroll
        for (int ni = 0; ni < 4; ni++) {
            int cb = n0 + wn * 32 + ni * 8 + 2 * lc;
            #pragma unroll
            for (int q = 0; q < 2; q++) {
                int cc = cb + q;
                if (cc >= N) continue;
                float bv = act ? bias[cc] : 0.f;
                float v0 = acc[mi][ni][q]     + bv;
                float v1 = acc[mi][ni][q + 2] + bv;
                if (act) { v0 = lrelu_f(v0); v1 = lrelu_f(v1); }
                Out[(long)r * N + cc]       = v0;
                Out[(long)(r + 8) * N + cc] = v1;
            }
        }
    }
}

// =====================================================================
// Scores + diag mask + column softmax, grid (4, D), 256 thr.
// cp.async raw loads (P: 64x76 chunks, C: 16x76 chunks), rna at
// fragment read. Chunk 75 zero-filled covers padded k=300..303;
// words 304..307 never referenced (mma k-index max 303).
// =====================================================================
#define SPAD 308
#define SCORES_SMEM ((80 * SPAD + 64 * 17) * 4)   // 102,912 B

__global__ void scores_kernel(const float* __restrict__ P,
                              const float* __restrict__ Cm,
                              float* __restrict__ A_out)
{
    extern __shared__ unsigned sdyn[];
    unsigned* Pt = sdyn;                       // [64][SPAD] raw fp32 bits
    unsigned* Ct = sdyn + 64 * SPAD;           // [16][SPAD] raw fp32 bits
    float*    Sh = (float*)(sdyn + 80 * SPAD); // [64][17]

    const int d  = blockIdx.y;
    const int j0 = blockIdx.x * 16;
    const int t = threadIdx.x;
    const int lane = t & 31;
    const int wid  = t >> 5;
    const int wm = wid >> 1;
    const int wn = wid & 1;
    const int lr = lane >> 2, lc = lane & 3;

    const float* Pd = P  + (long)d * S * H;
    const float* Cd = Cm + (long)d * S * H;

    // async raw loads: P 64x76 chunks (19/thread), C 16x76 chunks (~5/thread)
    for (int u = t; u < 64 * 76; u += 256) {
        int r = u / 76, c4 = u - r * 76;
        unsigned dst = (unsigned)__cvta_generic_to_shared(&Pt[r * SPAD + c4 * 4]);
        int sz = (c4 < 75) ? 16 : 0;
        cp_async16(dst, Pd + r * H + (sz ? c4 * 4 : 0), sz);
    }
    for (int u = t; u < 16 * 76; u += 256) {
        int r = u / 76, c4 = u - r * 76;
        unsigned dst = (unsigned)__cvta_generic_to_shared(&Ct[r * SPAD + c4 * 4]);
        int sz = (c4 < 75) ? 16 : 0;
        cp_async16(dst, Cd + (j0 + r) * H + (sz ? c4 * 4 : 0), sz);
    }
    cp_commit();
    cp_wait<0>();
    __syncthreads();

    float acc[4] = {};
    {
        const int r = wm * 16 + lr;
        const int c = wn * 8 + lr;
        #pragma unroll
        for (int ks = 0; ks < 38; ks++) {
            const int kb = ks * 8;
            unsigned a[4], b[2];
            a[0] = r2tf32(Pt[r * SPAD + kb + lc]);
            a[1] = r2tf32(Pt[(r + 8) * SPAD + kb + lc]);
            a[2] = r2tf32(Pt[r * SPAD + kb + lc + 4]);
            a[3] = r2tf32(Pt[(r + 8) * SPAD + kb + lc + 4]);
            b[0] = r2tf32(Ct[c * SPAD + kb + lc]);
            b[1] = r2tf32(Ct[c * SPAD + kb + lc + 4]);
            mma8(acc, a, b);
        }
    }

    {
        int r = wm * 16 + lr;
        int cb = wn * 8 + 2 * lc;
        int gc = j0 + cb;
        Sh[r * 17 + cb]           = (r == gc)         ? NEGV : acc[0];
        Sh[r * 17 + cb + 1]       = (r == gc + 1)     ? NEGV : acc[1];
        Sh[(r + 8) * 17 + cb]     = (r + 8 == gc)     ? NEGV : acc[2];
        Sh[(r + 8) * 17 + cb + 1] = (r + 8 == gc + 1) ? NEGV : acc[3];
    }
    __syncthreads();

    #pragma unroll
    for (int cc = 0; cc < 2; cc++) {
        int c = wid * 2 + cc;
        float v0 = Sh[lane * 17 + c];
        float v1 = Sh[(lane + 32) * 17 + c];
        float m = fmaxf(v0, v1);
        #pragma unroll
        for (int o = 16; o; o >>= 1) m = fmaxf(m, __shfl_xor_sync(0xffffffffu, m, o));
        float e0 = __expf(v0 - m), e1 = __expf(v1 - m);
        float s = e0 + e1;
        #pragma unroll
        for (int o = 16; o; o >>= 1) s += __shfl_xor_sync(0xffffffffu, s, o);
        float inv = 1.f / s;
        Sh[lane * 17 + c]        = e0 * inv;
        Sh[(lane + 32) * 17 + c] = e1 * inv;
    }
    __syncthreads();

    for (int u = t; u < 64 * 16; u += 256) {
        int i = u >> 4, j = u & 15;
        A_out[(long)d * 4096 + i * 64 + j0 + j] = Sh[i * 17 + j];
    }
}

// =====================================================================
// G[d,i,h] = sum_k A[d,k,i] * Y2[d*64+k, h]  (tf32 mma), grid (5, D).
// cp.async raw loads + rna at fragment read (R13-proven).
// Extras: x==0 -> rs, x==1 -> fri, x==2 -> v2.
// =====================================================================
#define GP 68

__global__ void g_kernel(const float* __restrict__ A_in,
                         const float* __restrict__ Y2,
                         const float* __restrict__ enc,
                         const float* __restrict__ w_root,
                         const float* __restrict__ b_root,
                         const float* __restrict__ W_r,
                         const float* __restrict__ root_embed,
                         float* __restrict__ G,
                         float* __restrict__ rs_out,
                         float* __restrict__ fri_out,
                         float* __restrict__ v2_out)
{
    const int d  = blockIdx.y;
    const int h0 = blockIdx.x * 64;
    const int t = threadIdx.x;
    const int lane = t & 31;
    const int wid  = t >> 5;
    const int wm = wid >> 1, wn = wid & 1;
    const int lr = lane >> 2, lc = lane & 3;

    __shared__ __align__(16) unsigned Ak[64][GP];
    __shared__ __align__(16) unsigned Ys[64][GP];
    __shared__ float sred[64];

    const float* Ad = A_in + (long)d * 4096;
    const float* Yd = Y2 + (long)d * 64 * H;
    const float* Ed = enc + (long)d * S * H;

    #pragma unroll
    for (int j = 0; j < 4; j++) {
        int u = t + 256 * j;
        int k = u >> 4, i = (u & 15) * 4;
        unsigned da = (unsigned)__cvta_generic_to_shared(&Ak[k][i]);
        cp_async16(da, Ad + k * 64 + i, 16);
        unsigned dy = (unsigned)__cvta_generic_to_shared(&Ys[k][i]);
        int h = h0 + i;
        int sz = (h + 4 <= H) ? 16 : 0;
        cp_async16(dy, Yd + (long)k * H + (sz ? h : 0), sz);
    }
    cp_commit();
    cp_wait<0>();
    __syncthreads();

    float acc[4][4] = {};
    #pragma unroll
    for (int ks = 0; ks < 8; ks++) {
        const int kb = ks * 8;
        unsigned a[4], b[4][2];
        int r = wm * 16 + lr;
        a[0] = r2tf32(Ak[kb + lc][r]);
        a[1] = r2tf32(Ak[kb + lc][r + 8]);
        a[2] = r2tf32(Ak[kb + lc + 4][r]);
        a[3] = r2tf32(Ak[kb + lc + 4][r + 8]);
        #pragma unroll
        for (int ni = 0; ni < 4; ni++) {
            int c = wn * 32 + ni * 8 + lr;
            b[ni][0] = r2tf32(Ys[kb + lc][c]);
            b[ni][1] = r2tf32(Ys[kb + lc + 4][c]);
        }
        #pragma unroll
        for (int ni = 0; ni < 4; ni++)
            mma8(acc[ni], a, b[ni]);
    }

    {
        int r = wm * 16 + lr;
        #pragma unroll
        for (int ni = 0; ni < 4; ni++) {
            int cb = wn * 32 + ni * 8 + 2 * lc;
            #pragma unroll
            for (int q = 0; q < 2; q++) {
                int h = h0 + cb + q;
                if (h >= H) continue;
                G[(long)(d * 64 + r) * H + h]     = acc[ni][q];
                G[(long)(d * 64 + r + 8) * H + h] = acc[ni][q + 2];
            }
        }
    }

    if (blockIdx.x == 0) {
        #pragma unroll
        for (int rr = 0; rr < 8; rr++) {
            int r = wid * 8 + rr;
            float s = Ad[r * 64 + lane] + Ad[r * 64 + lane + 32];
            #pragma unroll
            for (int o = 16; o; o >>= 1) s += __shfl_xor_sync(0xffffffffu, s, o);
            if (lane == 0) rs_out[d * 64 + r] = s;
        }
    } else if (blockIdx.x == 1) {
        const float br0 = b_root[0];
        #pragma unroll
        for (int ss = 0; ss < 8; ss++) {
            int s = wid * 8 + ss;
            const float* e = Ed + s * H;
            float p = 0.f;
            for (int h = lane; h < H; h += 32) p += e[h] * w_root[h];
            #pragma unroll
            for (int o = 16; o; o >>= 1) p += __shfl_xor_sync(0xffffffffu, p, o);
            if (lane == 0) sred[s] = p + br0;
        }
        __syncthreads();
        float mye = 0.f;
        if (t < 64) {
            float m = -1e30f;
            for (int u = 0; u < 64; u++) m = fmaxf(m, sred[u]);
            mye = __expf(sred[t] - m);
        }
        __syncthreads();
        if (t < 64) sred[t] = mye;
        __syncthreads();
        if (t < 64) {
            float ssum = 0.f;
            for (int u = 0; u < 64; u++) ssum += sred[u];
            fri_out[d * 64 + t] = mye / ssum;
        }
    } else if (blockIdx.x == 2) {
        if (wid < 5) {
            int n = d * 5 + wid;
            if (n < H) {
                const float* w = W_r + (long)n * 900 + 300;
                float p = 0.f;
                for (int k = lane; k < H; k += 32) p += w[k] * root_embed[k];
                #pragma unroll
                for (int o = 16; o; o >>= 1) p += __shfl_xor_sync(0xffffffffu, p, o);
                if (lane == 0) v2_out[n] = p;
            }
        }
    }
}

// =====================================================================
// ri+mean (R8-proven): fin[doc,n] = mean_s lrelu( enc@W1^T +
//        rs*(enc@W3^T) + G + fri*v2 + b_r )
// =====================================================================
__global__ void ri_mean_kernel(const float* __restrict__ enc,
                               const float* __restrict__ W_r,   // [H, 900]
                               const float* __restrict__ b_r,
                               const float* __restrict__ G,
                               const float* __restrict__ rs,
                               const float* __restrict__ fri,
                               const float* __restrict__ v2,
                               float* __restrict__ fin)
{
    __shared__ __align__(16) unsigned As[BM][BKP];
    __shared__ __align__(16) unsigned B1s[BN][BKP];
    __shared__ __align__(16) unsigned B3s[BN][BKP];
    __shared__ float red[2][BN];

    const int K = H;
    const int N = H;
    const int tid  = threadIdx.x;
    const int lane = tid & 31;
    const int wid  = tid >> 5;
    const int wm = wid >> 1, wn = wid & 1;
    const int m0 = blockIdx.y * BM;
    const int n0 = blockIdx.x * BN;

    if (tid < 2 * BN) ((float*)red)[tid] = 0.f;

    const int am0 = tid >> 2;
    const int ac  = (tid & 3) * 4;
    const long aoff0 = (long)(m0 + am0) * K;
    const long aoff1 = (long)(m0 + am0 + 64) * K;
    const int  bn     = tid >> 2;
    const bool bvalid = (n0 + bn) < N;
    const long boff   = (long)(n0 + bn) * 900;

    float acc1[2][4][4], acc3[2][4][4];
    #pragma unroll
    for (int i = 0; i < 2; i++)
        #pragma unroll
        for (int j = 0; j < 4; j++)
            #pragma unroll
            for (int q = 0; q < 4; q++) { acc1[i][j][q] = 0.f; acc3[i][j][q] = 0.f; }

    const int lr = lane >> 2, lc = lane & 3;

    for (int k0 = 0; k0 < K; k0 += BK) {
        if (k0 + BK <= K) {
            float4 a0 = *(const float4*)(enc + aoff0 + k0 + ac);
            float4 a1 = *(const float4*)(enc + aoff1 + k0 + ac);
            float4 b1 = bvalid ? *(const float4*)(W_r + boff + k0 + ac) : make_float4(0,0,0,0);
            float4 b3 = bvalid ? *(const float4*)(W_r + boff + 600 + k0 + ac) : make_float4(0,0,0,0);
            *(uint4*)&As[am0][ac]      = cvt4(a0);
            *(uint4*)&As[am0 + 64][ac] = cvt4(a1);
            *(uint4*)&B1s[bn][ac]      = cvt4(b1);
            *(uint4*)&B3s[bn][ac]      = cvt4(b3);
        } else {
            #pragma unroll
            for (int u = 0; u < 4; u++) {
                int k = k0 + ac + u;
                bool kk = k < K;
                As[am0][ac + u]      = kk ? f2tf32(enc[aoff0 + k]) : 0u;
                As[am0 + 64][ac + u] = kk ? f2tf32(enc[aoff1 + k]) : 0u;
                B1s[bn][ac + u]      = (bvalid && kk) ? f2tf32(W_r[boff + k]) : 0u;
                B3s[bn][ac + u]      = (bvalid && kk) ? f2tf32(W_r[boff + 600 + k]) : 0u;
            }
        }
        __syncthreads();
        #pragma unroll
        for (int ks = 0; ks < 2; ks++) {
            const int kb = ks * 8;
            unsigned a[2][4], b1[4][2], b3[4][2];
            #pragma unroll
            for (int mi = 0; mi < 2; mi++) {
                int r = wm * 32 + mi * 16 + lr;
                a[mi][0] = As[r][kb + lc];
                a[mi][1] = As[r + 8][kb + lc];
                a[mi][2] = As[r][kb + lc + 4];
                a[mi][3] = As[r + 8][kb + lc + 4];
            }
            #pragma unroll
            for (int ni = 0; ni < 4; ni++) {
                int c = wn * 32 + ni * 8 + lr;
                b1[ni][0] = B1s[c][kb + lc];
                b1[ni][1] = B1s[c][kb + lc + 4];
                b3[ni][0] = B3s[c][kb + lc];
                b3[ni][1] = B3s[c][kb + lc + 4];
            }
            #pragma unroll
            for (int mi = 0; mi < 2; mi++)
                #pragma unroll
                for (int ni = 0; ni < 4; ni++) {
                    mma8(acc1[mi][ni], a[mi], b1[ni]);
                    mma8(acc3[mi][ni], a[mi], b3[ni]);
                }
        }
        __syncthreads();
    }

    const int dl = wm >> 1;
    #pragma unroll
    for (int ni = 0; ni < 4; ni++) {
        int cb = n0 + wn * 32 + ni * 8 + 2 * lc;
        float s0 = 0.f, s1 = 0.f;
        #pragma unroll
        for (int mi = 0; mi < 2; mi++) {
            int r = m0 + wm * 32 + mi * 16 + lr;
            #pragma unroll
            for (int half = 0; half < 2; half++) {
                int m = r + half * 8;
                float rsm = rs[m], frm = fri[m];
                if (cb < N) {
                    float v = acc1[mi][ni][half * 2] + rsm * acc3[mi][ni][half * 2]
                            + G[(long)m * H + cb] + frm * v2[cb] + b_r[cb];
                    s0 += lrelu_f(v);
                }
                if (cb + 1 < N) {
                    float v = acc1[mi][ni][half * 2 + 1] + rsm * acc3[mi][ni][half * 2 + 1]
                            + G[(long)m * H + cb + 1] + frm * v2[cb + 1] + b_r[cb + 1];
                    s1 += lrelu_f(v);
                }
            }
        }
        #pragma unroll
        for (int o = 4; o < 32; o <<= 1) {
            s0 += __shfl_xor_sync(0xffffffffu, s0, o);
            s1 += __shfl_xor_sync(0xffffffffu, s1, o);
        }
        if (lane < 4) {
            atomicAdd(&red[dl][wn * 32 + ni * 8 + 2 * lc],     s0);
            atomicAdd(&red[dl][wn * 32 + ni * 8 + 2 * lc + 1], s1);
        }
    }
    __syncthreads();
    if (tid < 128) {
        int dloc = tid >> 6, c = tid & 63;
        int col = n0 + c;
        if (col < N)
            fin[(long)(blockIdx.y * 2 + dloc) * H + col] = red[dloc][c] * (1.f / 64.f);
    }
}

// out[d,c]: one warp per output
__global__ void cls_kernel(const float* __restrict__ fin,
                           const float* __restrict__ Wc,
                           const float* __restrict__ bc,
                           float* __restrict__ out)
{
    int gw = blockIdx.x * (blockDim.x >> 5) + (threadIdx.x >> 5);
    int lane = threadIdx.x & 31;
    if (gw >= 128) return;
    int d = gw >> 1, c = gw & 1;
    const float* f = fin + d * H;
    const float* w = Wc + c * H;
    float p = 0.f;
    for (int h = lane; h < H; h += 32) p += f[h] * w[h];
    #pragma unroll
    for (int o = 16; o; o >>= 1) p += __shfl_xor_sync(0xffffffffu, p, o);
    if (lane == 0) out[d * 2 + c] = p + bc[c];
}

// =====================================================================
extern "C" void kernel_launch(void* const* d_in, const int* in_sizes, int n_in,
                              void* d_out, int out_size)
{
    const int*   word_indices = (const int*)  d_in[0];
    const float* E            = (const float*)d_in[1];
    const float* W_sent       = (const float*)d_in[2];
    const float* b_sent       = (const float*)d_in[3];
    const float* W_par        = (const float*)d_in[4];
    const float* b_par        = (const float*)d_in[5];
    const float* W_ch         = (const float*)d_in[6];
    const float* b_ch         = (const float*)d_in[7];
    const float* w_root       = (const float*)d_in[8];
    const float* b_root       = (const float*)d_in[9];
    const float* root_embed   = (const float*)d_in[10];
    const float* W_r          = (const float*)d_in[11];
    const float* b_r          = (const float*)d_in[12];
    const float* W_cls        = (const float*)d_in[13];
    const float* b_cls        = (const float*)d_in[14];

    float* out_ptr = (float*)d_out;
    float* A_ptr   = out_ptr + D * 2;
    float* fri_ptr = A_ptr + D * S * S;

    float *enc, *Pm, *Cm, *Y2, *G, *rs, *fin, *v2;
    cudaGetSymbolAddress((void**)&enc, g_enc);
    cudaGetSymbolAddress((void**)&Pm,  g_P);
    cudaGetSymbolAddress((void**)&Cm,  g_C);
    cudaGetSymbolAddress((void**)&Y2,  g_Y2);
    cudaGetSymbolAddress((void**)&G,   g_G);
    cudaGetSymbolAddress((void**)&rs,  g_rs);
    cudaGetSymbolAddress((void**)&fin, g_fin);
    cudaGetSymbolAddress((void**)&v2,  g_v2);

    cudaFuncSetAttribute(scores_kernel,
                         cudaFuncAttributeMaxDynamicSharedMemorySize, SCORES_SMEM);

    dim3 gEnc((H + BN - 1) / BN, NROWS / BM, 1);
    gemm_tf32_kernel<true><<<gEnc, 256>>>(
        E, word_indices + (L - 1), L,
        W_sent, b_sent, enc,
        nullptr, nullptr, nullptr,
        nullptr, nullptr, nullptr, H, W, W, W, W);

    // P, C (lrelu+bias) and Y2 = enc @ W2^T (linear; W2 rows inside W_r, ld=900)
    dim3 gPCY((H + BN - 1) / BN, NROWS / BM, 3);
    gemm_tf32_kernel<false><<<gPCY, 256>>>(
        enc, nullptr, 0,
        W_par,       b_par,   Pm,
        W_ch,        b_ch,    Cm,
        W_r + 300,   nullptr, Y2,
        H, H, H, H, 900);

    // scores + mask + column softmax -> A (in d_out)
    scores_kernel<<<dim3(4, D), 256, SCORES_SMEM>>>(Pm, Cm, A_ptr);

    // G = A^T @ Y2 per doc; also rs (x==0), fri (x==1), v2 slice (x==2)
    g_kernel<<<dim3(5, D), 256>>>(A_ptr, Y2, enc, w_root, b_root,
                                  W_r, root_embed, G, rs, fri_ptr, v2);

    ri_mean_kernel<<<dim3(5, 32), 256>>>(enc, W_r, b_r, G, rs, fri_ptr, v2, fin);

    cls_kernel<<<8, 512>>>(fin, W_cls, b_cls, out_ptr);
}

// round 15
// speedup vs baseline: 1.1920x; 1.0320x over previous
#include <cuda_runtime.h>

#define D 64
#define S 64
#define L 64
#define W 300
#define H 300
#define NROWS (D*S)          // 4096
#define NEGV (-9999999.0f)

// ---------------- device scratch (no allocation allowed) ----------------
__device__ float g_enc[NROWS * H];
__device__ float g_P  [NROWS * H];
__device__ float g_C  [NROWS * H];
__device__ float g_Y2 [NROWS * H];
__device__ float g_G  [NROWS * H];
__device__ float g_rs [NROWS];
__device__ float g_fin[D * H];
__device__ float g_v2 [H];

__device__ __forceinline__ float lrelu_f(float x) { return x > 0.f ? x : 0.01f * x; }

__device__ __forceinline__ unsigned f2tf32(float f) {
    unsigned u;
    asm("cvt.rna.tf32.f32 %0, %1;" : "=r"(u) : "f"(f));
    return u;
}
// round raw fp32 bits (stored in smem as unsigned) to tf32
__device__ __forceinline__ unsigned r2tf32(unsigned raw) {
    return f2tf32(__uint_as_float(raw));
}
__device__ __forceinline__ uint4 cvt4(float4 v) {
    return make_uint4(f2tf32(v.x), f2tf32(v.y), f2tf32(v.z), f2tf32(v.w));
}

__device__ __forceinline__ void mma8(float* c, const unsigned* a, const unsigned* b) {
    asm volatile(
        "mma.sync.aligned.m16n8k8.row.col.f32.tf32.tf32.f32 "
        "{%0,%1,%2,%3}, {%4,%5,%6,%7}, {%8,%9}, {%0,%1,%2,%3};"
        : "+f"(c[0]), "+f"(c[1]), "+f"(c[2]), "+f"(c[3])
        : "r"(a[0]), "r"(a[1]), "r"(a[2]), "r"(a[3]), "r"(b[0]), "r"(b[1]));
}

// cp.async 16B with zero-fill when srcsize==0
__device__ __forceinline__ void cp_async16(unsigned smem_addr, const void* gptr, int srcsize) {
    asm volatile("cp.async.ca.shared.global [%0], [%1], 16, %2;"
                 :: "r"(smem_addr), "l"(gptr), "r"(srcsize));
}
__device__ __forceinline__ void cp_commit() {
    asm volatile("cp.async.commit_group;");
}
template<int N>
__device__ __forceinline__ void cp_wait() {
    asm volatile("cp.async.wait_group %0;" :: "n"(N));
}

#define BM 128
#define BN 64
#define BK 16
#define BKP 20

// =====================================================================
// TF32 GEMM, cp.async depth-2 pipeline, rna tf32 at fragment read
// (R12-proven). Out[M,N] = act( A[M,K] @ B[N,K(ld=ldb)]^T + bias[N] ).
// z selects among 3 (B,bias,Out) triples; bias==nullptr => linear.
// =====================================================================
template<bool GATHER>
__global__ void gemm_tf32_kernel(
    const float* __restrict__ Abase, const int* __restrict__ idx, int idxStride,
    const float* __restrict__ B0, const float* __restrict__ bias0, float* __restrict__ Out0,
    const float* __restrict__ B1, const float* __restrict__ bias1, float* __restrict__ Out1,
    const float* __restrict__ B2, const float* __restrict__ bias2, float* __restrict__ Out2,
    int N, int K, int ldb0, int ldb1, int ldb2)
{
    const float* Bw   = B0;
    const float* bias = bias0;
    float*       Out  = Out0;
    int          ldb  = ldb0;
    if (blockIdx.z == 1) { Bw = B1; bias = bias1; Out = Out1; ldb = ldb1; }
    if (blockIdx.z == 2) { Bw = B2; bias = bias2; Out = Out2; ldb = ldb2; }
    const bool act = (bias != nullptr);

    __shared__ __align__(16) unsigned As[2][BM][BKP];
    __shared__ __align__(16) unsigned Bs[2][BN][BKP];

    const int tid  = threadIdx.x;
    const int lane = tid & 31;
    const int wid  = tid >> 5;
    const int wm   = wid >> 1;
    const int wn   = wid & 1;
    const int m0   = blockIdx.y * BM;
    const int n0   = blockIdx.x * BN;

    const int am0 = tid >> 2;
    const int ac  = (tid & 3) * 4;
    long aoff0, aoff1;
    if (GATHER) {
        aoff0 = (long)idx[(long)(m0 + am0) * idxStride] * K;
        aoff1 = (long)idx[(long)(m0 + am0 + 64) * idxStride] * K;
    } else {
        aoff0 = (long)(m0 + am0) * K;
        aoff1 = (long)(m0 + am0 + 64) * K;
    }
    const int  bn     = tid >> 2;
    const bool bvalid = (n0 + bn) < N;
    const long boff   = bvalid ? (long)(n0 + bn) * ldb : 0;

    unsigned sa0[2], sa1[2], sb[2];
    sa0[0] = (unsigned)__cvta_generic_to_shared(&As[0][am0][ac]);
    sa0[1] = (unsigned)__cvta_generic_to_shared(&As[1][am0][ac]);
    sa1[0] = (unsigned)__cvta_generic_to_shared(&As[0][am0 + 64][ac]);
    sa1[1] = (unsigned)__cvta_generic_to_shared(&As[1][am0 + 64][ac]);
    sb[0]  = (unsigned)__cvta_generic_to_shared(&Bs[0][bn][ac]);
    sb[1]  = (unsigned)__cvta_generic_to_shared(&Bs[1][bn][ac]);

    const int nIter = (K + BK - 1) / BK;

    {
        int k = ac;
        int szA = (k + 4 <= K) ? 16 : 0;
        int szB = (bvalid && k + 4 <= K) ? 16 : 0;
        cp_async16(sa0[0], Abase + aoff0 + k, szA);
        cp_async16(sa1[0], Abase + aoff1 + k, szA);
        cp_async16(sb[0],  Bw + boff + k,     szB);
    }
    cp_commit();

    float acc[2][4][4];
    #pragma unroll
    for (int i = 0; i < 2; i++)
        #pragma unroll
        for (int j = 0; j < 4; j++)
            #pragma unroll
            for (int q = 0; q < 4; q++) acc[i][j][q] = 0.f;

    const int lr = lane >> 2;
    const int lc = lane & 3;

    for (int it = 0; it < nIter; it++) {
        const int cur = it & 1;
        if (it + 1 < nIter) {
            int k = (it + 1) * BK + ac;
            int szA = (k + 4 <= K) ? 16 : 0;
            int szB = (bvalid && k + 4 <= K) ? 16 : 0;
            const float* pa0 = Abase + aoff0 + (szA ? k : 0);
            const float* pa1 = Abase + aoff1 + (szA ? k : 0);
            const float* pb  = Bw + boff + (szB ? k : 0);
            cp_async16(sa0[cur ^ 1], pa0, szA);
            cp_async16(sa1[cur ^ 1], pa1, szA);
            cp_async16(sb[cur ^ 1],  pb,  szB);
            cp_commit();
            cp_wait<1>();
        } else {
            cp_wait<0>();
        }
        __syncthreads();

        #pragma unroll
        for (int ks = 0; ks < 2; ks++) {
            const int kb = ks * 8;
            unsigned a[2][4], b[4][2];
            #pragma unroll
            for (int mi = 0; mi < 2; mi++) {
                int r = wm * 32 + mi * 16 + lr;
                a[mi][0] = r2tf32(As[cur][r][kb + lc]);
                a[mi][1] = r2tf32(As[cur][r + 8][kb + lc]);
                a[mi][2] = r2tf32(As[cur][r][kb + lc + 4]);
                a[mi][3] = r2tf32(As[cur][r + 8][kb + lc + 4]);
            }
            #pragma unroll
            for (int ni = 0; ni < 4; ni++) {
                int c = wn * 32 + ni * 8 + lr;
                b[ni][0] = r2tf32(Bs[cur][c][kb + lc]);
                b[ni][1] = r2tf32(Bs[cur][c][kb + lc + 4]);
            }
            #pragma unroll
            for (int mi = 0; mi < 2; mi++)
                #pragma unroll
                for (int ni = 0; ni < 4; ni++)
                    mma8(acc[mi][ni], a[mi], b[ni]);
        }
        __syncthreads();
    }

    #pragma unroll
    for (int mi = 0; mi < 2; mi++) {
        int r = m0 + wm * 32 + mi * 16 + lr;
        #pragma unroll
        for (int ni = 0; ni < 4; ni++) {
            int cb = n0 + wn * 32 + ni * 8 + 2 * lc;
            #pragma unroll
            for (int q = 0; q < 2; q++) {
                int cc = cb + q;
                if (cc >= N) continue;
                float bv = act ? bias[cc] : 0.f;
                float v0 = acc[mi][ni][q]     + bv;
                float v1 = acc[mi][ni][q + 2] + bv;
                if (act) { v0 = lrelu_f(v0); v1 = lrelu_f(v1); }
                Out[(long)r * N + cc]       = v0;
                Out[(long)(r + 8) * N + cc] = v1;
            }
        }
    }
}

// =====================================================================
// Scores + diag mask + column softmax, grid (4, D), 256 thr.
// cp.async raw loads, rna at fragment read (R14-proven).
// =====================================================================
#define SPAD 308
#define SCORES_SMEM ((80 * SPAD + 64 * 17) * 4)   // 102,912 B

__global__ void scores_kernel(const float* __restrict__ P,
                              const float* __restrict__ Cm,
                              float* __restrict__ A_out)
{
    extern __shared__ unsigned sdyn[];
    unsigned* Pt = sdyn;                       // [64][SPAD] raw fp32 bits
    unsigned* Ct = sdyn + 64 * SPAD;           // [16][SPAD] raw fp32 bits
    float*    Sh = (float*)(sdyn + 80 * SPAD); // [64][17]

    const int d  = blockIdx.y;
    const int j0 = blockIdx.x * 16;
    const int t = threadIdx.x;
    const int lane = t & 31;
    const int wid  = t >> 5;
    const int wm = wid >> 1;
    const int wn = wid & 1;
    const int lr = lane >> 2, lc = lane & 3;

    const float* Pd = P  + (long)d * S * H;
    const float* Cd = Cm + (long)d * S * H;

    for (int u = t; u < 64 * 76; u += 256) {
        int r = u / 76, c4 = u - r * 76;
        unsigned dst = (unsigned)__cvta_generic_to_shared(&Pt[r * SPAD + c4 * 4]);
        int sz = (c4 < 75) ? 16 : 0;
        cp_async16(dst, Pd + r * H + (sz ? c4 * 4 : 0), sz);
    }
    for (int u = t; u < 16 * 76; u += 256) {
        int r = u / 76, c4 = u - r * 76;
        unsigned dst = (unsigned)__cvta_generic_to_shared(&Ct[r * SPAD + c4 * 4]);
        int sz = (c4 < 75) ? 16 : 0;
        cp_async16(dst, Cd + (j0 + r) * H + (sz ? c4 * 4 : 0), sz);
    }
    cp_commit();
    cp_wait<0>();
    __syncthreads();

    float acc[4] = {};
    {
        const int r = wm * 16 + lr;
        const int c = wn * 8 + lr;
        #pragma unroll
        for (int ks = 0; ks < 38; ks++) {
            const int kb = ks * 8;
            unsigned a[4], b[2];
            a[0] = r2tf32(Pt[r * SPAD + kb + lc]);
            a[1] = r2tf32(Pt[(r + 8) * SPAD + kb + lc]);
            a[2] = r2tf32(Pt[r * SPAD + kb + lc + 4]);
            a[3] = r2tf32(Pt[(r + 8) * SPAD + kb + lc + 4]);
            b[0] = r2tf32(Ct[c * SPAD + kb + lc]);
            b[1] = r2tf32(Ct[c * SPAD + kb + lc + 4]);
            mma8(acc, a, b);
        }
    }

    {
        int r = wm * 16 + lr;
        int cb = wn * 8 + 2 * lc;
        int gc = j0 + cb;
        Sh[r * 17 + cb]           = (r == gc)         ? NEGV : acc[0];
        Sh[r * 17 + cb + 1]       = (r == gc + 1)     ? NEGV : acc[1];
        Sh[(r + 8) * 17 + cb]     = (r + 8 == gc)     ? NEGV : acc[2];
        Sh[(r + 8) * 17 + cb + 1] = (r + 8 == gc + 1) ? NEGV : acc[3];
    }
    __syncthreads();

    #pragma unroll
    for (int cc = 0; cc < 2; cc++) {
        int c = wid * 2 + cc;
        float v0 = Sh[lane * 17 + c];
        float v1 = Sh[(lane + 32) * 17 + c];
        float m = fmaxf(v0, v1);
        #pragma unroll
        for (int o = 16; o; o >>= 1) m = fmaxf(m, __shfl_xor_sync(0xffffffffu, m, o));
        float e0 = __expf(v0 - m), e1 = __expf(v1 - m);
        float s = e0 + e1;
        #pragma unroll
        for (int o = 16; o; o >>= 1) s += __shfl_xor_sync(0xffffffffu, s, o);
        float inv = 1.f / s;
        Sh[lane * 17 + c]        = e0 * inv;
        Sh[(lane + 32) * 17 + c] = e1 * inv;
    }
    __syncthreads();

    for (int u = t; u < 64 * 16; u += 256) {
        int i = u >> 4, j = u & 15;
        A_out[(long)d * 4096 + i * 64 + j0 + j] = Sh[i * 17 + j];
    }
}

// =====================================================================
// G[d,i,h] = sum_k A[d,k,i] * Y2[d*64+k, h]  (tf32 mma), grid (5, D).
// cp.async raw loads + rna at fragment read (R13-proven).
// Extras: x==0 -> rs, x==1 -> fri, x==2 -> v2.
// =====================================================================
#define GP 68

__global__ void g_kernel(const float* __restrict__ A_in,
                         const float* __restrict__ Y2,
                         const float* __restrict__ enc,
                         const float* __restrict__ w_root,
                         const float* __restrict__ b_root,
                         const float* __restrict__ W_r,
                         const float* __restrict__ root_embed,
                         float* __restrict__ G,
                         float* __restrict__ rs_out,
                         float* __restrict__ fri_out,
                         float* __restrict__ v2_out)
{
    const int d  = blockIdx.y;
    const int h0 = blockIdx.x * 64;
    const int t = threadIdx.x;
    const int lane = t & 31;
    const int wid  = t >> 5;
    const int wm = wid >> 1, wn = wid & 1;
    const int lr = lane >> 2, lc = lane & 3;

    __shared__ __align__(16) unsigned Ak[64][GP];
    __shared__ __align__(16) unsigned Ys[64][GP];
    __shared__ float sred[64];

    const float* Ad = A_in + (long)d * 4096;
    const float* Yd = Y2 + (long)d * 64 * H;
    const float* Ed = enc + (long)d * S * H;

    #pragma unroll
    for (int j = 0; j < 4; j++) {
        int u = t + 256 * j;
        int k = u >> 4, i = (u & 15) * 4;
        unsigned da = (unsigned)__cvta_generic_to_shared(&Ak[k][i]);
        cp_async16(da, Ad + k * 64 + i, 16);
        unsigned dy = (unsigned)__cvta_generic_to_shared(&Ys[k][i]);
        int h = h0 + i;
        int sz = (h + 4 <= H) ? 16 : 0;
        cp_async16(dy, Yd + (long)k * H + (sz ? h : 0), sz);
    }
    cp_commit();
    cp_wait<0>();
    __syncthreads();

    float acc[4][4] = {};
    #pragma unroll
    for (int ks = 0; ks < 8; ks++) {
        const int kb = ks * 8;
        unsigned a[4], b[4][2];
        int r = wm * 16 + lr;
        a[0] = r2tf32(Ak[kb + lc][r]);
        a[1] = r2tf32(Ak[kb + lc][r + 8]);
        a[2] = r2tf32(Ak[kb + lc + 4][r]);
        a[3] = r2tf32(Ak[kb + lc + 4][r + 8]);
        #pragma unroll
        for (int ni = 0; ni < 4; ni++) {
            int c = wn * 32 + ni * 8 + lr;
            b[ni][0] = r2tf32(Ys[kb + lc][c]);
            b[ni][1] = r2tf32(Ys[kb + lc + 4][c]);
        }
        #pragma unroll
        for (int ni = 0; ni < 4; ni++)
            mma8(acc[ni], a, b[ni]);
    }

    {
        int r = wm * 16 + lr;
        #pragma unroll
        for (int ni = 0; ni < 4; ni++) {
            int cb = wn * 32 + ni * 8 + 2 * lc;
            #pragma unroll
            for (int q = 0; q < 2; q++) {
                int h = h0 + cb + q;
                if (h >= H) continue;
                G[(long)(d * 64 + r) * H + h]     = acc[ni][q];
                G[(long)(d * 64 + r + 8) * H + h] = acc[ni][q + 2];
            }
        }
    }

    if (blockIdx.x == 0) {
        #pragma unroll
        for (int rr = 0; rr < 8; rr++) {
            int r = wid * 8 + rr;
            float s = Ad[r * 64 + lane] + Ad[r * 64 + lane + 32];
            #pragma unroll
            for (int o = 16; o; o >>= 1) s += __shfl_xor_sync(0xffffffffu, s, o);
            if (lane == 0) rs_out[d * 64 + r] = s;
        }
    } else if (blockIdx.x == 1) {
        const float br0 = b_root[0];
        #pragma unroll
        for (int ss = 0; ss < 8; ss++) {
            int s = wid * 8 + ss;
            const float* e = Ed + s * H;
            float p = 0.f;
            for (int h = lane; h < H; h += 32) p += e[h] * w_root[h];
            #pragma unroll
            for (int o = 16; o; o >>= 1) p += __shfl_xor_sync(0xffffffffu, p, o);
            if (lane == 0) sred[s] = p + br0;
        }
        __syncthreads();
        float mye = 0.f;
        if (t < 64) {
            float m = -1e30f;
            for (int u = 0; u < 64; u++) m = fmaxf(m, sred[u]);
            mye = __expf(sred[t] - m);
        }
        __syncthreads();
        if (t < 64) sred[t] = mye;
        __syncthreads();
        if (t < 64) {
            float ssum = 0.f;
            for (int u = 0; u < 64; u++) ssum += sred[u];
            fri_out[d * 64 + t] = mye / ssum;
        }
    } else if (blockIdx.x == 2) {
        if (wid < 5) {
            int n = d * 5 + wid;
            if (n < H) {
                const float* w = W_r + (long)n * 900 + 300;
                float p = 0.f;
                for (int k = lane; k < H; k += 32) p += w[k] * root_embed[k];
                #pragma unroll
                for (int o = 16; o; o >>= 1) p += __shfl_xor_sync(0xffffffffu, p, o);
                if (lane == 0) v2_out[n] = p;
            }
        }
    }
}

// =====================================================================
// ri+mean with cp.async depth-2 pipeline (recipe from gemm_tf32):
// fin[doc,n] = mean_s lrelu( enc@W1^T + rs*(enc@W3^T) + G + fri*v2 + b_r )
// =====================================================================
__global__ void ri_mean_kernel(const float* __restrict__ enc,
                               const float* __restrict__ W_r,   // [H, 900]
                               const float* __restrict__ b_r,
                               const float* __restrict__ G,
                               const float* __restrict__ rs,
                               const float* __restrict__ fri,
                               const float* __restrict__ v2,
                               float* __restrict__ fin)
{
    __shared__ __align__(16) unsigned As[2][BM][BKP];
    __shared__ __align__(16) unsigned B1s[2][BN][BKP];
    __shared__ __align__(16) unsigned B3s[2][BN][BKP];
    __shared__ float red[2][BN];

    const int K = H;
    const int N = H;
    const int tid  = threadIdx.x;
    const int lane = tid & 31;
    const int wid  = tid >> 5;
    const int wm = wid >> 1, wn = wid & 1;
    const int m0 = blockIdx.y * BM;
    const int n0 = blockIdx.x * BN;

    if (tid < 2 * BN) ((float*)red)[tid] = 0.f;

    const int am0 = tid >> 2;
    const int ac  = (tid & 3) * 4;
    const long aoff0 = (long)(m0 + am0) * K;
    const long aoff1 = (long)(m0 + am0 + 64) * K;
    const int  bn     = tid >> 2;
    const bool bvalid = (n0 + bn) < N;
    const long boff   = bvalid ? (long)(n0 + bn) * 900 : 0;

    unsigned sa0[2], sa1[2], sb1[2], sb3[2];
    sa0[0] = (unsigned)__cvta_generic_to_shared(&As[0][am0][ac]);
    sa0[1] = (unsigned)__cvta_generic_to_shared(&As[1][am0][ac]);
    sa1[0] = (unsigned)__cvta_generic_to_shared(&As[0][am0 + 64][ac]);
    sa1[1] = (unsigned)__cvta_generic_to_shared(&As[1][am0 + 64][ac]);
    sb1[0] = (unsigned)__cvta_generic_to_shared(&B1s[0][bn][ac]);
    sb1[1] = (unsigned)__cvta_generic_to_shared(&B1s[1][bn][ac]);
    sb3[0] = (unsigned)__cvta_generic_to_shared(&B3s[0][bn][ac]);
    sb3[1] = (unsigned)__cvta_generic_to_shared(&B3s[1][bn][ac]);

    const int nIter = (K + BK - 1) / BK;

    {
        int k = ac;
        int szA = (k + 4 <= K) ? 16 : 0;
        int szB = (bvalid && k + 4 <= K) ? 16 : 0;
        cp_async16(sa0[0], enc + aoff0 + k, szA);
        cp_async16(sa1[0], enc + aoff1 + k, szA);
        cp_async16(sb1[0], W_r + boff + k,        szB);
        cp_async16(sb3[0], W_r + boff + 600 + k,  szB);
    }
    cp_commit();

    float acc1[2][4][4], acc3[2][4][4];
    #pragma unroll
    for (int i = 0; i < 2; i++)
        #pragma unroll
        for (int j = 0; j < 4; j++)
            #pragma unroll
            for (int q = 0; q < 4; q++) { acc1[i][j][q] = 0.f; acc3[i][j][q] = 0.f; }

    const int lr = lane >> 2, lc = lane & 3;

    for (int it = 0; it < nIter; it++) {
        const int cur = it & 1;
        if (it + 1 < nIter) {
            int k = (it + 1) * BK + ac;
            int szA = (k + 4 <= K) ? 16 : 0;
            int szB = (bvalid && k + 4 <= K) ? 16 : 0;
            const float* pa0 = enc + aoff0 + (szA ? k : 0);
            const float* pa1 = enc + aoff1 + (szA ? k : 0);
            const float* pb1 = W_r + boff + (szB ? k : 0);
            const float* pb3 = W_r + boff + 600 + (szB ? k : 0);
            cp_async16(sa0[cur ^ 1], pa0, szA);
            cp_async16(sa1[cur ^ 1], pa1, szA);
            cp_async16(sb1[cur ^ 1], pb1, szB);
            cp_async16(sb3[cur ^ 1], pb3, szB);
            cp_commit();
            cp_wait<1>();
        } else {
            cp_wait<0>();
        }
        __syncthreads();

        #pragma unroll
        for (int ks = 0; ks < 2; ks++) {
            const int kb = ks * 8;
            unsigned a[2][4], b1[4][2], b3[4][2];
            #pragma unroll
            for (int mi = 0; mi < 2; mi++) {
                int r = wm * 32 + mi * 16 + lr;
                a[mi][0] = r2tf32(As[cur][r][kb + lc]);
                a[mi][1] = r2tf32(As[cur][r + 8][kb + lc]);
                a[mi][2] = r2tf32(As[cur][r][kb + lc + 4]);
                a[mi][3] = r2tf32(As[cur][r + 8][kb + lc + 4]);
            }
            #pragma unroll
            for (int ni = 0; ni < 4; ni++) {
                int c = wn * 32 + ni * 8 + lr;
                b1[ni][0] = r2tf32(B1s[cur][c][kb + lc]);
                b1[ni][1] = r2tf32(B1s[cur][c][kb + lc + 4]);
                b3[ni][0] = r2tf32(B3s[cur][c][kb + lc]);
                b3[ni][1] = r2tf32(B3s[cur][c][kb + lc + 4]);
            }
            #pragma unroll
            for (int mi = 0; mi < 2; mi++)
                #pragma unroll
                for (int ni = 0; ni < 4; ni++) {
                    mma8(acc1[mi][ni], a[mi], b1[ni]);
                    mma8(acc3[mi][ni], a[mi], b3[ni]);
                }
        }
        __syncthreads();
    }

    const int dl = wm >> 1;
    #pragma unroll
    for (int ni = 0; ni < 4; ni++) {
        int cb = n0 + wn * 32 + ni * 8 + 2 * lc;
        float s0 = 0.f, s1 = 0.f;
        #pragma unroll
        for (int mi = 0; mi < 2; mi++) {
            int r = m0 + wm * 32 + mi * 16 + lr;
            #pragma unroll
            for (int half = 0; half < 2; half++) {
                int m = r + half * 8;
                float rsm = rs[m], frm = fri[m];
                if (cb < N) {
                    float v = acc1[mi][ni][half * 2] + rsm * acc3[mi][ni][half * 2]
                            + G[(long)m * H + cb] + frm * v2[cb] + b_r[cb];
                    s0 += lrelu_f(v);
                }
                if (cb + 1 < N) {
                    float v = acc1[mi][ni][half * 2 + 1] + rsm * acc3[mi][ni][half * 2 + 1]
                            + G[(long)m * H + cb + 1] + frm * v2[cb + 1] + b_r[cb + 1];
                    s1 += lrelu_f(v);
                }
            }
        }
        #pragma unroll
        for (int o = 4; o < 32; o <<= 1) {
            s0 += __shfl_xor_sync(0xffffffffu, s0, o);
            s1 += __shfl_xor_sync(0xffffffffu, s1, o);
        }
        if (lane < 4) {
            atomicAdd(&red[dl][wn * 32 + ni * 8 + 2 * lc],     s0);
            atomicAdd(&red[dl][wn * 32 + ni * 8 + 2 * lc + 1], s1);
        }
    }
    __syncthreads();
    if (tid < 128) {
        int dloc = tid >> 6, c = tid & 63;
        int col = n0 + c;
        if (col < N)
            fin[(long)(blockIdx.y * 2 + dloc) * H + col] = red[dloc][c] * (1.f / 64.f);
    }
}

// out[d,c]: one warp per output
__global__ void cls_kernel(const float* __restrict__ fin,
                           const float* __restrict__ Wc,
                           const float* __restrict__ bc,
                           float* __restrict__ out)
{
    int gw = blockIdx.x * (blockDim.x >> 5) + (threadIdx.x >> 5);
    int lane = threadIdx.x & 31;
    if (gw >= 128) return;
    int d = gw >> 1, c = gw & 1;
    const float* f = fin + d * H;
    const float* w = Wc + c * H;
    float p = 0.f;
    for (int h = lane; h < H; h += 32) p += f[h] * w[h];
    #pragma unroll
    for (int o = 16; o; o >>= 1) p += __shfl_xor_sync(0xffffffffu, p, o);
    if (lane == 0) out[d * 2 + c] = p + bc[c];
}

// =====================================================================
extern "C" void kernel_launch(void* const* d_in, const int* in_sizes, int n_in,
                              void* d_out, int out_size)
{
    const int*   word_indices = (const int*)  d_in[0];
    const float* E            = (const float*)d_in[1];
    const float* W_sent       = (const float*)d_in[2];
    const float* b_sent       = (const float*)d_in[3];
    const float* W_par        = (const float*)d_in[4];
    const float* b_par        = (const float*)d_in[5];
    const float* W_ch         = (const float*)d_in[6];
    const float* b_ch         = (const float*)d_in[7];
    const float* w_root       = (const float*)d_in[8];
    const float* b_root       = (const float*)d_in[9];
    const float* root_embed   = (const float*)d_in[10];
    const float* W_r          = (const float*)d_in[11];
    const float* b_r          = (const float*)d_in[12];
    const float* W_cls        = (const float*)d_in[13];
    const float* b_cls        = (const float*)d_in[14];

    float* out_ptr = (float*)d_out;
    float* A_ptr   = out_ptr + D * 2;
    float* fri_ptr = A_ptr + D * S * S;

    float *enc, *Pm, *Cm, *Y2, *G, *rs, *fin, *v2;
    cudaGetSymbolAddress((void**)&enc, g_enc);
    cudaGetSymbolAddress((void**)&Pm,  g_P);
    cudaGetSymbolAddress((void**)&Cm,  g_C);
    cudaGetSymbolAddress((void**)&Y2,  g_Y2);
    cudaGetSymbolAddress((void**)&G,   g_G);
    cudaGetSymbolAddress((void**)&rs,  g_rs);
    cudaGetSymbolAddress((void**)&fin, g_fin);
    cudaGetSymbolAddress((void**)&v2,  g_v2);

    cudaFuncSetAttribute(scores_kernel,
                         cudaFuncAttributeMaxDynamicSharedMemorySize, SCORES_SMEM);

    dim3 gEnc((H + BN - 1) / BN, NROWS / BM, 1);
    gemm_tf32_kernel<true><<<gEnc, 256>>>(
        E, word_indices + (L - 1), L,
        W_sent, b_sent, enc,
        nullptr, nullptr, nullptr,
        nullptr, nullptr, nullptr, H, W, W, W, W);

    // P, C (lrelu+bias) and Y2 = enc @ W2^T (linear; W2 rows inside W_r, ld=900)
    dim3 gPCY((H + BN - 1) / BN, NROWS / BM, 3);
    gemm_tf32_kernel<false><<<gPCY, 256>>>(
        enc, nullptr, 0,
        W_par,       b_par,   Pm,
        W_ch,        b_ch,    Cm,
        W_r + 300,   nullptr, Y2,
        H, H, H, H, 900);

    // scores + mask + column softmax -> A (in d_out)
    scores_kernel<<<dim3(4, D), 256, SCORES_SMEM>>>(Pm, Cm, A_ptr);

    // G = A^T @ Y2 per doc; also rs (x==0), fri (x==1), v2 slice (x==2)
    g_kernel<<<dim3(5, D), 256>>>(A_ptr, Y2, enc, w_root, b_root,
                                  W_r, root_embed, G, rs, fri_ptr, v2);

    ri_mean_kernel<<<dim3(5, 32), 256>>>(enc, W_r, b_r, G, rs, fri_ptr, v2, fin);

    cls_kernel<<<8, 512>>>(fin, W_cls, b_cls, out_ptr);
}

// round 16
// speedup vs baseline: 1.2356x; 1.0366x over previous
#include <cuda_runtime.h>

#define D 64
#define S 64
#define L 64
#define W 300
#define H 300
#define NROWS (D*S)          // 4096
#define NEGV (-9999999.0f)

// ---------------- device scratch (no allocation allowed) ----------------
__device__ float g_enc[NROWS * H];
__device__ float g_P  [NROWS * H];
__device__ float g_C  [NROWS * H];
__device__ float g_Y2 [NROWS * H];
__device__ float g_G  [NROWS * H];
__device__ float g_rs [NROWS];
__device__ float g_v2 [H];

__device__ __forceinline__ float lrelu_f(float x) { return x > 0.f ? x : 0.01f * x; }

__device__ __forceinline__ unsigned f2tf32(float f) {
    unsigned u;
    asm("cvt.rna.tf32.f32 %0, %1;" : "=r"(u) : "f"(f));
    return u;
}
// round raw fp32 bits (stored in smem as unsigned) to tf32
__device__ __forceinline__ unsigned r2tf32(unsigned raw) {
    return f2tf32(__uint_as_float(raw));
}

__device__ __forceinline__ void mma8(float* c, const unsigned* a, const unsigned* b) {
    asm volatile(
        "mma.sync.aligned.m16n8k8.row.col.f32.tf32.tf32.f32 "
        "{%0,%1,%2,%3}, {%4,%5,%6,%7}, {%8,%9}, {%0,%1,%2,%3};"
        : "+f"(c[0]), "+f"(c[1]), "+f"(c[2]), "+f"(c[3])
        : "r"(a[0]), "r"(a[1]), "r"(a[2]), "r"(a[3]), "r"(b[0]), "r"(b[1]));
}

// cp.async 16B with zero-fill when srcsize==0
__device__ __forceinline__ void cp_async16(unsigned smem_addr, const void* gptr, int srcsize) {
    asm volatile("cp.async.ca.shared.global [%0], [%1], 16, %2;"
                 :: "r"(smem_addr), "l"(gptr), "r"(srcsize));
}
__device__ __forceinline__ void cp_commit() {
    asm volatile("cp.async.commit_group;");
}
template<int N>
__device__ __forceinline__ void cp_wait() {
    asm volatile("cp.async.wait_group %0;" :: "n"(N));
}

#define BM 128
#define BN 64
#define BK 16
#define BKP 20

// =====================================================================
// TF32 GEMM, cp.async depth-2 pipeline, rna tf32 at fragment read
// (R12-proven). Out[M,N] = act( A[M,K] @ B[N,K(ld=ldb)]^T + bias[N] ).
// z selects among 3 (B,bias,Out) triples; bias==nullptr => linear.
// =====================================================================
template<bool GATHER>
__global__ void gemm_tf32_kernel(
    const float* __restrict__ Abase, const int* __restrict__ idx, int idxStride,
    const float* __restrict__ B0, const float* __restrict__ bias0, float* __restrict__ Out0,
    const float* __restrict__ B1, const float* __restrict__ bias1, float* __restrict__ Out1,
    const float* __restrict__ B2, const float* __restrict__ bias2, float* __restrict__ Out2,
    int N, int K, int ldb0, int ldb1, int ldb2)
{
    const float* Bw   = B0;
    const float* bias = bias0;
    float*       Out  = Out0;
    int          ldb  = ldb0;
    if (blockIdx.z == 1) { Bw = B1; bias = bias1; Out = Out1; ldb = ldb1; }
    if (blockIdx.z == 2) { Bw = B2; bias = bias2; Out = Out2; ldb = ldb2; }
    const bool act = (bias != nullptr);

    __shared__ __align__(16) unsigned As[2][BM][BKP];
    __shared__ __align__(16) unsigned Bs[2][BN][BKP];

    const int tid  = threadIdx.x;
    const int lane = tid & 31;
    const int wid  = tid >> 5;
    const int wm   = wid >> 1;
    const int wn   = wid & 1;
    const int m0   = blockIdx.y * BM;
    const int n0   = blockIdx.x * BN;

    const int am0 = tid >> 2;
    const int ac  = (tid & 3) * 4;
    long aoff0, aoff1;
    if (GATHER) {
        aoff0 = (long)idx[(long)(m0 + am0) * idxStride] * K;
        aoff1 = (long)idx[(long)(m0 + am0 + 64) * idxStride] * K;
    } else {
        aoff0 = (long)(m0 + am0) * K;
        aoff1 = (long)(m0 + am0 + 64) * K;
    }
    const int  bn     = tid >> 2;
    const bool bvalid = (n0 + bn) < N;
    const long boff   = bvalid ? (long)(n0 + bn) * ldb : 0;

    unsigned sa0[2], sa1[2], sb[2];
    sa0[0] = (unsigned)__cvta_generic_to_shared(&As[0][am0][ac]);
    sa0[1] = (unsigned)__cvta_generic_to_shared(&As[1][am0][ac]);
    sa1[0] = (unsigned)__cvta_generic_to_shared(&As[0][am0 + 64][ac]);
    sa1[1] = (unsigned)__cvta_generic_to_shared(&As[1][am0 + 64][ac]);
    sb[0]  = (unsigned)__cvta_generic_to_shared(&Bs[0][bn][ac]);
    sb[1]  = (unsigned)__cvta_generic_to_shared(&Bs[1][bn][ac]);

    const int nIter = (K + BK - 1) / BK;

    {
        int k = ac;
        int szA = (k + 4 <= K) ? 16 : 0;
        int szB = (bvalid && k + 4 <= K) ? 16 : 0;
        cp_async16(sa0[0], Abase + aoff0 + k, szA);
        cp_async16(sa1[0], Abase + aoff1 + k, szA);
        cp_async16(sb[0],  Bw + boff + k,     szB);
    }
    cp_commit();

    float acc[2][4][4];
    #pragma unroll
    for (int i = 0; i < 2; i++)
        #pragma unroll
        for (int j = 0; j < 4; j++)
            #pragma unroll
            for (int q = 0; q < 4; q++) acc[i][j][q] = 0.f;

    const int lr = lane >> 2;
    const int lc = lane & 3;

    for (int it = 0; it < nIter; it++) {
        const int cur = it & 1;
        if (it + 1 < nIter) {
            int k = (it + 1) * BK + ac;
            int szA = (k + 4 <= K) ? 16 : 0;
            int szB = (bvalid && k + 4 <= K) ? 16 : 0;
            const float* pa0 = Abase + aoff0 + (szA ? k : 0);
            const float* pa1 = Abase + aoff1 + (szA ? k : 0);
            const float* pb  = Bw + boff + (szB ? k : 0);
            cp_async16(sa0[cur ^ 1], pa0, szA);
            cp_async16(sa1[cur ^ 1], pa1, szA);
            cp_async16(sb[cur ^ 1],  pb,  szB);
            cp_commit();
            cp_wait<1>();
        } else {
            cp_wait<0>();
        }
        __syncthreads();

        #pragma unroll
        for (int ks = 0; ks < 2; ks++) {
            const int kb = ks * 8;
            unsigned a[2][4], b[4][2];
            #pragma unroll
            for (int mi = 0; mi < 2; mi++) {
                int r = wm * 32 + mi * 16 + lr;
                a[mi][0] = r2tf32(As[cur][r][kb + lc]);
                a[mi][1] = r2tf32(As[cur][r + 8][kb + lc]);
                a[mi][2] = r2tf32(As[cur][r][kb + lc + 4]);
                a[mi][3] = r2tf32(As[cur][r + 8][kb + lc + 4]);
            }
            #pragma unroll
            for (int ni = 0; ni < 4; ni++) {
                int c = wn * 32 + ni * 8 + lr;
                b[ni][0] = r2tf32(Bs[cur][c][kb + lc]);
                b[ni][1] = r2tf32(Bs[cur][c][kb + lc + 4]);
            }
            #pragma unroll
            for (int mi = 0; mi < 2; mi++)
                #pragma unroll
                for (int ni = 0; ni < 4; ni++)
                    mma8(acc[mi][ni], a[mi], b[ni]);
        }
        __syncthreads();
    }

    #pragma unroll
    for (int mi = 0; mi < 2; mi++) {
        int r = m0 + wm * 32 + mi * 16 + lr;
        #pragma unroll
        for (int ni = 0; ni < 4; ni++) {
            int cb = n0 + wn * 32 + ni * 8 + 2 * lc;
            #pragma unroll
            for (int q = 0; q < 2; q++) {
                int cc = cb + q;
                if (cc >= N) continue;
                float bv = act ? bias[cc] : 0.f;
                float v0 = acc[mi][ni][q]     + bv;
                float v1 = acc[mi][ni][q + 2] + bv;
                if (act) { v0 = lrelu_f(v0); v1 = lrelu_f(v1); }
                Out[(long)r * N + cc]       = v0;
                Out[(long)(r + 8) * N + cc] = v1;
            }
        }
    }
}

// =====================================================================
// Scores + diag mask + column softmax, grid (4, D), 256 thr.
// cp.async raw loads, rna at fragment read (R14-proven).
// =====================================================================
#define SPAD 308
#define SCORES_SMEM ((80 * SPAD + 64 * 17) * 4)   // 102,912 B

__global__ void scores_kernel(const float* __restrict__ P,
                              const float* __restrict__ Cm,
                              float* __restrict__ A_out)
{
    extern __shared__ unsigned sdyn[];
    unsigned* Pt = sdyn;                       // [64][SPAD] raw fp32 bits
    unsigned* Ct = sdyn + 64 * SPAD;           // [16][SPAD] raw fp32 bits
    float*    Sh = (float*)(sdyn + 80 * SPAD); // [64][17]

    const int d  = blockIdx.y;
    const int j0 = blockIdx.x * 16;
    const int t = threadIdx.x;
    const int lane = t & 31;
    const int wid  = t >> 5;
    const int wm = wid >> 1;
    const int wn = wid & 1;
    const int lr = lane >> 2, lc = lane & 3;

    const float* Pd = P  + (long)d * S * H;
    const float* Cd = Cm + (long)d * S * H;

    for (int u = t; u < 64 * 76; u += 256) {
        int r = u / 76, c4 = u - r * 76;
        unsigned dst = (unsigned)__cvta_generic_to_shared(&Pt[r * SPAD + c4 * 4]);
        int sz = (c4 < 75) ? 16 : 0;
        cp_async16(dst, Pd + r * H + (sz ? c4 * 4 : 0), sz);
    }
    for (int u = t; u < 16 * 76; u += 256) {
        int r = u / 76, c4 = u - r * 76;
        unsigned dst = (unsigned)__cvta_generic_to_shared(&Ct[r * SPAD + c4 * 4]);
        int sz = (c4 < 75) ? 16 : 0;
        cp_async16(dst, Cd + (j0 + r) * H + (sz ? c4 * 4 : 0), sz);
    }
    cp_commit();
    cp_wait<0>();
    __syncthreads();

    float acc[4] = {};
    {
        const int r = wm * 16 + lr;
        const int c = wn * 8 + lr;
        #pragma unroll
        for (int ks = 0; ks < 38; ks++) {
            const int kb = ks * 8;
            unsigned a[4], b[2];
            a[0] = r2tf32(Pt[r * SPAD + kb + lc]);
            a[1] = r2tf32(Pt[(r + 8) * SPAD + kb + lc]);
            a[2] = r2tf32(Pt[r * SPAD + kb + lc + 4]);
            a[3] = r2tf32(Pt[(r + 8) * SPAD + kb + lc + 4]);
            b[0] = r2tf32(Ct[c * SPAD + kb + lc]);
            b[1] = r2tf32(Ct[c * SPAD + kb + lc + 4]);
            mma8(acc, a, b);
        }
    }

    {
        int r = wm * 16 + lr;
        int cb = wn * 8 + 2 * lc;
        int gc = j0 + cb;
        Sh[r * 17 + cb]           = (r == gc)         ? NEGV : acc[0];
        Sh[r * 17 + cb + 1]       = (r == gc + 1)     ? NEGV : acc[1];
        Sh[(r + 8) * 17 + cb]     = (r + 8 == gc)     ? NEGV : acc[2];
        Sh[(r + 8) * 17 + cb + 1] = (r + 8 == gc + 1) ? NEGV : acc[3];
    }
    __syncthreads();

    #pragma unroll
    for (int cc = 0; cc < 2; cc++) {
        int c = wid * 2 + cc;
        float v0 = Sh[lane * 17 + c];
        float v1 = Sh[(lane + 32) * 17 + c];
        float m = fmaxf(v0, v1);
        #pragma unroll
        for (int o = 16; o; o >>= 1) m = fmaxf(m, __shfl_xor_sync(0xffffffffu, m, o));
        float e0 = __expf(v0 - m), e1 = __expf(v1 - m);
        float s = e0 + e1;
        #pragma unroll
        for (int o = 16; o; o >>= 1) s += __shfl_xor_sync(0xffffffffu, s, o);
        float inv = 1.f / s;
        Sh[lane * 17 + c]        = e0 * inv;
        Sh[(lane + 32) * 17 + c] = e1 * inv;
    }
    __syncthreads();

    for (int u = t; u < 64 * 16; u += 256) {
        int i = u >> 4, j = u & 15;
        A_out[(long)d * 4096 + i * 64 + j0 + j] = Sh[i * 17 + j];
    }
}

// =====================================================================
// G[d,i,h] = sum_k A[d,k,i] * Y2[d*64+k, h]  (tf32 mma), grid (5, D).
// cp.async raw loads + rna at fragment read (R13-proven).
// Extras: x==0 -> rs, x==1 -> fri, x==2 -> v2, x==3 (d==0) -> zero out.
// =====================================================================
#define GP 68

__global__ void g_kernel(const float* __restrict__ A_in,
                         const float* __restrict__ Y2,
                         const float* __restrict__ enc,
                         const float* __restrict__ w_root,
                         const float* __restrict__ b_root,
                         const float* __restrict__ W_r,
                         const float* __restrict__ root_embed,
                         float* __restrict__ G,
                         float* __restrict__ rs_out,
                         float* __restrict__ fri_out,
                         float* __restrict__ v2_out,
                         float* __restrict__ out_logits)
{
    const int d  = blockIdx.y;
    const int h0 = blockIdx.x * 64;
    const int t = threadIdx.x;
    const int lane = t & 31;
    const int wid  = t >> 5;
    const int wm = wid >> 1, wn = wid & 1;
    const int lr = lane >> 2, lc = lane & 3;

    __shared__ __align__(16) unsigned Ak[64][GP];
    __shared__ __align__(16) unsigned Ys[64][GP];
    __shared__ float sred[64];

    const float* Ad = A_in + (long)d * 4096;
    const float* Yd = Y2 + (long)d * 64 * H;
    const float* Ed = enc + (long)d * S * H;

    #pragma unroll
    for (int j = 0; j < 4; j++) {
        int u = t + 256 * j;
        int k = u >> 4, i = (u & 15) * 4;
        unsigned da = (unsigned)__cvta_generic_to_shared(&Ak[k][i]);
        cp_async16(da, Ad + k * 64 + i, 16);
        unsigned dy = (unsigned)__cvta_generic_to_shared(&Ys[k][i]);
        int h = h0 + i;
        int sz = (h + 4 <= H) ? 16 : 0;
        cp_async16(dy, Yd + (long)k * H + (sz ? h : 0), sz);
    }
    cp_commit();
    cp_wait<0>();
    __syncthreads();

    float acc[4][4] = {};
    #pragma unroll
    for (int ks = 0; ks < 8; ks++) {
        const int kb = ks * 8;
        unsigned a[4], b[4][2];
        int r = wm * 16 + lr;
        a[0] = r2tf32(Ak[kb + lc][r]);
        a[1] = r2tf32(Ak[kb + lc][r + 8]);
        a[2] = r2tf32(Ak[kb + lc + 4][r]);
        a[3] = r2tf32(Ak[kb + lc + 4][r + 8]);
        #pragma unroll
        for (int ni = 0; ni < 4; ni++) {
            int c = wn * 32 + ni * 8 + lr;
            b[ni][0] = r2tf32(Ys[kb + lc][c]);
            b[ni][1] = r2tf32(Ys[kb + lc + 4][c]);
        }
        #pragma unroll
        for (int ni = 0; ni < 4; ni++)
            mma8(acc[ni], a, b[ni]);
    }

    {
        int r = wm * 16 + lr;
        #pragma unroll
        for (int ni = 0; ni < 4; ni++) {
            int cb = wn * 32 + ni * 8 + 2 * lc;
            #pragma unroll
            for (int q = 0; q < 2; q++) {
                int h = h0 + cb + q;
                if (h >= H) continue;
                G[(long)(d * 64 + r) * H + h]     = acc[ni][q];
                G[(long)(d * 64 + r + 8) * H + h] = acc[ni][q + 2];
            }
        }
    }

    if (blockIdx.x == 0) {
        #pragma unroll
        for (int rr = 0; rr < 8; rr++) {
            int r = wid * 8 + rr;
            float s = Ad[r * 64 + lane] + Ad[r * 64 + lane + 32];
            #pragma unroll
            for (int o = 16; o; o >>= 1) s += __shfl_xor_sync(0xffffffffu, s, o);
            if (lane == 0) rs_out[d * 64 + r] = s;
        }
    } else if (blockIdx.x == 1) {
        const float br0 = b_root[0];
        #pragma unroll
        for (int ss = 0; ss < 8; ss++) {
            int s = wid * 8 + ss;
            const float* e = Ed + s * H;
            float p = 0.f;
            for (int h = lane; h < H; h += 32) p += e[h] * w_root[h];
            #pragma unroll
            for (int o = 16; o; o >>= 1) p += __shfl_xor_sync(0xffffffffu, p, o);
            if (lane == 0) sred[s] = p + br0;
        }
        __syncthreads();
        float mye = 0.f;
        if (t < 64) {
            float m = -1e30f;
            for (int u = 0; u < 64; u++) m = fmaxf(m, sred[u]);
            mye = __expf(sred[t] - m);
        }
        __syncthreads();
        if (t < 64) sred[t] = mye;
        __syncthreads();
        if (t < 64) {
            float ssum = 0.f;
            for (int u = 0; u < 64; u++) ssum += sred[u];
            fri_out[d * 64 + t] = mye / ssum;
        }
    } else if (blockIdx.x == 2) {
        if (wid < 5) {
            int n = d * 5 + wid;
            if (n < H) {
                const float* w = W_r + (long)n * 900 + 300;
                float p = 0.f;
                for (int k = lane; k < H; k += 32) p += w[k] * root_embed[k];
                #pragma unroll
                for (int o = 16; o; o >>= 1) p += __shfl_xor_sync(0xffffffffu, p, o);
                if (lane == 0) v2_out[n] = p;
            }
        }
    } else if (blockIdx.x == 3) {
        // zero the output logits (poisoned by harness); ri_mean atomicAdds later
        if (d == 0 && t < D * 2) out_logits[t] = 0.f;
    }
}

// =====================================================================
// ri+mean+classifier, cp.async depth-2 pipeline:
//   fin[doc,n] = mean_s lrelu( enc@W1^T + rs*(enc@W3^T) + G + fri*v2 + b_r )
//   out[doc,c] += sum over this block's 64 cols of fin*W_cls[c]  (atomic)
//   (bias b_cls added once by the n0==0 block)
// =====================================================================
__global__ void ri_mean_kernel(const float* __restrict__ enc,
                               const float* __restrict__ W_r,   // [H, 900]
                               const float* __restrict__ b_r,
                               const float* __restrict__ G,
                               const float* __restrict__ rs,
                               const float* __restrict__ fri,
                               const float* __restrict__ v2,
                               const float* __restrict__ W_cls, // [2, H]
                               const float* __restrict__ b_cls, // [2]
                               float* __restrict__ out)         // [D, 2]
{
    __shared__ __align__(16) unsigned As[2][BM][BKP];
    __shared__ __align__(16) unsigned B1s[2][BN][BKP];
    __shared__ __align__(16) unsigned B3s[2][BN][BKP];
    __shared__ float red[2][BN];
    __shared__ float outred[4][2];   // [warp<4][class]

    const int K = H;
    const int N = H;
    const int tid  = threadIdx.x;
    const int lane = tid & 31;
    const int wid  = tid >> 5;
    const int wm = wid >> 1, wn = wid & 1;
    const int m0 = blockIdx.y * BM;
    const int n0 = blockIdx.x * BN;

    if (tid < 2 * BN) ((float*)red)[tid] = 0.f;

    const int am0 = tid >> 2;
    const int ac  = (tid & 3) * 4;
    const long aoff0 = (long)(m0 + am0) * K;
    const long aoff1 = (long)(m0 + am0 + 64) * K;
    const int  bn     = tid >> 2;
    const bool bvalid = (n0 + bn) < N;
    const long boff   = bvalid ? (long)(n0 + bn) * 900 : 0;

    unsigned sa0[2], sa1[2], sb1[2], sb3[2];
    sa0[0] = (unsigned)__cvta_generic_to_shared(&As[0][am0][ac]);
    sa0[1] = (unsigned)__cvta_generic_to_shared(&As[1][am0][ac]);
    sa1[0] = (unsigned)__cvta_generic_to_shared(&As[0][am0 + 64][ac]);
    sa1[1] = (unsigned)__cvta_generic_to_shared(&As[1][am0 + 64][ac]);
    sb1[0] = (unsigned)__cvta_generic_to_shared(&B1s[0][bn][ac]);
    sb1[1] = (unsigned)__cvta_generic_to_shared(&B1s[1][bn][ac]);
    sb3[0] = (unsigned)__cvta_generic_to_shared(&B3s[0][bn][ac]);
    sb3[1] = (unsigned)__cvta_generic_to_shared(&B3s[1][bn][ac]);

    const int nIter = (K + BK - 1) / BK;

    {
        int k = ac;
        int szA = (k + 4 <= K) ? 16 : 0;
        int szB = (bvalid && k + 4 <= K) ? 16 : 0;
        cp_async16(sa0[0], enc + aoff0 + k, szA);
        cp_async16(sa1[0], enc + aoff1 + k, szA);
        cp_async16(sb1[0], W_r + boff + k,        szB);
        cp_async16(sb3[0], W_r + boff + 600 + k,  szB);
    }
    cp_commit();

    float acc1[2][4][4], acc3[2][4][4];
    #pragma unroll
    for (int i = 0; i < 2; i++)
        #pragma unroll
        for (int j = 0; j < 4; j++)
            #pragma unroll
            for (int q = 0; q < 4; q++) { acc1[i][j][q] = 0.f; acc3[i][j][q] = 0.f; }

    const int lr = lane >> 2, lc = lane & 3;

    for (int it = 0; it < nIter; it++) {
        const int cur = it & 1;
        if (it + 1 < nIter) {
            int k = (it + 1) * BK + ac;
            int szA = (k + 4 <= K) ? 16 : 0;
            int szB = (bvalid && k + 4 <= K) ? 16 : 0;
            const float* pa0 = enc + aoff0 + (szA ? k : 0);
            const float* pa1 = enc + aoff1 + (szA ? k : 0);
            const float* pb1 = W_r + boff + (szB ? k : 0);
            const float* pb3 = W_r + boff + 600 + (szB ? k : 0);
            cp_async16(sa0[cur ^ 1], pa0, szA);
            cp_async16(sa1[cur ^ 1], pa1, szA);
            cp_async16(sb1[cur ^ 1], pb1, szB);
            cp_async16(sb3[cur ^ 1], pb3, szB);
            cp_commit();
            cp_wait<1>();
        } else {
            cp_wait<0>();
        }
        __syncthreads();

        #pragma unroll
        for (int ks = 0; ks < 2; ks++) {
            const int kb = ks * 8;
            unsigned a[2][4], b1[4][2], b3[4][2];
            #pragma unroll
            for (int mi = 0; mi < 2; mi++) {
                int r = wm * 32 + mi * 16 + lr;
                a[mi][0] = r2tf32(As[cur][r][kb + lc]);
                a[mi][1] = r2tf32(As[cur][r + 8][kb + lc]);
                a[mi][2] = r2tf32(As[cur][r][kb + lc + 4]);
                a[mi][3] = r2tf32(As[cur][r + 8][kb + lc + 4]);
            }
            #pragma unroll
            for (int ni = 0; ni < 4; ni++) {
                int c = wn * 32 + ni * 8 + lr;
                b1[ni][0] = r2tf32(B1s[cur][c][kb + lc]);
                b1[ni][1] = r2tf32(B1s[cur][c][kb + lc + 4]);
                b3[ni][0] = r2tf32(B3s[cur][c][kb + lc]);
                b3[ni][1] = r2tf32(B3s[cur][c][kb + lc + 4]);
            }
            #pragma unroll
            for (int mi = 0; mi < 2; mi++)
                #pragma unroll
                for (int ni = 0; ni < 4; ni++) {
                    mma8(acc1[mi][ni], a[mi], b1[ni]);
                    mma8(acc3[mi][ni], a[mi], b3[ni]);
                }
        }
        __syncthreads();
    }

    const int dl = wm >> 1;
    #pragma unroll
    for (int ni = 0; ni < 4; ni++) {
        int cb = n0 + wn * 32 + ni * 8 + 2 * lc;
        float s0 = 0.f, s1 = 0.f;
        #pragma unroll
        for (int mi = 0; mi < 2; mi++) {
            int r = m0 + wm * 32 + mi * 16 + lr;
            #pragma unroll
            for (int half = 0; half < 2; half++) {
                int m = r + half * 8;
                float rsm = rs[m], frm = fri[m];
                if (cb < N) {
                    float v = acc1[mi][ni][half * 2] + rsm * acc3[mi][ni][half * 2]
                            + G[(long)m * H + cb] + frm * v2[cb] + b_r[cb];
                    s0 += lrelu_f(v);
                }
                if (cb + 1 < N) {
                    float v = acc1[mi][ni][half * 2 + 1] + rsm * acc3[mi][ni][half * 2 + 1]
                            + G[(long)m * H + cb + 1] + frm * v2[cb + 1] + b_r[cb + 1];
                    s1 += lrelu_f(v);
                }
            }
        }
        #pragma unroll
        for (int o = 4; o < 32; o <<= 1) {
            s0 += __shfl_xor_sync(0xffffffffu, s0, o);
            s1 += __shfl_xor_sync(0xffffffffu, s1, o);
        }
        if (lane < 4) {
            atomicAdd(&red[dl][wn * 32 + ni * 8 + 2 * lc],     s0);
            atomicAdd(&red[dl][wn * 32 + ni * 8 + 2 * lc + 1], s1);
        }
    }
    __syncthreads();

    // --- fused classifier: reduce red against W_cls, atomicAdd into out ---
    if (tid < 128) {
        int dloc = tid >> 6;            // warps 0-1 -> doc0, warps 2-3 -> doc1
        int c    = tid & 63;
        int col  = n0 + c;
        float fv = (col < N) ? red[dloc][c] * (1.f / 64.f) : 0.f;
        float p0 = (col < N) ? fv * W_cls[col]     : 0.f;
        float p1 = (col < N) ? fv * W_cls[H + col] : 0.f;
        #pragma unroll
        for (int o = 16; o; o >>= 1) {
            p0 += __shfl_xor_sync(0xffffffffu, p0, o);
            p1 += __shfl_xor_sync(0xffffffffu, p1, o);
        }
        if (lane == 0) { outred[wid][0] = p0; outred[wid][1] = p1; }
    }
    __syncthreads();
    if (tid == 0) {
        int doc0 = blockIdx.y * 2;
        float d0c0 = outred[0][0] + outred[1][0];
        float d0c1 = outred[0][1] + outred[1][1];
        float d1c0 = outred[2][0] + outred[3][0];
        float d1c1 = outred[2][1] + outred[3][1];
        if (blockIdx.x == 0) {
            d0c0 += b_cls[0]; d0c1 += b_cls[1];
            d1c0 += b_cls[0]; d1c1 += b_cls[1];
        }
        atomicAdd(&out[doc0 * 2 + 0], d0c0);
        atomicAdd(&out[doc0 * 2 + 1], d0c1);
        atomicAdd(&out[doc0 * 2 + 2], d1c0);
        atomicAdd(&out[doc0 * 2 + 3], d1c1);
    }
}

// =====================================================================
extern "C" void kernel_launch(void* const* d_in, const int* in_sizes, int n_in,
                              void* d_out, int out_size)
{
    const int*   word_indices = (const int*)  d_in[0];
    const float* E            = (const float*)d_in[1];
    const float* W_sent       = (const float*)d_in[2];
    const float* b_sent       = (const float*)d_in[3];
    const float* W_par        = (const float*)d_in[4];
    const float* b_par        = (const float*)d_in[5];
    const float* W_ch         = (const float*)d_in[6];
    const float* b_ch         = (const float*)d_in[7];
    const float* w_root       = (const float*)d_in[8];
    const float* b_root       = (const float*)d_in[9];
    const float* root_embed   = (const float*)d_in[10];
    const float* W_r          = (const float*)d_in[11];
    const float* b_r          = (const float*)d_in[12];
    const float* W_cls        = (const float*)d_in[13];
    const float* b_cls        = (const float*)d_in[14];

    float* out_ptr = (float*)d_out;
    float* A_ptr   = out_ptr + D * 2;
    float* fri_ptr = A_ptr + D * S * S;

    float *enc, *Pm, *Cm, *Y2, *G, *rs, *v2;
    cudaGetSymbolAddress((void**)&enc, g_enc);
    cudaGetSymbolAddress((void**)&Pm,  g_P);
    cudaGetSymbolAddress((void**)&Cm,  g_C);
    cudaGetSymbolAddress((void**)&Y2,  g_Y2);
    cudaGetSymbolAddress((void**)&G,   g_G);
    cudaGetSymbolAddress((void**)&rs,  g_rs);
    cudaGetSymbolAddress((void**)&v2,  g_v2);

    cudaFuncSetAttribute(scores_kernel,
                         cudaFuncAttributeMaxDynamicSharedMemorySize, SCORES_SMEM);

    dim3 gEnc((H + BN - 1) / BN, NROWS / BM, 1);
    gemm_tf32_kernel<true><<<gEnc, 256>>>(
        E, word_indices + (L - 1), L,
        W_sent, b_sent, enc,
        nullptr, nullptr, nullptr,
        nullptr, nullptr, nullptr, H, W, W, W, W);

    // P, C (lrelu+bias) and Y2 = enc @ W2^T (linear; W2 rows inside W_r, ld=900)
    dim3 gPCY((H + BN - 1) / BN, NROWS / BM, 3);
    gemm_tf32_kernel<false><<<gPCY, 256>>>(
        enc, nullptr, 0,
        W_par,       b_par,   Pm,
        W_ch,        b_ch,    Cm,
        W_r + 300,   nullptr, Y2,
        H, H, H, H, 900);

    // scores + mask + column softmax -> A (in d_out)
    scores_kernel<<<dim3(4, D), 256, SCORES_SMEM>>>(Pm, Cm, A_ptr);

    // G = A^T @ Y2 per doc; rs (x==0), fri (x==1), v2 (x==2), zero out (x==3)
    g_kernel<<<dim3(5, D), 256>>>(A_ptr, Y2, enc, w_root, b_root,
                                  W_r, root_embed, G, rs, fri_ptr, v2, out_ptr);

    // ri + mean + fused classifier -> out (atomic)
    ri_mean_kernel<<<dim3(5, 32), 256>>>(enc, W_r, b_r, G, rs, fri_ptr, v2,
                                         W_cls, b_cls, out_ptr);
}

// round 17
// speedup vs baseline: 1.2802x; 1.0361x over previous
#include <cuda_runtime.h>

#define D 64
#define S 64
#define L 64
#define W 300
#define H 300
#define NROWS (D*S)          // 4096
#define NEGV (-9999999.0f)

// ---------------- device scratch (no allocation allowed) ----------------
__device__ float g_enc[NROWS * H];
__device__ float g_P  [NROWS * H];
__device__ float g_C  [NROWS * H];
__device__ float g_Y2 [NROWS * H];
__device__ float g_G  [NROWS * H];
__device__ float g_rs [NROWS];
__device__ float g_v2 [H];

__device__ __forceinline__ float lrelu_f(float x) { return x > 0.f ? x : 0.01f * x; }

__device__ __forceinline__ unsigned f2tf32(float f) {
    unsigned u;
    asm("cvt.rna.tf32.f32 %0, %1;" : "=r"(u) : "f"(f));
    return u;
}
__device__ __forceinline__ unsigned r2tf32(unsigned raw) {
    return f2tf32(__uint_as_float(raw));
}

__device__ __forceinline__ void mma8(float* c, const unsigned* a, const unsigned* b) {
    asm volatile(
        "mma.sync.aligned.m16n8k8.row.col.f32.tf32.tf32.f32 "
        "{%0,%1,%2,%3}, {%4,%5,%6,%7}, {%8,%9}, {%0,%1,%2,%3};"
        : "+f"(c[0]), "+f"(c[1]), "+f"(c[2]), "+f"(c[3])
        : "r"(a[0]), "r"(a[1]), "r"(a[2]), "r"(a[3]), "r"(b[0]), "r"(b[1]));
}

// cp.async 16B with zero-fill when srcsize==0
__device__ __forceinline__ void cp_async16(unsigned smem_addr, const void* gptr, int srcsize) {
    asm volatile("cp.async.ca.shared.global [%0], [%1], 16, %2;"
                 :: "r"(smem_addr), "l"(gptr), "r"(srcsize));
}
__device__ __forceinline__ void cp_commit() {
    asm volatile("cp.async.commit_group;");
}
template<int N>
__device__ __forceinline__ void cp_wait() {
    asm volatile("cp.async.wait_group %0;" :: "n"(N));
}

#define BM 128
#define BN 64
#define BK 16
#define BKP 20

// =====================================================================
// TF32 GEMM, cp.async depth-2 pipeline, rna tf32 at fragment read.
// z<3 selects (B,bias,Out,ldb) triples; bias==nullptr => linear.
// z==3 (extras slice, PCY launch only):
//   x==0: fri = softmax(enc @ w_root + b) for docs 2y, 2y+1
//   x==1: v2[n] = W_r[n,300:600].root_embed for n = y*10..y*10+9
//   x==2,y==0: zero out logits; x==2,y==1: zero rs
// =====================================================================
template<bool GATHER>
__global__ void gemm_tf32_kernel(
    const float* __restrict__ Abase, const int* __restrict__ idx, int idxStride,
    const float* __restrict__ B0, const float* __restrict__ bias0, float* __restrict__ Out0,
    const float* __restrict__ B1, const float* __restrict__ bias1, float* __restrict__ Out1,
    const float* __restrict__ B2, const float* __restrict__ bias2, float* __restrict__ Out2,
    int N, int K, int ldb0, int ldb1, int ldb2,
    const float* __restrict__ enc_x,
    const float* __restrict__ w_root, const float* __restrict__ b_root,
    const float* __restrict__ W_rx,  const float* __restrict__ root_embed,
    float* __restrict__ fri_out, float* __restrict__ v2_out,
    float* __restrict__ rs_out,  float* __restrict__ out_logits)
{
    const int tid = threadIdx.x;

    if (blockIdx.z == 3) {
        // ---------------- extras slice ----------------
        const int lane = tid & 31;
        if (blockIdx.x == 0) {
            // fri for docs 2y, 2y+1
            __shared__ float sc[2][64];
            __shared__ float part[2][2][2];   // [half][warp-of-64][0=max,1=sum]
            const int half   = tid >> 7;      // 0/1
            const int wg_tid = tid & 127;
            const int wq     = wg_tid >> 5;   // 0..3
            const int doc    = blockIdx.y * 2 + half;
            const float* Ed  = enc_x + (long)doc * S * H;
            const float  br0 = b_root[0];
            #pragma unroll
            for (int ss = 0; ss < 16; ss++) {
                int s = wq * 16 + ss;
                const float* e = Ed + s * H;
                float p = 0.f;
                for (int h = lane; h < H; h += 32) p += e[h] * w_root[h];
                #pragma unroll
                for (int o = 16; o; o >>= 1) p += __shfl_xor_sync(0xffffffffu, p, o);
                if (lane == 0) sc[half][s] = p + br0;
            }
            __syncthreads();
            if (wg_tid < 64) {
                float v = sc[half][wg_tid];
                float m = v;
                #pragma unroll
                for (int o = 16; o; o >>= 1) m = fmaxf(m, __shfl_xor_sync(0xffffffffu, m, o));
                if (lane == 0) part[half][wq][0] = m;
            }
            __syncthreads();
            float ex = 0.f;
            if (wg_tid < 64) {
                float m = fmaxf(part[half][0][0], part[half][1][0]);
                ex = __expf(sc[half][wg_tid] - m);
                float s = ex;
                #pragma unroll
                for (int o = 16; o; o >>= 1) s += __shfl_xor_sync(0xffffffffu, s, o);
                if (lane == 0) part[half][wq][1] = s;
            }
            __syncthreads();
            if (wg_tid < 64) {
                float ssum = part[half][0][1] + part[half][1][1];
                fri_out[doc * 64 + wg_tid] = ex / ssum;
            }
        } else if (blockIdx.x == 1) {
            // v2 slice: n = y*10 + idx
            const int wq = tid >> 5;
            #pragma unroll
            for (int pass = 0; pass < 2; pass++) {
                int idxn = pass * 8 + wq;
                if (idxn < 10) {
                    int n = blockIdx.y * 10 + idxn;
                    if (n < H) {
                        const float* w = W_rx + (long)n * 900 + 300;
                        float p = 0.f;
                        for (int k = lane; k < H; k += 32) p += w[k] * root_embed[k];
                        #pragma unroll
                        for (int o = 16; o; o >>= 1) p += __shfl_xor_sync(0xffffffffu, p, o);
                        if (lane == 0) v2_out[n] = p;
                    }
                }
            }
        } else if (blockIdx.x == 2) {
            if (blockIdx.y == 0) {
                if (tid < D * 2) out_logits[tid] = 0.f;
            } else if (blockIdx.y == 1) {
                for (int i = tid; i < NROWS; i += 256) rs_out[i] = 0.f;
            }
        }
        return;
    }

    // ---------------- main GEMM path ----------------
    const float* Bw   = B0;
    const float* bias = bias0;
    float*       Out  = Out0;
    int          ldb  = ldb0;
    if (blockIdx.z == 1) { Bw = B1; bias = bias1; Out = Out1; ldb = ldb1; }
    if (blockIdx.z == 2) { Bw = B2; bias = bias2; Out = Out2; ldb = ldb2; }
    const bool act = (bias != nullptr);

    __shared__ __align__(16) unsigned As[2][BM][BKP];
    __shared__ __align__(16) unsigned Bs[2][BN][BKP];

    const int lane = tid & 31;
    const int wid  = tid >> 5;
    const int wm   = wid >> 1;
    const int wn   = wid & 1;
    const int m0   = blockIdx.y * BM;
    const int n0   = blockIdx.x * BN;

    const int am0 = tid >> 2;
    const int ac  = (tid & 3) * 4;
    long aoff0, aoff1;
    if (GATHER) {
        aoff0 = (long)idx[(long)(m0 + am0) * idxStride] * K;
        aoff1 = (long)idx[(long)(m0 + am0 + 64) * idxStride] * K;
    } else {
        aoff0 = (long)(m0 + am0) * K;
        aoff1 = (long)(m0 + am0 + 64) * K;
    }
    const int  bn     = tid >> 2;
    const bool bvalid = (n0 + bn) < N;
    const long boff   = bvalid ? (long)(n0 + bn) * ldb : 0;

    unsigned sa0[2], sa1[2], sb[2];
    sa0[0] = (unsigned)__cvta_generic_to_shared(&As[0][am0][ac]);
    sa0[1] = (unsigned)__cvta_generic_to_shared(&As[1][am0][ac]);
    sa1[0] = (unsigned)__cvta_generic_to_shared(&As[0][am0 + 64][ac]);
    sa1[1] = (unsigned)__cvta_generic_to_shared(&As[1][am0 + 64][ac]);
    sb[0]  = (unsigned)__cvta_generic_to_shared(&Bs[0][bn][ac]);
    sb[1]  = (unsigned)__cvta_generic_to_shared(&Bs[1][bn][ac]);

    const int nIter = (K + BK - 1) / BK;

    {
        int k = ac;
        int szA = (k + 4 <= K) ? 16 : 0;
        int szB = (bvalid && k + 4 <= K) ? 16 : 0;
        cp_async16(sa0[0], Abase + aoff0 + k, szA);
        cp_async16(sa1[0], Abase + aoff1 + k, szA);
        cp_async16(sb[0],  Bw + boff + k,     szB);
    }
    cp_commit();

    float acc[2][4][4];
    #pragma unroll
    for (int i = 0; i < 2; i++)
        #pragma unroll
        for (int j = 0; j < 4; j++)
            #pragma unroll
            for (int q = 0; q < 4; q++) acc[i][j][q] = 0.f;

    const int lr = lane >> 2;
    const int lc = lane & 3;

    for (int it = 0; it < nIter; it++) {
        const int cur = it & 1;
        if (it + 1 < nIter) {
            int k = (it + 1) * BK + ac;
            int szA = (k + 4 <= K) ? 16 : 0;
            int szB = (bvalid && k + 4 <= K) ? 16 : 0;
            const float* pa0 = Abase + aoff0 + (szA ? k : 0);
            const float* pa1 = Abase + aoff1 + (szA ? k : 0);
            const float* pb  = Bw + boff + (szB ? k : 0);
            cp_async16(sa0[cur ^ 1], pa0, szA);
            cp_async16(sa1[cur ^ 1], pa1, szA);
            cp_async16(sb[cur ^ 1],  pb,  szB);
            cp_commit();
            cp_wait<1>();
        } else {
            cp_wait<0>();
        }
        __syncthreads();

        #pragma unroll
        for (int ks = 0; ks < 2; ks++) {
            const int kb = ks * 8;
            unsigned a[2][4], b[4][2];
            #pragma unroll
            for (int mi = 0; mi < 2; mi++) {
                int r = wm * 32 + mi * 16 + lr;
                a[mi][0] = r2tf32(As[cur][r][kb + lc]);
                a[mi][1] = r2tf32(As[cur][r + 8][kb + lc]);
                a[mi][2] = r2tf32(As[cur][r][kb + lc + 4]);
                a[mi][3] = r2tf32(As[cur][r + 8][kb + lc + 4]);
            }
            #pragma unroll
            for (int ni = 0; ni < 4; ni++) {
                int c = wn * 32 + ni * 8 + lr;
                b[ni][0] = r2tf32(Bs[cur][c][kb + lc]);
                b[ni][1] = r2tf32(Bs[cur][c][kb + lc + 4]);
            }
            #pragma unroll
            for (int mi = 0; mi < 2; mi++)
                #pragma unroll
                for (int ni = 0; ni < 4; ni++)
                    mma8(acc[mi][ni], a[mi], b[ni]);
        }
        __syncthreads();
    }

    #pragma unroll
    for (int mi = 0; mi < 2; mi++) {
        int r = m0 + wm * 32 + mi * 16 + lr;
        #pragma unroll
        for (int ni = 0; ni < 4; ni++) {
            int cb = n0 + wn * 32 + ni * 8 + 2 * lc;
            #pragma unroll
            for (int q = 0; q < 2; q++) {
                int cc = cb + q;
                if (cc >= N) continue;
                float bv = act ? bias[cc] : 0.f;
                float v0 = acc[mi][ni][q]     + bv;
                float v1 = acc[mi][ni][q + 2] + bv;
                if (act) { v0 = lrelu_f(v0); v1 = lrelu_f(v1); }
                Out[(long)r * N + cc]       = v0;
                Out[(long)(r + 8) * N + cc] = v1;
            }
        }
    }
}

// =====================================================================
// Scores + diag mask + column softmax + partial rs, grid (4, D).
// cp.async raw loads, rna at fragment read. rs accumulated via atomics
// (rs zeroed in the PCY extras slice, stream-ordered before this).
// =====================================================================
#define SPAD 308
#define SCORES_SMEM ((80 * SPAD + 64 * 17) * 4)   // 102,912 B

__global__ void scores_kernel(const float* __restrict__ P,
                              const float* __restrict__ Cm,
                              float* __restrict__ A_out,
                              float* __restrict__ rs_out)
{
    extern __shared__ unsigned sdyn[];
    unsigned* Pt = sdyn;                       // [64][SPAD] raw fp32 bits
    unsigned* Ct = sdyn + 64 * SPAD;           // [16][SPAD] raw fp32 bits
    float*    Sh = (float*)(sdyn + 80 * SPAD); // [64][17]

    const int d  = blockIdx.y;
    const int j0 = blockIdx.x * 16;
    const int t = threadIdx.x;
    const int lane = t & 31;
    const int wid  = t >> 5;
    const int wm = wid >> 1;
    const int wn = wid & 1;
    const int lr = lane >> 2, lc = lane & 3;

    const float* Pd = P  + (long)d * S * H;
    const float* Cd = Cm + (long)d * S * H;

    for (int u = t; u < 64 * 76; u += 256) {
        int r = u / 76, c4 = u - r * 76;
        unsigned dst = (unsigned)__cvta_generic_to_shared(&Pt[r * SPAD + c4 * 4]);
        int sz = (c4 < 75) ? 16 : 0;
        cp_async16(dst, Pd + r * H + (sz ? c4 * 4 : 0), sz);
    }
    for (int u = t; u < 16 * 76; u += 256) {
        int r = u / 76, c4 = u - r * 76;
        unsigned dst = (unsigned)__cvta_generic_to_shared(&Ct[r * SPAD + c4 * 4]);
        int sz = (c4 < 75) ? 16 : 0;
        cp_async16(dst, Cd + (j0 + r) * H + (sz ? c4 * 4 : 0), sz);
    }
    cp_commit();
    cp_wait<0>();
    __syncthreads();

    float acc[4] = {};
    {
        const int r = wm * 16 + lr;
        const int c = wn * 8 + lr;
        #pragma unroll
        for (int ks = 0; ks < 38; ks++) {
            const int kb = ks * 8;
            unsigned a[4], b[2];
            a[0] = r2tf32(Pt[r * SPAD + kb + lc]);
            a[1] = r2tf32(Pt[(r + 8) * SPAD + kb + lc]);
            a[2] = r2tf32(Pt[r * SPAD + kb + lc + 4]);
            a[3] = r2tf32(Pt[(r + 8) * SPAD + kb + lc + 4]);
            b[0] = r2tf32(Ct[c * SPAD + kb + lc]);
            b[1] = r2tf32(Ct[c * SPAD + kb + lc + 4]);
            mma8(acc, a, b);
        }
    }

    {
        int r = wm * 16 + lr;
        int cb = wn * 8 + 2 * lc;
        int gc = j0 + cb;
        Sh[r * 17 + cb]           = (r == gc)         ? NEGV : acc[0];
        Sh[r * 17 + cb + 1]       = (r == gc + 1)     ? NEGV : acc[1];
        Sh[(r + 8) * 17 + cb]     = (r + 8 == gc)     ? NEGV : acc[2];
        Sh[(r + 8) * 17 + cb + 1] = (r + 8 == gc + 1) ? NEGV : acc[3];
    }
    __syncthreads();

    #pragma unroll
    for (int cc = 0; cc < 2; cc++) {
        int c = wid * 2 + cc;
        float v0 = Sh[lane * 17 + c];
        float v1 = Sh[(lane + 32) * 17 + c];
        float m = fmaxf(v0, v1);
        #pragma unroll
        for (int o = 16; o; o >>= 1) m = fmaxf(m, __shfl_xor_sync(0xffffffffu, m, o));
        float e0 = __expf(v0 - m), e1 = __expf(v1 - m);
        float s = e0 + e1;
        #pragma unroll
        for (int o = 16; o; o >>= 1) s += __shfl_xor_sync(0xffffffffu, s, o);
        float inv = 1.f / s;
        Sh[lane * 17 + c]        = e0 * inv;
        Sh[(lane + 32) * 17 + c] = e1 * inv;
    }
    __syncthreads();

    for (int u = t; u < 64 * 16; u += 256) {
        int i = u >> 4, j = u & 15;
        A_out[(long)d * 4096 + i * 64 + j0 + j] = Sh[i * 17 + j];
    }

    // partial rs: this block owns cols j0..j0+15 of every row
    if (t < 64) {
        float s = 0.f;
        #pragma unroll
        for (int j = 0; j < 16; j++) s += Sh[t * 17 + j];
        atomicAdd(&rs_out[d * 64 + t], s);
    }
}

// =====================================================================
// G[d,i,h] = sum_k A[d,k,i] * Y2[d*64+k, h]  (tf32 mma), grid (5, D).
// Pure GEMM — all extras moved out (no straggler blocks).
// =====================================================================
#define GP 68

__global__ void g_kernel(const float* __restrict__ A_in,
                         const float* __restrict__ Y2,
                         float* __restrict__ G)
{
    const int d  = blockIdx.y;
    const int h0 = blockIdx.x * 64;
    const int t = threadIdx.x;
    const int lane = t & 31;
    const int wid  = t >> 5;
    const int wm = wid >> 1, wn = wid & 1;
    const int lr = lane >> 2, lc = lane & 3;

    __shared__ __align__(16) unsigned Ak[64][GP];
    __shared__ __align__(16) unsigned Ys[64][GP];

    const float* Ad = A_in + (long)d * 4096;
    const float* Yd = Y2 + (long)d * 64 * H;

    #pragma unroll
    for (int j = 0; j < 4; j++) {
        int u = t + 256 * j;
        int k = u >> 4, i = (u & 15) * 4;
        unsigned da = (unsigned)__cvta_generic_to_shared(&Ak[k][i]);
        cp_async16(da, Ad + k * 64 + i, 16);
        unsigned dy = (unsigned)__cvta_generic_to_shared(&Ys[k][i]);
        int h = h0 + i;
        int sz = (h + 4 <= H) ? 16 : 0;
        cp_async16(dy, Yd + (long)k * H + (sz ? h : 0), sz);
    }
    cp_commit();
    cp_wait<0>();
    __syncthreads();

    float acc[4][4] = {};
    #pragma unroll
    for (int ks = 0; ks < 8; ks++) {
        const int kb = ks * 8;
        unsigned a[4], b[4][2];
        int r = wm * 16 + lr;
        a[0] = r2tf32(Ak[kb + lc][r]);
        a[1] = r2tf32(Ak[kb + lc][r + 8]);
        a[2] = r2tf32(Ak[kb + lc + 4][r]);
        a[3] = r2tf32(Ak[kb + lc + 4][r + 8]);
        #pragma unroll
        for (int ni = 0; ni < 4; ni++) {
            int c = wn * 32 + ni * 8 + lr;
            b[ni][0] = r2tf32(Ys[kb + lc][c]);
            b[ni][1] = r2tf32(Ys[kb + lc + 4][c]);
        }
        #pragma unroll
        for (int ni = 0; ni < 4; ni++)
            mma8(acc[ni], a, b[ni]);
    }

    {
        int r = wm * 16 + lr;
        #pragma unroll
        for (int ni = 0; ni < 4; ni++) {
            int cb = wn * 32 + ni * 8 + 2 * lc;
            #pragma unroll
            for (int q = 0; q < 2; q++) {
                int h = h0 + cb + q;
                if (h >= H) continue;
                G[(long)(d * 64 + r) * H + h]     = acc[ni][q];
                G[(long)(d * 64 + r + 8) * H + h] = acc[ni][q + 2];
            }
        }
    }
}

// =====================================================================
// ri+mean+classifier, cp.async depth-2 pipeline (R16-proven).
// =====================================================================
__global__ void ri_mean_kernel(const float* __restrict__ enc,
                               const float* __restrict__ W_r,   // [H, 900]
                               const float* __restrict__ b_r,
                               const float* __restrict__ G,
                               const float* __restrict__ rs,
                               const float* __restrict__ fri,
                               const float* __restrict__ v2,
                               const float* __restrict__ W_cls, // [2, H]
                               const float* __restrict__ b_cls, // [2]
                               float* __restrict__ out)         // [D, 2]
{
    __shared__ __align__(16) unsigned As[2][BM][BKP];
    __shared__ __align__(16) unsigned B1s[2][BN][BKP];
    __shared__ __align__(16) unsigned B3s[2][BN][BKP];
    __shared__ float red[2][BN];
    __shared__ float outred[4][2];

    const int K = H;
    const int N = H;
    const int tid  = threadIdx.x;
    const int lane = tid & 31;
    const int wid  = tid >> 5;
    const int wm = wid >> 1, wn = wid & 1;
    const int m0 = blockIdx.y * BM;
    const int n0 = blockIdx.x * BN;

    if (tid < 2 * BN) ((float*)red)[tid] = 0.f;

    const int am0 = tid >> 2;
    const int ac  = (tid & 3) * 4;
    const long aoff0 = (long)(m0 + am0) * K;
    const long aoff1 = (long)(m0 + am0 + 64) * K;
    const int  bn     = tid >> 2;
    const bool bvalid = (n0 + bn) < N;
    const long boff   = bvalid ? (long)(n0 + bn) * 900 : 0;

    unsigned sa0[2], sa1[2], sb1[2], sb3[2];
    sa0[0] = (unsigned)__cvta_generic_to_shared(&As[0][am0][ac]);
    sa0[1] = (unsigned)__cvta_generic_to_shared(&As[1][am0][ac]);
    sa1[0] = (unsigned)__cvta_generic_to_shared(&As[0][am0 + 64][ac]);
    sa1[1] = (unsigned)__cvta_generic_to_shared(&As[1][am0 + 64][ac]);
    sb1[0] = (unsigned)__cvta_generic_to_shared(&B1s[0][bn][ac]);
    sb1[1] = (unsigned)__cvta_generic_to_shared(&B1s[1][bn][ac]);
    sb3[0] = (unsigned)__cvta_generic_to_shared(&B3s[0][bn][ac]);
    sb3[1] = (unsigned)__cvta_generic_to_shared(&B3s[1][bn][ac]);

    const int nIter = (K + BK - 1) / BK;

    {
        int k = ac;
        int szA = (k + 4 <= K) ? 16 : 0;
        int szB = (bvalid && k + 4 <= K) ? 16 : 0;
        cp_async16(sa0[0], enc + aoff0 + k, szA);
        cp_async16(sa1[0], enc + aoff1 + k, szA);
        cp_async16(sb1[0], W_r + boff + k,        szB);
        cp_async16(sb3[0], W_r + boff + 600 + k,  szB);
    }
    cp_commit();

    float acc1[2][4][4], acc3[2][4][4];
    #pragma unroll
    for (int i = 0; i < 2; i++)
        #pragma unroll
        for (int j = 0; j < 4; j++)
            #pragma unroll
            for (int q = 0; q < 4; q++) { acc1[i][j][q] = 0.f; acc3[i][j][q] = 0.f; }

    const int lr = lane >> 2, lc = lane & 3;

    for (int it = 0; it < nIter; it++) {
        const int cur = it & 1;
        if (it + 1 < nIter) {
            int k = (it + 1) * BK + ac;
            int szA = (k + 4 <= K) ? 16 : 0;
            int szB = (bvalid && k + 4 <= K) ? 16 : 0;
            const float* pa0 = enc + aoff0 + (szA ? k : 0);
            const float* pa1 = enc + aoff1 + (szA ? k : 0);
            const float* pb1 = W_r + boff + (szB ? k : 0);
            const float* pb3 = W_r + boff + 600 + (szB ? k : 0);
            cp_async16(sa0[cur ^ 1], pa0, szA);
            cp_async16(sa1[cur ^ 1], pa1, szA);
            cp_async16(sb1[cur ^ 1], pb1, szB);
            cp_async16(sb3[cur ^ 1], pb3, szB);
            cp_commit();
            cp_wait<1>();
        } else {
            cp_wait<0>();
        }
        __syncthreads();

        #pragma unroll
        for (int ks = 0; ks < 2; ks++) {
            const int kb = ks * 8;
            unsigned a[2][4], b1[4][2], b3[4][2];
            #pragma unroll
            for (int mi = 0; mi < 2; mi++) {
                int r = wm * 32 + mi * 16 + lr;
                a[mi][0] = r2tf32(As[cur][r][kb + lc]);
                a[mi][1] = r2tf32(As[cur][r + 8][kb + lc]);
                a[mi][2] = r2tf32(As[cur][r][kb + lc + 4]);
                a[mi][3] = r2tf32(As[cur][r + 8][kb + lc + 4]);
            }
            #pragma unroll
            for (int ni = 0; ni < 4; ni++) {
                int c = wn * 32 + ni * 8 + lr;
                b1[ni][0] = r2tf32(B1s[cur][c][kb + lc]);
                b1[ni][1] = r2tf32(B1s[cur][c][kb + lc + 4]);
                b3[ni][0] = r2tf32(B3s[cur][c][kb + lc]);
                b3[ni][1] = r2tf32(B3s[cur][c][kb + lc + 4]);
            }
            #pragma unroll
            for (int mi = 0; mi < 2; mi++)
                #pragma unroll
                for (int ni = 0; ni < 4; ni++) {
                    mma8(acc1[mi][ni], a[mi], b1[ni]);
                    mma8(acc3[mi][ni], a[mi], b3[ni]);
                }
        }
        __syncthreads();
    }

    const int dl = wm >> 1;
    #pragma unroll
    for (int ni = 0; ni < 4; ni++) {
        int cb = n0 + wn * 32 + ni * 8 + 2 * lc;
        float s0 = 0.f, s1 = 0.f;
        #pragma unroll
        for (int mi = 0; mi < 2; mi++) {
            int r = m0 + wm * 32 + mi * 16 + lr;
            #pragma unroll
            for (int half = 0; half < 2; half++) {
                int m = r + half * 8;
                float rsm = rs[m], frm = fri[m];
                if (cb < N) {
                    float v = acc1[mi][ni][half * 2] + rsm * acc3[mi][ni][half * 2]
                            + G[(long)m * H + cb] + frm * v2[cb] + b_r[cb];
                    s0 += lrelu_f(v);
                }
                if (cb + 1 < N) {
                    float v = acc1[mi][ni][half * 2 + 1] + rsm * acc3[mi][ni][half * 2 + 1]
                            + G[(long)m * H + cb + 1] + frm * v2[cb + 1] + b_r[cb + 1];
                    s1 += lrelu_f(v);
                }
            }
        }
        #pragma unroll
        for (int o = 4; o < 32; o <<= 1) {
            s0 += __shfl_xor_sync(0xffffffffu, s0, o);
            s1 += __shfl_xor_sync(0xffffffffu, s1, o);
        }
        if (lane < 4) {
            atomicAdd(&red[dl][wn * 32 + ni * 8 + 2 * lc],     s0);
            atomicAdd(&red[dl][wn * 32 + ni * 8 + 2 * lc + 1], s1);
        }
    }
    __syncthreads();

    if (tid < 128) {
        int dloc = tid >> 6;
        int c    = tid & 63;
        int col  = n0 + c;
        float fv = (col < N) ? red[dloc][c] * (1.f / 64.f) : 0.f;
        float p0 = (col < N) ? fv * W_cls[col]     : 0.f;
        float p1 = (col < N) ? fv * W_cls[H + col] : 0.f;
        #pragma unroll
        for (int o = 16; o; o >>= 1) {
            p0 += __shfl_xor_sync(0xffffffffu, p0, o);
            p1 += __shfl_xor_sync(0xffffffffu, p1, o);
        }
        if (lane == 0) { outred[wid][0] = p0; outred[wid][1] = p1; }
    }
    __syncthreads();
    if (tid == 0) {
        int doc0 = blockIdx.y * 2;
        float d0c0 = outred[0][0] + outred[1][0];
        float d0c1 = outred[0][1] + outred[1][1];
        float d1c0 = outred[2][0] + outred[3][0];
        float d1c1 = outred[2][1] + outred[3][1];
        if (blockIdx.x == 0) {
            d0c0 += b_cls[0]; d0c1 += b_cls[1];
            d1c0 += b_cls[0]; d1c1 += b_cls[1];
        }
        atomicAdd(&out[doc0 * 2 + 0], d0c0);
        atomicAdd(&out[doc0 * 2 + 1], d0c1);
        atomicAdd(&out[doc0 * 2 + 2], d1c0);
        atomicAdd(&out[doc0 * 2 + 3], d1c1);
    }
}

// =====================================================================
extern "C" void kernel_launch(void* const* d_in, const int* in_sizes, int n_in,
                              void* d_out, int out_size)
{
    const int*   word_indices = (const int*)  d_in[0];
    const float* E            = (const float*)d_in[1];
    const float* W_sent       = (const float*)d_in[2];
    const float* b_sent       = (const float*)d_in[3];
    const float* W_par        = (const float*)d_in[4];
    const float* b_par        = (const float*)d_in[5];
    const float* W_ch         = (const float*)d_in[6];
    const float* b_ch         = (const float*)d_in[7];
    const float* w_root       = (const float*)d_in[8];
    const float* b_root       = (const float*)d_in[9];
    const float* root_embed   = (const float*)d_in[10];
    const float* W_r          = (const float*)d_in[11];
    const float* b_r          = (const float*)d_in[12];
    const float* W_cls        = (const float*)d_in[13];
    const float* b_cls        = (const float*)d_in[14];

    float* out_ptr = (float*)d_out;
    float* A_ptr   = out_ptr + D * 2;
    float* fri_ptr = A_ptr + D * S * S;

    float *enc, *Pm, *Cm, *Y2, *G, *rs, *v2;
    cudaGetSymbolAddress((void**)&enc, g_enc);
    cudaGetSymbolAddress((void**)&Pm,  g_P);
    cudaGetSymbolAddress((void**)&Cm,  g_C);
    cudaGetSymbolAddress((void**)&Y2,  g_Y2);
    cudaGetSymbolAddress((void**)&G,   g_G);
    cudaGetSymbolAddress((void**)&rs,  g_rs);
    cudaGetSymbolAddress((void**)&v2,  g_v2);

    cudaFuncSetAttribute(scores_kernel,
                         cudaFuncAttributeMaxDynamicSharedMemorySize, SCORES_SMEM);

    // 1) enc = lrelu(gather(E) @ W_sent^T + b_sent)   (z == 0 only)
    dim3 gEnc((H + BN - 1) / BN, NROWS / BM, 1);
    gemm_tf32_kernel<true><<<gEnc, 256>>>(
        E, word_indices + (L - 1), L,
        W_sent, b_sent, enc,
        nullptr, nullptr, nullptr,
        nullptr, nullptr, nullptr, H, W, W, W, W,
        nullptr, nullptr, nullptr, nullptr, nullptr,
        nullptr, nullptr, nullptr, nullptr);

    // 2) P, C, Y2 (z=0..2) + extras slice (z==3): fri, v2, zero out/rs
    dim3 gPCY((H + BN - 1) / BN, NROWS / BM, 4);
    gemm_tf32_kernel<false><<<gPCY, 256>>>(
        enc, nullptr, 0,
        W_par,       b_par,   Pm,
        W_ch,        b_ch,    Cm,
        W_r + 300,   nullptr, Y2,
        H, H, H, H, 900,
        enc, w_root, b_root, W_r, root_embed,
        fri_ptr, v2, rs, out_ptr);

    // 3) scores + mask + column softmax -> A (d_out) + partial rs (atomic)
    scores_kernel<<<dim3(4, D), 256, SCORES_SMEM>>>(Pm, Cm, A_ptr, rs);

    // 4) G = A^T @ Y2 per doc (pure GEMM)
    g_kernel<<<dim3(5, D), 256>>>(A_ptr, Y2, G);

    // 5) ri + mean + fused classifier -> out (atomic)
    ri_mean_kernel<<<dim3(5, 32), 256>>>(enc, W_r, b_r, G, rs, fri_ptr, v2,
                                         W_cls, b_cls, out_ptr);
}